// round 8
// baseline (speedup 1.0000x reference)
#include <cuda_runtime.h>
#include <cuda_bf16.h>
#include <cstdint>
#include <cstddef>

#define S 2048
#define E 1024
#define H 16
#define HD 64
#define NT 16              // S/128 k-tiles
#define SCALE 0.125f

// Scratch
__device__ float g_q[S * E];
__device__ float g_k[S * E];
__device__ float g_v[S * E];
__device__ float g_rel[S * S];      // pre-scaled by SCALE
__device__ float g_attn[S * E];
// Pre-split, pre-swizzled bf16 hi/lo tile images (exact smem byte layout)
__device__ __align__(128) char g_kt[H * NT * 32768];
__device__ __align__(128) char g_vt[H * NT * 32768];

// ---------------------------------------------------------------------------
// Helpers
// ---------------------------------------------------------------------------
__device__ __forceinline__ uint32_t smem_u32(const void* p) {
    uint32_t a;
    asm("{ .reg .u64 t; cvta.to.shared.u64 t, %1; cvt.u32.u64 %0, t; }"
        : "=r"(a) : "l"(p));
    return a;
}

__device__ __forceinline__ uint32_t sw128(uint32_t off) {
    return off ^ ((off >> 3) & 0x70);
}

__device__ __forceinline__ void ldsm4(uint32_t* r, uint32_t addr) {
    asm volatile("ldmatrix.sync.aligned.m8n8.x4.shared.b16 {%0,%1,%2,%3}, [%4];"
                 : "=r"(r[0]), "=r"(r[1]), "=r"(r[2]), "=r"(r[3]) : "r"(addr));
}

__device__ __forceinline__ void mma16816(float* c, const uint32_t* a, const uint32_t* b) {
    asm volatile(
        "mma.sync.aligned.m16n8k16.row.col.f32.bf16.bf16.f32 "
        "{%0,%1,%2,%3}, {%4,%5,%6,%7}, {%8,%9}, {%0,%1,%2,%3};"
        : "+f"(c[0]), "+f"(c[1]), "+f"(c[2]), "+f"(c[3])
        : "r"(a[0]), "r"(a[1]), "r"(a[2]), "r"(a[3]), "r"(b[0]), "r"(b[1]));
}

__device__ __forceinline__ uint32_t bf2(float lo, float hi) {
    uint32_t r;
    asm("cvt.rn.bf16x2.f32 %0, %1, %2;" : "=r"(r) : "f"(hi), "f"(lo));
    return r;
}

__device__ __forceinline__ void split2(float x, float y, uint32_t& hi, uint32_t& lo) {
    __nv_bfloat16 bx = __float2bfloat16(x), by = __float2bfloat16(y);
    __nv_bfloat162 hp; hp.x = bx; hp.y = by;
    hi = *(uint32_t*)&hp;
    lo = bf2(x - __bfloat162float(bx), y - __bfloat162float(by));
}

__device__ __forceinline__ void split_store_pair(char* base, int row, int col2,
                                                 float x0, float x1) {
    __nv_bfloat16 h0 = __float2bfloat16(x0);
    __nv_bfloat16 h1 = __float2bfloat16(x1);
    __nv_bfloat16 l0 = __float2bfloat16(x0 - __bfloat162float(h0));
    __nv_bfloat16 l1 = __float2bfloat16(x1 - __bfloat162float(h1));
    __nv_bfloat162 hp; hp.x = h0; hp.y = h1;
    __nv_bfloat162 lp; lp.x = l0; lp.y = l1;
    *(__nv_bfloat162*)(base + sw128(row * 128 + col2 * 2)) = hp;
    *(__nv_bfloat162*)(base + sw128(row * 128 + 64 + col2 * 2)) = lp;
}

#define CP16(dst, src) \
    asm volatile("cp.async.cg.shared.global [%0], [%1], 16;" :: "r"(dst), "l"(src))
#define CP_COMMIT() asm volatile("cp.async.commit_group;" ::: "memory")
#define CP_WAIT(n)  asm volatile("cp.async.wait_group %0;" :: "n"(n) : "memory")

__constant__ int c_aofs[3] = {0, 0, 32};
__constant__ int c_bofs[3] = {0, 32, 0};

// ---------------------------------------------------------------------------
// tc_gemm (R5-proven): C = (A[M,K]*B[N,K]^T)*cscale + bias.  128x128, BK=32.
// ---------------------------------------------------------------------------
__global__ __launch_bounds__(256) void tc_gemm(
    const float* __restrict__ A, const float* __restrict__ B,
    float* __restrict__ C, int K, int lda, int ldb, int ldc,
    const float* __restrict__ bias, float cscale)
{
    __shared__ __align__(128) char smA[128 * 128];
    __shared__ __align__(128) char smB[128 * 128];

    const int tid = threadIdx.x;
    const int warp = tid >> 5, lane = tid & 31;
    const int row0 = blockIdx.y * 128;
    const int col0 = blockIdx.x * 128;
    const int wm0 = (warp >> 1) * 32;
    const int wn0 = (warp & 1) * 64;

    uint32_t sA = smem_u32(smA);
    uint32_t sB = smem_u32(smB);

    float c[2][8][4];
#pragma unroll
    for (int i = 0; i < 2; i++)
#pragma unroll
        for (int j = 0; j < 8; j++)
#pragma unroll
            for (int t = 0; t < 4; t++) c[i][j][t] = 0.f;

    const int lr = tid >> 4;
    const int lp = tid & 15;

    for (int k0 = 0; k0 < K; k0 += 32) {
#pragma unroll
        for (int s = 0; s < 8; s++) {
            int r = s * 16 + lr;
            float2 va = *(const float2*)&A[(size_t)(row0 + r) * lda + k0 + 2 * lp];
            split_store_pair(smA, r, 2 * lp, va.x, va.y);
            float2 vb = *(const float2*)&B[(size_t)(col0 + r) * ldb + k0 + 2 * lp];
            split_store_pair(smB, r, 2 * lp, vb.x, vb.y);
        }
        __syncthreads();

        const int arow = wm0 + (lane & 15);
        const int acolq = (lane >> 4) * 8;
        const int bn = wn0 + (lane & 7) + ((lane >> 4) << 3);
        const int bkq = ((lane >> 3) & 1) * 8;

#pragma unroll
        for (int s3 = 0; s3 < 3; s3++) {
            const int aoff = c_aofs[s3], boff = c_bofs[s3];
#pragma unroll
            for (int ks = 0; ks < 2; ks++) {
                int acol = aoff + ks * 16 + acolq;
                uint32_t a0[4], a1[4];
                ldsm4(a0, sA + sw128((uint32_t)(arow * 128 + acol * 2)));
                ldsm4(a1, sA + sw128((uint32_t)((arow + 16) * 128 + acol * 2)));
                int bcol = boff + ks * 16 + bkq;
                uint32_t bq[4][4];
#pragma unroll
                for (int j2 = 0; j2 < 4; j2++)
                    ldsm4(bq[j2], sB + sw128((uint32_t)((bn + j2 * 16) * 128 + bcol * 2)));
#pragma unroll
                for (int i = 0; i < 2; i++) {
                    const uint32_t* ai = (i == 0) ? a0 : a1;
#pragma unroll
                    for (int j = 0; j < 8; j++)
                        mma16816(c[i][j], ai, &bq[j >> 1][(j & 1) * 2]);
                }
            }
        }
        __syncthreads();
    }

    const int g = lane >> 2, t4 = lane & 3;
#pragma unroll
    for (int i = 0; i < 2; i++) {
#pragma unroll
        for (int j = 0; j < 8; j++) {
            int gr0 = row0 + wm0 + i * 16 + g;
            int gc = col0 + wn0 + j * 8 + t4 * 2;
            float v0 = c[i][j][0] * cscale, v1 = c[i][j][1] * cscale;
            float v2 = c[i][j][2] * cscale, v3 = c[i][j][3] * cscale;
            if (bias) {
                float2 bv = *(const float2*)&bias[gc];
                v0 += bv.x; v1 += bv.y; v2 += bv.x; v3 += bv.y;
            }
            *(float2*)&C[(size_t)gr0 * ldc + gc] = make_float2(v0, v1);
            *(float2*)&C[(size_t)(gr0 + 8) * ldc + gc] = make_float2(v2, v3);
        }
    }
}

// ---------------------------------------------------------------------------
// prep_kv: split k/v into bf16 hi/lo pre-swizzled 32KB tile images.
// ---------------------------------------------------------------------------
__global__ __launch_bounds__(128) void prep_kv()
{
    const int tid = threadIdx.x;
    const int t0 = blockIdx.x * 128;
    const int h = blockIdx.y;
    const int qc0 = h * HD;
    char* kimg = g_kt + ((size_t)(h * NT + blockIdx.x)) * 32768;
    char* vimg = g_vt + ((size_t)(h * NT + blockIdx.x)) * 32768;

    const int lr = tid >> 4, lp = tid & 15;
#pragma unroll 4
    for (int s = 0; s < 16; s++) {
        int tr = s * 8 + lr;
        float4 kv = *(const float4*)&g_k[(size_t)(t0 + tr) * E + qc0 + 4 * lp];
        uint32_t h0, l0, h1, l1;
        split2(kv.x, kv.y, h0, l0);
        split2(kv.z, kv.w, h1, l1);
        *(uint2*)(kimg + sw128(tr * 128 + 8 * lp)) = make_uint2(h0, h1);
        *(uint2*)(kimg + 16384 + sw128(tr * 128 + 8 * lp)) = make_uint2(l0, l1);

        float4 vv = *(const float4*)&g_v[(size_t)(t0 + tr) * E + qc0 + 4 * lp];
        int sub = tr >> 6, tc = tr & 63;
        char* bh_ = vimg + sub * 8192;
        char* bl_ = vimg + 16384 + sub * 8192;
        float vs[4] = {vv.x, vv.y, vv.z, vv.w};
#pragma unroll
        for (int j = 0; j < 4; j++) {
            int d = 4 * lp + j;
            __nv_bfloat16 hb = __float2bfloat16(vs[j]);
            __nv_bfloat16 lb = __float2bfloat16(vs[j] - __bfloat162float(hb));
            *(__nv_bfloat16*)(bh_ + sw128(d * 128 + tc * 2)) = hb;
            *(__nv_bfloat16*)(bl_ + sw128(d * 128 + tc * 2)) = lb;
        }
    }
}

// ---------------------------------------------------------------------------
// fused_attn: 128 threads, 64 q-rows/CTA, grid (S/64, H). 96KB smem:
//   [0,32K)=kbuf0  [32K,64K)=kbuf1  [64K,96K)=vbuf
// pass1: double-buffered k, l = sum exp(q'k + rel')
// pass2: v_t staged under score MMAs, k_{t+1} staged under PV.
// Score MMAs use 3 independent accumulator sets (chain 12 -> 4).
// ---------------------------------------------------------------------------
__global__ __launch_bounds__(128) void fused_attn(
    const float* __restrict__ rels, float* __restrict__ wout)
{
    extern __shared__ char dyn[];
    const uint32_t smb = smem_u32(dyn);
    const uint32_t vbuf = smb + 65536;

    const int tid = threadIdx.x;
    const int warp = tid >> 5, lane = tid & 31;
    const int g = lane >> 2, t4 = lane & 3;
    const int h = blockIdx.y;
    const int row0 = blockIdx.x * 64;
    const int qc0 = h * HD;

    const int rA = row0 + warp * 16 + g;
    const int rB = rA + 8;

    // q fragments, scaled by SCALE
    uint32_t qh[4][4], ql[4][4];
#pragma unroll
    for (int ks = 0; ks < 4; ks++) {
        int c = qc0 + ks * 16 + 2 * t4;
        float2 x00 = *(const float2*)&g_q[(size_t)rA * E + c];
        float2 x10 = *(const float2*)&g_q[(size_t)rB * E + c];
        float2 x01 = *(const float2*)&g_q[(size_t)rA * E + c + 8];
        float2 x11 = *(const float2*)&g_q[(size_t)rB * E + c + 8];
        split2(x00.x * SCALE, x00.y * SCALE, qh[ks][0], ql[ks][0]);
        split2(x10.x * SCALE, x10.y * SCALE, qh[ks][1], ql[ks][1]);
        split2(x01.x * SCALE, x01.y * SCALE, qh[ks][2], ql[ks][2]);
        split2(x11.x * SCALE, x11.y * SCALE, qh[ks][3], ql[ks][3]);
    }

    const int bnp = (lane & 7) + ((lane >> 4) << 3);
    const int bkq = ((lane >> 3) & 1) * 8;

    const char* ksrc = g_kt + ((size_t)h * NT) * 32768;
    const char* vsrc = g_vt + ((size_t)h * NT) * 32768;

    float lA = 0.f, lB = 0.f;

    // ===================== PASS 1: row sums =====================
#pragma unroll
    for (int i = 0; i < 16; i++) {
        uint32_t off = (uint32_t)(tid + i * 128) * 16;
        CP16(smb + off, ksrc + off);
    }
    CP_COMMIT();

#pragma unroll 1
    for (int t = 0; t < NT; t++) {
        CP_WAIT(0);
        __syncthreads();
        if (t + 1 < NT) {
            const char* src = ksrc + (size_t)(t + 1) * 32768;
            uint32_t dst = smb + ((t + 1) & 1) * 32768;
#pragma unroll
            for (int i = 0; i < 16; i++) {
                uint32_t off = (uint32_t)(tid + i * 128) * 16;
                CP16(dst + off, src + off);
            }
            CP_COMMIT();
        }
        const uint32_t uSkh = smb + (t & 1) * 32768;
        const uint32_t uSkl = uSkh + 16384;

#pragma unroll 1
        for (int ch = 0; ch < 8; ch++) {
            // prefetch rel (overlaps MMAs)
            int cg = t * 128 + ch * 16 + 2 * t4;
            float2 r00 = *(const float2*)&rels[(size_t)rA * S + cg];
            float2 r10 = *(const float2*)&rels[(size_t)rB * S + cg];
            float2 r01 = *(const float2*)&rels[(size_t)rA * S + cg + 8];
            float2 r11 = *(const float2*)&rels[(size_t)rB * S + cg + 8];

            float csA[2][4], csB[2][4], csC[2][4];
#pragma unroll
            for (int i = 0; i < 2; i++)
#pragma unroll
                for (int q2 = 0; q2 < 4; q2++) { csA[i][q2] = 0.f; csB[i][q2] = 0.f; csC[i][q2] = 0.f; }
            int brow = ch * 16 + bnp;
#pragma unroll
            for (int ks = 0; ks < 4; ks++) {
                uint32_t bh[4], bl[4];
                uint32_t cb = (uint32_t)((ks * 16 + bkq) * 2);
                ldsm4(bh, uSkh + sw128(brow * 128 + cb));
                ldsm4(bl, uSkl + sw128(brow * 128 + cb));
                mma16816(csA[0], qh[ks], bh + 0);
                mma16816(csA[1], qh[ks], bh + 2);
                mma16816(csB[0], qh[ks], bl + 0);
                mma16816(csB[1], qh[ks], bl + 2);
                mma16816(csC[0], ql[ks], bh + 0);
                mma16816(csC[1], ql[ks], bh + 2);
            }
            float cs00 = csA[0][0] + csB[0][0] + csC[0][0];
            float cs01 = csA[0][1] + csB[0][1] + csC[0][1];
            float cs02 = csA[0][2] + csB[0][2] + csC[0][2];
            float cs03 = csA[0][3] + csB[0][3] + csC[0][3];
            float cs10 = csA[1][0] + csB[1][0] + csC[1][0];
            float cs11 = csA[1][1] + csB[1][1] + csC[1][1];
            float cs12 = csA[1][2] + csB[1][2] + csC[1][2];
            float cs13 = csA[1][3] + csB[1][3] + csC[1][3];
            lA += __expf(cs00 + r00.x) + __expf(cs01 + r00.y) +
                  __expf(cs10 + r01.x) + __expf(cs11 + r01.y);
            lB += __expf(cs02 + r10.x) + __expf(cs03 + r10.y) +
                  __expf(cs12 + r11.x) + __expf(cs13 + r11.y);
        }
    }

    lA += __shfl_xor_sync(0xffffffffu, lA, 1);
    lA += __shfl_xor_sync(0xffffffffu, lA, 2);
    lB += __shfl_xor_sync(0xffffffffu, lB, 1);
    lB += __shfl_xor_sync(0xffffffffu, lB, 2);
    const float invA = 1.f / lA, invB = 1.f / lB;

    float o[8][4];
#pragma unroll
    for (int j = 0; j < 8; j++)
#pragma unroll
        for (int q2 = 0; q2 < 4; q2++) o[j][q2] = 0.f;

    float* wrow = wout + (size_t)h * S * S;

    // ===================== PASS 2: w + PV (pipelined) =====================
    __syncthreads();   // pass1 smem reads complete
    // stage k_0 into kbuf0
#pragma unroll
    for (int i = 0; i < 16; i++) {
        uint32_t off = (uint32_t)(tid + i * 128) * 16;
        CP16(smb + off, ksrc + off);
    }
    CP_COMMIT();

#pragma unroll 1
    for (int t = 0; t < NT; t++) {
        // stage v_t (overlaps score MMAs below)
        {
            const char* srcv = vsrc + (size_t)t * 32768;
#pragma unroll
            for (int i = 0; i < 16; i++) {
                uint32_t off = (uint32_t)(tid + i * 128) * 16;
                CP16(vbuf + off, srcv + off);
            }
            CP_COMMIT();
        }
        // stage k_{t+1} (overlaps PV below)
        if (t + 1 < NT) {
            const char* src = ksrc + (size_t)(t + 1) * 32768;
            uint32_t dst = smb + ((t + 1) & 1) * 32768;
#pragma unroll
            for (int i = 0; i < 16; i++) {
                uint32_t off = (uint32_t)(tid + i * 128) * 16;
                CP16(dst + off, src + off);
            }
            CP_COMMIT();
        }
        // k_t ready (all groups except the 2 newest done)
        if (t + 1 < NT) { CP_WAIT(2); } else { CP_WAIT(1); }
        __syncthreads();

        const uint32_t uSkh = smb + (t & 1) * 32768;
        const uint32_t uSkl = uSkh + 16384;

        // -------- scores + w --------
        uint32_t ahf[8][4], alf[8][4];   // per-chunk A frags for PV
#pragma unroll 1
        for (int ch = 0; ch < 8; ch++) {
            int cg = t * 128 + ch * 16 + 2 * t4;
            float2 r00 = *(const float2*)&rels[(size_t)rA * S + cg];
            float2 r10 = *(const float2*)&rels[(size_t)rB * S + cg];
            float2 r01 = *(const float2*)&rels[(size_t)rA * S + cg + 8];
            float2 r11 = *(const float2*)&rels[(size_t)rB * S + cg + 8];

            float csA[2][4], csB[2][4], csC[2][4];
#pragma unroll
            for (int i = 0; i < 2; i++)
#pragma unroll
                for (int q2 = 0; q2 < 4; q2++) { csA[i][q2] = 0.f; csB[i][q2] = 0.f; csC[i][q2] = 0.f; }
            int brow = ch * 16 + bnp;
#pragma unroll
            for (int ks = 0; ks < 4; ks++) {
                uint32_t bh[4], bl[4];
                uint32_t cb = (uint32_t)((ks * 16 + bkq) * 2);
                ldsm4(bh, uSkh + sw128(brow * 128 + cb));
                ldsm4(bl, uSkl + sw128(brow * 128 + cb));
                mma16816(csA[0], qh[ks], bh + 0);
                mma16816(csA[1], qh[ks], bh + 2);
                mma16816(csB[0], qh[ks], bl + 0);
                mma16816(csB[1], qh[ks], bl + 2);
                mma16816(csC[0], ql[ks], bh + 0);
                mma16816(csC[1], ql[ks], bh + 2);
            }
            float wA0 = __expf(csA[0][0] + csB[0][0] + csC[0][0] + r00.x) * invA;
            float wA1 = __expf(csA[0][1] + csB[0][1] + csC[0][1] + r00.y) * invA;
            float wA2 = __expf(csA[1][0] + csB[1][0] + csC[1][0] + r01.x) * invA;
            float wA3 = __expf(csA[1][1] + csB[1][1] + csC[1][1] + r01.y) * invA;
            float wB0 = __expf(csA[0][2] + csB[0][2] + csC[0][2] + r10.x) * invB;
            float wB1 = __expf(csA[0][3] + csB[0][3] + csC[0][3] + r10.y) * invB;
            float wB2 = __expf(csA[1][2] + csB[1][2] + csC[1][2] + r11.x) * invB;
            float wB3 = __expf(csA[1][3] + csB[1][3] + csC[1][3] + r11.y) * invB;

            *(float2*)&wrow[(size_t)rA * S + cg]     = make_float2(wA0, wA1);
            *(float2*)&wrow[(size_t)rA * S + cg + 8] = make_float2(wA2, wA3);
            *(float2*)&wrow[(size_t)rB * S + cg]     = make_float2(wB0, wB1);
            *(float2*)&wrow[(size_t)rB * S + cg + 8] = make_float2(wB2, wB3);

            split2(wA0, wA1, ahf[ch][0], alf[ch][0]);
            split2(wB0, wB1, ahf[ch][1], alf[ch][1]);
            split2(wA2, wA3, ahf[ch][2], alf[ch][2]);
            split2(wB2, wB3, ahf[ch][3], alf[ch][3]);
        }

        // v_t ready (only k_{t+1} may still be in flight)
        if (t + 1 < NT) { CP_WAIT(1); } else { CP_WAIT(0); }
        __syncthreads();

        // -------- PV --------
#pragma unroll 1
        for (int ch = 0; ch < 8; ch++) {
            int sub = ch >> 2;
            uint32_t cb = (uint32_t)(((ch & 3) * 16 + bkq) * 2);
            uint32_t vbaseh = vbuf + sub * 8192;
            uint32_t vbasel = vbuf + 16384 + sub * 8192;
#pragma unroll
            for (int jd = 0; jd < 4; jd++) {
                int dn = jd * 16 + bnp;
                uint32_t vh[4], vl[4];
                ldsm4(vh, vbaseh + sw128(dn * 128 + cb));
                ldsm4(vl, vbasel + sw128(dn * 128 + cb));
                mma16816(o[2 * jd],     ahf[ch], vh + 0);
                mma16816(o[2 * jd + 1], ahf[ch], vh + 2);
                mma16816(o[2 * jd],     ahf[ch], vl + 0);
                mma16816(o[2 * jd + 1], ahf[ch], vl + 2);
                mma16816(o[2 * jd],     alf[ch], vh + 0);
                mma16816(o[2 * jd + 1], alf[ch], vh + 2);
            }
        }
        __syncthreads();   // vbuf consumed before next iteration's staging
    }

    // epilogue
#pragma unroll
    for (int j = 0; j < 8; j++) {
        int gc = qc0 + j * 8 + 2 * t4;
        *(float2*)&g_attn[(size_t)rA * E + gc] = make_float2(o[j][0], o[j][1]);
        *(float2*)&g_attn[(size_t)rB * E + gc] = make_float2(o[j][2], o[j][3]);
    }
}

// ---------------------------------------------------------------------------
// Launch
// ---------------------------------------------------------------------------
extern "C" void kernel_launch(void* const* d_in, const int* in_sizes, int n_in,
                              void* d_out, int out_size)
{
    (void)in_sizes; (void)n_in; (void)out_size;
    const float* query = (const float*)d_in[0];
    const float* key   = (const float*)d_in[1];
    const float* value = (const float*)d_in[2];
    const float* sim   = (const float*)d_in[3];
    const float* Wq    = (const float*)d_in[4];
    const float* bq    = (const float*)d_in[5];
    const float* Wk    = (const float*)d_in[6];
    const float* bk    = (const float*)d_in[7];
    const float* Wv    = (const float*)d_in[8];
    const float* bv    = (const float*)d_in[9];
    const float* Wo    = (const float*)d_in[10];
    const float* bo    = (const float*)d_in[11];

    float* out = (float*)d_out;                 // [S,E]
    float* w   = out + (size_t)S * E;           // [H,S,S]

    float *gq, *gk, *gv, *grel, *gattn;
    cudaGetSymbolAddress((void**)&gq,    g_q);
    cudaGetSymbolAddress((void**)&gk,    g_k);
    cudaGetSymbolAddress((void**)&gv,    g_v);
    cudaGetSymbolAddress((void**)&grel,  g_rel);
    cudaGetSymbolAddress((void**)&gattn, g_attn);

    static int attr_done = 0;
    if (!attr_done) {
        cudaFuncSetAttribute(fused_attn,
                             cudaFuncAttributeMaxDynamicSharedMemorySize, 98304);
        attr_done = 1;
    }

    dim3 blk(256);

    // Projections
    tc_gemm<<<dim3(E / 128, S / 128), blk>>>(query, Wq, gq, E, E, E, E, bq, 1.f);
    tc_gemm<<<dim3(E / 128, S / 128), blk>>>(key,   Wk, gk, E, E, E, E, bk, 1.f);
    tc_gemm<<<dim3(E / 128, S / 128), blk>>>(value, Wv, gv, E, E, E, E, bv, 1.f);

    // rel = (sim @ sim^T) * SCALE
    tc_gemm<<<dim3(S / 128, S / 128), blk>>>(sim, sim, grel, HD, HD, HD, S, nullptr, SCALE);

    // pre-split k/v into swizzled bf16 tile images
    prep_kv<<<dim3(NT, H), dim3(128)>>>();

    // fused attention
    fused_attn<<<dim3(S / 64, H), dim3(128), 98304>>>(grel, w);

    // out = attn @ Wo^T + bo
    tc_gemm<<<dim3(E / 128, S / 128), blk>>>(gattn, Wo, out, E, E, E, E, bo, 1.f);
}

// round 9
// speedup vs baseline: 1.1534x; 1.1534x over previous
#include <cuda_runtime.h>
#include <cuda_bf16.h>
#include <cuda_fp16.h>
#include <cstdint>
#include <cstddef>

#define S 2048
#define E 1024
#define H 16
#define HD 64
#define SCALE 0.125f

// Scratch
__device__ float g_q[S * E];
__device__ float g_k[S * E];
__device__ float g_v[S * E];
__device__ float g_rel[S * S];
__device__ float g_attn[S * E];

// ---------------------------------------------------------------------------
// Helpers
// ---------------------------------------------------------------------------
__device__ __forceinline__ uint32_t smem_u32(const void* p) {
    uint32_t a;
    asm("{ .reg .u64 t; cvta.to.shared.u64 t, %1; cvt.u32.u64 %0, t; }"
        : "=r"(a) : "l"(p));
    return a;
}

__device__ __forceinline__ uint32_t sw128(uint32_t off) {
    return off ^ ((off >> 3) & 0x70);
}

__device__ __forceinline__ void ldsm4(uint32_t* r, uint32_t addr) {
    asm volatile("ldmatrix.sync.aligned.m8n8.x4.shared.b16 {%0,%1,%2,%3}, [%4];"
                 : "=r"(r[0]), "=r"(r[1]), "=r"(r[2]), "=r"(r[3]) : "r"(addr));
}

// bf16 mma, f32 acc (tc_gemm path — unchanged, proven)
__device__ __forceinline__ void mma16816(float* c, const uint32_t* a, const uint32_t* b) {
    asm volatile(
        "mma.sync.aligned.m16n8k16.row.col.f32.bf16.bf16.f32 "
        "{%0,%1,%2,%3}, {%4,%5,%6,%7}, {%8,%9}, {%0,%1,%2,%3};"
        : "+f"(c[0]), "+f"(c[1]), "+f"(c[2]), "+f"(c[3])
        : "r"(a[0]), "r"(a[1]), "r"(a[2]), "r"(a[3]), "r"(b[0]), "r"(b[1]));
}

// fp16 mma, f32 acc (fused hi*hi)
__device__ __forceinline__ void mma_h32(float* c, const uint32_t* a, const uint32_t* b) {
    asm volatile(
        "mma.sync.aligned.m16n8k16.row.col.f32.f16.f16.f32 "
        "{%0,%1,%2,%3}, {%4,%5,%6,%7}, {%8,%9}, {%0,%1,%2,%3};"
        : "+f"(c[0]), "+f"(c[1]), "+f"(c[2]), "+f"(c[3])
        : "r"(a[0]), "r"(a[1]), "r"(a[2]), "r"(a[3]), "r"(b[0]), "r"(b[1]));
}

// fp16 mma, f16 acc (fused cross terms; potentially double-rate)
__device__ __forceinline__ void mma_h16(uint32_t* c, const uint32_t* a, const uint32_t* b) {
    asm volatile(
        "mma.sync.aligned.m16n8k16.row.col.f16.f16.f16.f16 "
        "{%0,%1}, {%2,%3,%4,%5}, {%6,%7}, {%0,%1};"
        : "+r"(c[0]), "+r"(c[1])
        : "r"(a[0]), "r"(a[1]), "r"(a[2]), "r"(a[3]), "r"(b[0]), "r"(b[1]));
}

// bf16 split (tc_gemm)
__device__ __forceinline__ void split_store_pair(char* base, int row, int col2,
                                                 float x0, float x1) {
    __nv_bfloat16 h0 = __float2bfloat16(x0);
    __nv_bfloat16 h1 = __float2bfloat16(x1);
    __nv_bfloat16 l0 = __float2bfloat16(x0 - __bfloat162float(h0));
    __nv_bfloat16 l1 = __float2bfloat16(x1 - __bfloat162float(h1));
    __nv_bfloat162 hp; hp.x = h0; hp.y = h1;
    __nv_bfloat162 lp; lp.x = l0; lp.y = l1;
    *(__nv_bfloat162*)(base + sw128(row * 128 + col2 * 2)) = hp;
    *(__nv_bfloat162*)(base + sw128(row * 128 + 64 + col2 * 2)) = lp;
}

// fp16 split of a pair (fused)
__device__ __forceinline__ void split2h(float x, float y, uint32_t& hi, uint32_t& lo) {
    __half2 hp = __floats2half2_rn(x, y);
    float rx = x - __half2float(__low2half(hp));
    float ry = y - __half2float(__high2half(hp));
    __half2 lp = __floats2half2_rn(rx, ry);
    hi = *(uint32_t*)&hp;
    lo = *(uint32_t*)&lp;
}

__constant__ int c_aofs[3] = {0, 0, 32};
__constant__ int c_bofs[3] = {0, 32, 0};

// ---------------------------------------------------------------------------
// GEMM body (bf16x3, proven): C[rows] = A*B^T + bias, tile 128x128, BK=32
// ---------------------------------------------------------------------------
__device__ __forceinline__ void gemm_body(
    const float* __restrict__ A, const float* __restrict__ B,
    float* __restrict__ C, int K, int lda, int ldb, int ldc,
    const float* __restrict__ bias, int row0, int col0)
{
    __shared__ __align__(128) char smA[128 * 128];
    __shared__ __align__(128) char smB[128 * 128];

    const int tid = threadIdx.x;
    const int warp = tid >> 5, lane = tid & 31;
    const int wm0 = (warp >> 1) * 32;
    const int wn0 = (warp & 1) * 64;

    uint32_t sA = smem_u32(smA);
    uint32_t sB = smem_u32(smB);

    float c[2][8][4];
#pragma unroll
    for (int i = 0; i < 2; i++)
#pragma unroll
        for (int j = 0; j < 8; j++)
#pragma unroll
            for (int t = 0; t < 4; t++) c[i][j][t] = 0.f;

    const int lr = tid >> 4;
    const int lp = tid & 15;

    for (int k0 = 0; k0 < K; k0 += 32) {
#pragma unroll
        for (int s = 0; s < 8; s++) {
            int r = s * 16 + lr;
            float2 va = *(const float2*)&A[(size_t)(row0 + r) * lda + k0 + 2 * lp];
            split_store_pair(smA, r, 2 * lp, va.x, va.y);
            float2 vb = *(const float2*)&B[(size_t)(col0 + r) * ldb + k0 + 2 * lp];
            split_store_pair(smB, r, 2 * lp, vb.x, vb.y);
        }
        __syncthreads();

        const int arow = wm0 + (lane & 15);
        const int acolq = (lane >> 4) * 8;
        const int bn = wn0 + (lane & 7) + ((lane >> 4) << 3);
        const int bkq = ((lane >> 3) & 1) * 8;

#pragma unroll
        for (int s3 = 0; s3 < 3; s3++) {
            const int aoff = c_aofs[s3], boff = c_bofs[s3];
#pragma unroll
            for (int ks = 0; ks < 2; ks++) {
                int acol = aoff + ks * 16 + acolq;
                uint32_t a0[4], a1[4];
                ldsm4(a0, sA + sw128((uint32_t)(arow * 128 + acol * 2)));
                ldsm4(a1, sA + sw128((uint32_t)((arow + 16) * 128 + acol * 2)));
                int bcol = boff + ks * 16 + bkq;
                uint32_t bq[4][4];
#pragma unroll
                for (int j2 = 0; j2 < 4; j2++)
                    ldsm4(bq[j2], sB + sw128((uint32_t)((bn + j2 * 16) * 128 + bcol * 2)));
#pragma unroll
                for (int i = 0; i < 2; i++) {
                    const uint32_t* ai = (i == 0) ? a0 : a1;
#pragma unroll
                    for (int j = 0; j < 8; j++)
                        mma16816(c[i][j], ai, &bq[j >> 1][(j & 1) * 2]);
                }
            }
        }
        __syncthreads();
    }

    const int g = lane >> 2, t4 = lane & 3;
#pragma unroll
    for (int i = 0; i < 2; i++) {
#pragma unroll
        for (int j = 0; j < 8; j++) {
            int gr0 = row0 + wm0 + i * 16 + g;
            int gc = col0 + wn0 + j * 8 + t4 * 2;
            float v0 = c[i][j][0], v1 = c[i][j][1];
            float v2 = c[i][j][2], v3 = c[i][j][3];
            if (bias) {
                float2 bv = *(const float2*)&bias[gc];
                v0 += bv.x; v1 += bv.y; v2 += bv.x; v3 += bv.y;
            }
            *(float2*)&C[(size_t)gr0 * ldc + gc] = make_float2(v0, v1);
            *(float2*)&C[(size_t)(gr0 + 8) * ldc + gc] = make_float2(v2, v3);
        }
    }
}

__global__ __launch_bounds__(256) void tc_gemm(
    const float* __restrict__ A, const float* __restrict__ B,
    float* __restrict__ C, int K, int lda, int ldb, int ldc,
    const float* __restrict__ bias, int row_base)
{
    gemm_body(A, B, C, K, lda, ldb, ldc, bias,
              row_base + blockIdx.y * 128, blockIdx.x * 128);
}

// Batched q/k/v projection: z selects input/weight/bias/output
__global__ __launch_bounds__(256) void proj_qkv(
    const float* __restrict__ query, const float* __restrict__ key,
    const float* __restrict__ value,
    const float* __restrict__ Wq, const float* __restrict__ Wk,
    const float* __restrict__ Wv,
    const float* __restrict__ bq, const float* __restrict__ bk,
    const float* __restrict__ bv)
{
    const int z = blockIdx.z;
    const float* A = (z == 0) ? query : (z == 1) ? key : value;
    const float* B = (z == 0) ? Wq : (z == 1) ? Wk : Wv;
    const float* bias = (z == 0) ? bq : (z == 1) ? bk : bv;
    float* C = (z == 0) ? g_q : (z == 1) ? g_k : g_v;
    gemm_body(A, B, C, E, E, E, E, bias, blockIdx.y * 128, blockIdx.x * 128);
}

// ---------------------------------------------------------------------------
// fused_attn (R5 structure, fp16 split, cross terms in f16-acc):
// 256 threads, 128 q-rows/CTA, grid (S/128, H), 64KB dyn smem.
// pass1: l = sum exp((q k^T)*SCALE + rel*SCALE)
// pass2: w = exp(.)/l -> gmem; PV via C-frag->A-frag reuse.
// ---------------------------------------------------------------------------
__global__ __launch_bounds__(256) void fused_attn(
    const float* __restrict__ rel, float* __restrict__ wout)
{
    extern __shared__ char dyn[];
    char* skh = dyn;
    char* skl = dyn + 16384;
    char* svh = dyn + 32768;
    char* svl = dyn + 49152;

    const int tid = threadIdx.x;
    const int warp = tid >> 5, lane = tid & 31;
    const int g = lane >> 2, t4 = lane & 3;
    const int h = blockIdx.y;
    const int row0 = blockIdx.x * 128;
    const int qc0 = h * HD;

    const uint32_t uSkh = smem_u32(skh);
    const uint32_t uSkl = smem_u32(skl);
    const uint32_t uSvh = smem_u32(svh);
    const uint32_t uSvl = smem_u32(svl);

    const int rA = row0 + warp * 16 + g;
    const int rB = rA + 8;

    // q fragments (fp16 split, pre-scaled)
    uint32_t qh[4][4], ql[4][4];
#pragma unroll
    for (int ks = 0; ks < 4; ks++) {
        int c = qc0 + ks * 16 + 2 * t4;
        float2 x00 = *(const float2*)&g_q[(size_t)rA * E + c];
        float2 x10 = *(const float2*)&g_q[(size_t)rB * E + c];
        float2 x01 = *(const float2*)&g_q[(size_t)rA * E + c + 8];
        float2 x11 = *(const float2*)&g_q[(size_t)rB * E + c + 8];
        split2h(x00.x * SCALE, x00.y * SCALE, qh[ks][0], ql[ks][0]);
        split2h(x10.x * SCALE, x10.y * SCALE, qh[ks][1], ql[ks][1]);
        split2h(x01.x * SCALE, x01.y * SCALE, qh[ks][2], ql[ks][2]);
        split2h(x11.x * SCALE, x11.y * SCALE, qh[ks][3], ql[ks][3]);
    }

    const int lr = tid >> 4, lp = tid & 15;
    const int bnp = (lane & 7) + ((lane >> 4) << 3);
    const int bkq = ((lane >> 3) & 1) * 8;

    float lA = 0.f, lB = 0.f;

    // ===================== PASS 1 =====================
#pragma unroll 1
    for (int t0 = 0; t0 < S; t0 += 128) {
        __syncthreads();
#pragma unroll
        for (int s = 0; s < 8; s++) {
            int tr = s * 16 + lr;
            float4 kv = *(const float4*)&g_k[(size_t)(t0 + tr) * E + qc0 + 4 * lp];
            uint32_t h0, l0, h1, l1;
            split2h(kv.x, kv.y, h0, l0);
            split2h(kv.z, kv.w, h1, l1);
            *(uint2*)(skh + sw128(tr * 128 + 8 * lp)) = make_uint2(h0, h1);
            *(uint2*)(skl + sw128(tr * 128 + 8 * lp)) = make_uint2(l0, l1);
        }
        __syncthreads();

#pragma unroll 1
        for (int ch = 0; ch < 8; ch++) {
            int cg = t0 + ch * 16 + 2 * t4;
            float2 r00 = *(const float2*)&rel[(size_t)rA * S + cg];
            float2 r10 = *(const float2*)&rel[(size_t)rB * S + cg];
            float2 r01 = *(const float2*)&rel[(size_t)rA * S + cg + 8];
            float2 r11 = *(const float2*)&rel[(size_t)rB * S + cg + 8];

            float cs[2][4];
            uint32_t cx[2][2];
#pragma unroll
            for (int i = 0; i < 2; i++) {
#pragma unroll
                for (int t = 0; t < 4; t++) cs[i][t] = 0.f;
                cx[i][0] = 0u; cx[i][1] = 0u;
            }
            int brow = ch * 16 + bnp;
#pragma unroll
            for (int ks = 0; ks < 4; ks++) {
                uint32_t bh[4], bl[4];
                uint32_t cb = (uint32_t)((ks * 16 + bkq) * 2);
                ldsm4(bh, uSkh + sw128(brow * 128 + cb));
                ldsm4(bl, uSkl + sw128(brow * 128 + cb));
                mma_h32(cs[0], qh[ks], bh + 0);
                mma_h32(cs[1], qh[ks], bh + 2);
                mma_h16(cx[0], qh[ks], bl + 0);
                mma_h16(cx[1], qh[ks], bl + 2);
                mma_h16(cx[0], ql[ks], bh + 0);
                mma_h16(cx[1], ql[ks], bh + 2);
            }
            float2 x0a = __half22float2(*(__half2*)&cx[0][0]);
            float2 x0b = __half22float2(*(__half2*)&cx[0][1]);
            float2 x1a = __half22float2(*(__half2*)&cx[1][0]);
            float2 x1b = __half22float2(*(__half2*)&cx[1][1]);
            lA += __expf(cs[0][0] + x0a.x + r00.x * SCALE) +
                  __expf(cs[0][1] + x0a.y + r00.y * SCALE) +
                  __expf(cs[1][0] + x1a.x + r01.x * SCALE) +
                  __expf(cs[1][1] + x1a.y + r01.y * SCALE);
            lB += __expf(cs[0][2] + x0b.x + r10.x * SCALE) +
                  __expf(cs[0][3] + x0b.y + r10.y * SCALE) +
                  __expf(cs[1][2] + x1b.x + r11.x * SCALE) +
                  __expf(cs[1][3] + x1b.y + r11.y * SCALE);
        }
    }

    lA += __shfl_xor_sync(0xffffffffu, lA, 1);
    lA += __shfl_xor_sync(0xffffffffu, lA, 2);
    lB += __shfl_xor_sync(0xffffffffu, lB, 1);
    lB += __shfl_xor_sync(0xffffffffu, lB, 2);
    const float invA = 1.f / lA, invB = 1.f / lB;

    float o[8][4];
    uint32_t ox[8][2];
#pragma unroll
    for (int j = 0; j < 8; j++) {
#pragma unroll
        for (int t = 0; t < 4; t++) o[j][t] = 0.f;
        ox[j][0] = 0u; ox[j][1] = 0u;
    }

    float* wrow = wout + (size_t)h * S * S;

    // ===================== PASS 2 =====================
#pragma unroll 1
    for (int t0 = 0; t0 < S; t0 += 128) {
        __syncthreads();
#pragma unroll
        for (int s = 0; s < 8; s++) {
            int tr = s * 16 + lr;
            float4 kv = *(const float4*)&g_k[(size_t)(t0 + tr) * E + qc0 + 4 * lp];
            uint32_t h0, l0, h1, l1;
            split2h(kv.x, kv.y, h0, l0);
            split2h(kv.z, kv.w, h1, l1);
            *(uint2*)(skh + sw128(tr * 128 + 8 * lp)) = make_uint2(h0, h1);
            *(uint2*)(skl + sw128(tr * 128 + 8 * lp)) = make_uint2(l0, l1);

            float4 vv = *(const float4*)&g_v[(size_t)(t0 + tr) * E + qc0 + 4 * lp];
            int sub = tr >> 6, tc = tr & 63;
            char* bh_ = svh + sub * 8192;
            char* bl_ = svl + sub * 8192;
            float vs[4] = {vv.x, vv.y, vv.z, vv.w};
#pragma unroll
            for (int j = 0; j < 4; j++) {
                int d = 4 * lp + j;
                __half hb = __float2half_rn(vs[j]);
                __half lb = __float2half_rn(vs[j] - __half2float(hb));
                *(__half*)(bh_ + sw128(d * 128 + tc * 2)) = hb;
                *(__half*)(bl_ + sw128(d * 128 + tc * 2)) = lb;
            }
        }
        __syncthreads();

#pragma unroll 1
        for (int ch = 0; ch < 8; ch++) {
            int cg = t0 + ch * 16 + 2 * t4;
            float2 r00 = *(const float2*)&rel[(size_t)rA * S + cg];
            float2 r10 = *(const float2*)&rel[(size_t)rB * S + cg];
            float2 r01 = *(const float2*)&rel[(size_t)rA * S + cg + 8];
            float2 r11 = *(const float2*)&rel[(size_t)rB * S + cg + 8];

            float cs[2][4];
            uint32_t cx[2][2];
#pragma unroll
            for (int i = 0; i < 2; i++) {
#pragma unroll
                for (int t = 0; t < 4; t++) cs[i][t] = 0.f;
                cx[i][0] = 0u; cx[i][1] = 0u;
            }
            int brow = ch * 16 + bnp;
#pragma unroll
            for (int ks = 0; ks < 4; ks++) {
                uint32_t bh[4], bl[4];
                uint32_t cb = (uint32_t)((ks * 16 + bkq) * 2);
                ldsm4(bh, uSkh + sw128(brow * 128 + cb));
                ldsm4(bl, uSkl + sw128(brow * 128 + cb));
                mma_h32(cs[0], qh[ks], bh + 0);
                mma_h32(cs[1], qh[ks], bh + 2);
                mma_h16(cx[0], qh[ks], bl + 0);
                mma_h16(cx[1], qh[ks], bl + 2);
                mma_h16(cx[0], ql[ks], bh + 0);
                mma_h16(cx[1], ql[ks], bh + 2);
            }
            float2 x0a = __half22float2(*(__half2*)&cx[0][0]);
            float2 x0b = __half22float2(*(__half2*)&cx[0][1]);
            float2 x1a = __half22float2(*(__half2*)&cx[1][0]);
            float2 x1b = __half22float2(*(__half2*)&cx[1][1]);

            float wA0 = __expf(cs[0][0] + x0a.x + r00.x * SCALE) * invA;
            float wA1 = __expf(cs[0][1] + x0a.y + r00.y * SCALE) * invA;
            float wA2 = __expf(cs[1][0] + x1a.x + r01.x * SCALE) * invA;
            float wA3 = __expf(cs[1][1] + x1a.y + r01.y * SCALE) * invA;
            float wB0 = __expf(cs[0][2] + x0b.x + r10.x * SCALE) * invB;
            float wB1 = __expf(cs[0][3] + x0b.y + r10.y * SCALE) * invB;
            float wB2 = __expf(cs[1][2] + x1b.x + r11.x * SCALE) * invB;
            float wB3 = __expf(cs[1][3] + x1b.y + r11.y * SCALE) * invB;

            *(float2*)&wrow[(size_t)rA * S + cg]     = make_float2(wA0, wA1);
            *(float2*)&wrow[(size_t)rA * S + cg + 8] = make_float2(wA2, wA3);
            *(float2*)&wrow[(size_t)rB * S + cg]     = make_float2(wB0, wB1);
            *(float2*)&wrow[(size_t)rB * S + cg + 8] = make_float2(wB2, wB3);

            uint32_t ah[4], al[4];
            split2h(wA0, wA1, ah[0], al[0]);
            split2h(wB0, wB1, ah[1], al[1]);
            split2h(wA2, wA3, ah[2], al[2]);
            split2h(wB2, wB3, ah[3], al[3]);

            int sub = ch >> 2;
            uint32_t cb = (uint32_t)(((ch & 3) * 16 + bkq) * 2);
            uint32_t vbaseh = uSvh + sub * 8192;
            uint32_t vbasel = uSvl + sub * 8192;
#pragma unroll
            for (int jd = 0; jd < 4; jd++) {
                int dn = jd * 16 + bnp;
                uint32_t vh[4], vl[4];
                ldsm4(vh, vbaseh + sw128(dn * 128 + cb));
                ldsm4(vl, vbasel + sw128(dn * 128 + cb));
                mma_h32(o[2 * jd],      ah, vh + 0);
                mma_h32(o[2 * jd + 1],  ah, vh + 2);
                mma_h16(ox[2 * jd],     ah, vl + 0);
                mma_h16(ox[2 * jd + 1], ah, vl + 2);
                mma_h16(ox[2 * jd],     al, vh + 0);
                mma_h16(ox[2 * jd + 1], al, vh + 2);
            }
        }
    }

    // epilogue: attn = o(f32) + cross(f16) -> g_attn
#pragma unroll
    for (int j = 0; j < 8; j++) {
        int gc = qc0 + j * 8 + 2 * t4;
        float2 ca = __half22float2(*(__half2*)&ox[j][0]);
        float2 cb2 = __half22float2(*(__half2*)&ox[j][1]);
        *(float2*)&g_attn[(size_t)rA * E + gc] =
            make_float2(o[j][0] + ca.x, o[j][1] + ca.y);
        *(float2*)&g_attn[(size_t)rB * E + gc] =
            make_float2(o[j][2] + cb2.x, o[j][3] + cb2.y);
    }
}

// ---------------------------------------------------------------------------
// Launch.  Order matters: ncu capture lands on launch index 3 == fused_attn.
// ---------------------------------------------------------------------------
extern "C" void kernel_launch(void* const* d_in, const int* in_sizes, int n_in,
                              void* d_out, int out_size)
{
    (void)in_sizes; (void)n_in; (void)out_size;
    const float* query = (const float*)d_in[0];
    const float* key   = (const float*)d_in[1];
    const float* value = (const float*)d_in[2];
    const float* sim   = (const float*)d_in[3];
    const float* Wq    = (const float*)d_in[4];
    const float* bq    = (const float*)d_in[5];
    const float* Wk    = (const float*)d_in[6];
    const float* bk    = (const float*)d_in[7];
    const float* Wv    = (const float*)d_in[8];
    const float* bv    = (const float*)d_in[9];
    const float* Wo    = (const float*)d_in[10];
    const float* bo    = (const float*)d_in[11];

    float* out = (float*)d_out;                 // [S,E]
    float* w   = out + (size_t)S * E;           // [H,S,S]

    float *grel, *gattn;
    cudaGetSymbolAddress((void**)&grel,  g_rel);
    cudaGetSymbolAddress((void**)&gattn, g_attn);

    static int attr_done = 0;
    if (!attr_done) {
        cudaFuncSetAttribute(fused_attn,
                             cudaFuncAttributeMaxDynamicSharedMemorySize, 65536);
        attr_done = 1;
    }

    dim3 blk(256);

    // 0: q/k/v projections (batched, z = 0/1/2)
    proj_qkv<<<dim3(E / 128, S / 128, 3), blk>>>(query, key, value,
                                                 Wq, Wk, Wv, bq, bk, bv);

    // 1,2: rel = sim @ sim^T (split into two half-grids)
    tc_gemm<<<dim3(S / 128, 8), blk>>>(sim, sim, grel, HD, HD, HD, S, nullptr, 0);
    tc_gemm<<<dim3(S / 128, 8), blk>>>(sim, sim, grel, HD, HD, HD, S, nullptr, 1024);

    // 3: fused attention  (<-- ncu capture index)
    fused_attn<<<dim3(S / 128, H), blk, 65536>>>(grel, w);

    // 4: out = attn @ Wo^T + bo
    tc_gemm<<<dim3(E / 128, S / 128), blk>>>(gattn, Wo, out, E, E, E, E, bo, 0);
}

// round 10
// speedup vs baseline: 1.2146x; 1.0530x over previous
#include <cuda_runtime.h>
#include <cuda_bf16.h>
#include <cuda_fp16.h>
#include <cstdint>
#include <cstddef>

#define S 2048
#define E 1024
#define H 16
#define HD 64
#define NT 16
#define SCALE 0.125f

// Scratch
__device__ float g_q[S * E];
__device__ float g_k[S * E];
__device__ float g_v[S * E];
__device__ float g_rel[S * S];
__device__ float g_attn[S * E];
// fp16 hi/lo pre-swizzled tile images (exact smem byte layout)
__device__ __align__(128) char g_kt[H * NT * 32768];   // [khi 16K][klo 16K]
__device__ __align__(128) char g_vt[H * NT * 32768];   // [vhi 16K][vlo 16K]

// ---------------------------------------------------------------------------
// Helpers
// ---------------------------------------------------------------------------
__device__ __forceinline__ uint32_t smem_u32(const void* p) {
    uint32_t a;
    asm("{ .reg .u64 t; cvta.to.shared.u64 t, %1; cvt.u32.u64 %0, t; }"
        : "=r"(a) : "l"(p));
    return a;
}

__device__ __forceinline__ uint32_t sw128(uint32_t off) {
    return off ^ ((off >> 3) & 0x70);
}

__device__ __forceinline__ void ldsm4(uint32_t* r, uint32_t addr) {
    asm volatile("ldmatrix.sync.aligned.m8n8.x4.shared.b16 {%0,%1,%2,%3}, [%4];"
                 : "=r"(r[0]), "=r"(r[1]), "=r"(r[2]), "=r"(r[3]) : "r"(addr));
}

// bf16 mma, f32 acc (GEMM path — proven)
__device__ __forceinline__ void mma16816(float* c, const uint32_t* a, const uint32_t* b) {
    asm volatile(
        "mma.sync.aligned.m16n8k16.row.col.f32.bf16.bf16.f32 "
        "{%0,%1,%2,%3}, {%4,%5,%6,%7}, {%8,%9}, {%0,%1,%2,%3};"
        : "+f"(c[0]), "+f"(c[1]), "+f"(c[2]), "+f"(c[3])
        : "r"(a[0]), "r"(a[1]), "r"(a[2]), "r"(a[3]), "r"(b[0]), "r"(b[1]));
}

// fp16 mma, f32 acc (fused hi*hi)
__device__ __forceinline__ void mma_h32(float* c, const uint32_t* a, const uint32_t* b) {
    asm volatile(
        "mma.sync.aligned.m16n8k16.row.col.f32.f16.f16.f32 "
        "{%0,%1,%2,%3}, {%4,%5,%6,%7}, {%8,%9}, {%0,%1,%2,%3};"
        : "+f"(c[0]), "+f"(c[1]), "+f"(c[2]), "+f"(c[3])
        : "r"(a[0]), "r"(a[1]), "r"(a[2]), "r"(a[3]), "r"(b[0]), "r"(b[1]));
}

// fp16 mma, f16 acc (fused cross terms)
__device__ __forceinline__ void mma_h16(uint32_t* c, const uint32_t* a, const uint32_t* b) {
    asm volatile(
        "mma.sync.aligned.m16n8k16.row.col.f16.f16.f16.f16 "
        "{%0,%1}, {%2,%3,%4,%5}, {%6,%7}, {%0,%1};"
        : "+r"(c[0]), "+r"(c[1])
        : "r"(a[0]), "r"(a[1]), "r"(a[2]), "r"(a[3]), "r"(b[0]), "r"(b[1]));
}

// bf16 split (GEMM)
__device__ __forceinline__ void split_store_pair(char* base, int row, int col2,
                                                 float x0, float x1) {
    __nv_bfloat16 h0 = __float2bfloat16(x0);
    __nv_bfloat16 h1 = __float2bfloat16(x1);
    __nv_bfloat16 l0 = __float2bfloat16(x0 - __bfloat162float(h0));
    __nv_bfloat16 l1 = __float2bfloat16(x1 - __bfloat162float(h1));
    __nv_bfloat162 hp; hp.x = h0; hp.y = h1;
    __nv_bfloat162 lp; lp.x = l0; lp.y = l1;
    *(__nv_bfloat162*)(base + sw128(row * 128 + col2 * 2)) = hp;
    *(__nv_bfloat162*)(base + sw128(row * 128 + 64 + col2 * 2)) = lp;
}

// fp16 split of a pair
__device__ __forceinline__ void split2h(float x, float y, uint32_t& hi, uint32_t& lo) {
    __half2 hp = __floats2half2_rn(x, y);
    float rx = x - __half2float(__low2half(hp));
    float ry = y - __half2float(__high2half(hp));
    __half2 lp = __floats2half2_rn(rx, ry);
    hi = *(uint32_t*)&hp;
    lo = *(uint32_t*)&lp;
}

#define CP16(dst, src) \
    asm volatile("cp.async.cg.shared.global [%0], [%1], 16;" :: "r"(dst), "l"(src))
#define CP_COMMIT() asm volatile("cp.async.commit_group;" ::: "memory")
#define CP_WAIT(n)  asm volatile("cp.async.wait_group %0;" :: "n"(n) : "memory")

__constant__ int c_aofs[3] = {0, 0, 32};
__constant__ int c_bofs[3] = {0, 32, 0};

// ---------------------------------------------------------------------------
// GEMM body (bf16x3, proven)
// ---------------------------------------------------------------------------
__device__ __forceinline__ void gemm_body(
    const float* __restrict__ A, const float* __restrict__ B,
    float* __restrict__ C, int K, int lda, int ldb, int ldc,
    const float* __restrict__ bias, int row0, int col0)
{
    __shared__ __align__(128) char smA[128 * 128];
    __shared__ __align__(128) char smB[128 * 128];

    const int tid = threadIdx.x;
    const int warp = tid >> 5, lane = tid & 31;
    const int wm0 = (warp >> 1) * 32;
    const int wn0 = (warp & 1) * 64;

    uint32_t sA = smem_u32(smA);
    uint32_t sB = smem_u32(smB);

    float c[2][8][4];
#pragma unroll
    for (int i = 0; i < 2; i++)
#pragma unroll
        for (int j = 0; j < 8; j++)
#pragma unroll
            for (int t = 0; t < 4; t++) c[i][j][t] = 0.f;

    const int lr = tid >> 4;
    const int lp = tid & 15;

    for (int k0 = 0; k0 < K; k0 += 32) {
#pragma unroll
        for (int s = 0; s < 8; s++) {
            int r = s * 16 + lr;
            float2 va = *(const float2*)&A[(size_t)(row0 + r) * lda + k0 + 2 * lp];
            split_store_pair(smA, r, 2 * lp, va.x, va.y);
            float2 vb = *(const float2*)&B[(size_t)(col0 + r) * ldb + k0 + 2 * lp];
            split_store_pair(smB, r, 2 * lp, vb.x, vb.y);
        }
        __syncthreads();

        const int arow = wm0 + (lane & 15);
        const int acolq = (lane >> 4) * 8;
        const int bn = wn0 + (lane & 7) + ((lane >> 4) << 3);
        const int bkq = ((lane >> 3) & 1) * 8;

#pragma unroll
        for (int s3 = 0; s3 < 3; s3++) {
            const int aoff = c_aofs[s3], boff = c_bofs[s3];
#pragma unroll
            for (int ks = 0; ks < 2; ks++) {
                int acol = aoff + ks * 16 + acolq;
                uint32_t a0[4], a1[4];
                ldsm4(a0, sA + sw128((uint32_t)(arow * 128 + acol * 2)));
                ldsm4(a1, sA + sw128((uint32_t)((arow + 16) * 128 + acol * 2)));
                int bcol = boff + ks * 16 + bkq;
                uint32_t bq[4][4];
#pragma unroll
                for (int j2 = 0; j2 < 4; j2++)
                    ldsm4(bq[j2], sB + sw128((uint32_t)((bn + j2 * 16) * 128 + bcol * 2)));
#pragma unroll
                for (int i = 0; i < 2; i++) {
                    const uint32_t* ai = (i == 0) ? a0 : a1;
#pragma unroll
                    for (int j = 0; j < 8; j++)
                        mma16816(c[i][j], ai, &bq[j >> 1][(j & 1) * 2]);
                }
            }
        }
        __syncthreads();
    }

    const int g = lane >> 2, t4 = lane & 3;
#pragma unroll
    for (int i = 0; i < 2; i++) {
#pragma unroll
        for (int j = 0; j < 8; j++) {
            int gr0 = row0 + wm0 + i * 16 + g;
            int gc = col0 + wn0 + j * 8 + t4 * 2;
            float v0 = c[i][j][0], v1 = c[i][j][1];
            float v2 = c[i][j][2], v3 = c[i][j][3];
            if (bias) {
                float2 bv = *(const float2*)&bias[gc];
                v0 += bv.x; v1 += bv.y; v2 += bv.x; v3 += bv.y;
            }
            *(float2*)&C[(size_t)gr0 * ldc + gc] = make_float2(v0, v1);
            *(float2*)&C[(size_t)(gr0 + 8) * ldc + gc] = make_float2(v2, v3);
        }
    }
}

__global__ __launch_bounds__(256) void tc_gemm(
    const float* __restrict__ A, const float* __restrict__ B,
    float* __restrict__ C, int K, int lda, int ldb, int ldc,
    const float* __restrict__ bias, int row_base)
{
    gemm_body(A, B, C, K, lda, ldb, ldc, bias,
              row_base + blockIdx.y * 128, blockIdx.x * 128);
}

__global__ __launch_bounds__(256) void proj_qkv(
    const float* __restrict__ query, const float* __restrict__ key,
    const float* __restrict__ value,
    const float* __restrict__ Wq, const float* __restrict__ Wk,
    const float* __restrict__ Wv,
    const float* __restrict__ bq, const float* __restrict__ bk,
    const float* __restrict__ bv)
{
    const int z = blockIdx.z;
    const float* A = (z == 0) ? query : (z == 1) ? key : value;
    const float* B = (z == 0) ? Wq : (z == 1) ? Wk : Wv;
    const float* bias = (z == 0) ? bq : (z == 1) ? bk : bv;
    float* C = (z == 0) ? g_q : (z == 1) ? g_k : g_v;
    gemm_body(A, B, C, E, E, E, E, bias, blockIdx.y * 128, blockIdx.x * 128);
}

// ---------------------------------------------------------------------------
// prep_kv: fp16 hi/lo pre-swizzled 32KB tile images. grid (NT, H), 128 thr.
// ---------------------------------------------------------------------------
__global__ __launch_bounds__(128) void prep_kv()
{
    const int tid = threadIdx.x;
    const int t0 = blockIdx.x * 128;
    const int h = blockIdx.y;
    const int qc0 = h * HD;
    char* kimg = g_kt + ((size_t)(h * NT + blockIdx.x)) * 32768;
    char* vimg = g_vt + ((size_t)(h * NT + blockIdx.x)) * 32768;

    const int lr = tid >> 4, lp = tid & 15;
#pragma unroll 4
    for (int s = 0; s < 16; s++) {
        int tr = s * 8 + lr;
        float4 kv = *(const float4*)&g_k[(size_t)(t0 + tr) * E + qc0 + 4 * lp];
        uint32_t h0, l0, h1, l1;
        split2h(kv.x, kv.y, h0, l0);
        split2h(kv.z, kv.w, h1, l1);
        *(uint2*)(kimg + sw128(tr * 128 + 8 * lp)) = make_uint2(h0, h1);
        *(uint2*)(kimg + 16384 + sw128(tr * 128 + 8 * lp)) = make_uint2(l0, l1);

        float4 vv = *(const float4*)&g_v[(size_t)(t0 + tr) * E + qc0 + 4 * lp];
        int sub = tr >> 6, tc = tr & 63;
        char* bh_ = vimg + sub * 8192;
        char* bl_ = vimg + 16384 + sub * 8192;
        float vs[4] = {vv.x, vv.y, vv.z, vv.w};
#pragma unroll
        for (int j = 0; j < 4; j++) {
            int d = 4 * lp + j;
            __half hb = __float2half_rn(vs[j]);
            __half lb = __float2half_rn(vs[j] - __half2float(hb));
            *(__half*)(bh_ + sw128(d * 128 + tc * 2)) = hb;
            *(__half*)(bl_ + sw128(d * 128 + tc * 2)) = lb;
        }
    }
}

// ---------------------------------------------------------------------------
// fused_attn: 256 threads, 128 q-rows/CTA, grid (S/128, H), 96KB smem.
//   [0,32K)=kbuf0  [32K,64K)=kbuf1  [64K,96K)=vbuf
// All staging via cp.async from pre-split images (no STS/CVT in loop).
// ---------------------------------------------------------------------------
__global__ __launch_bounds__(256) void fused_attn(
    const float* __restrict__ rel, float* __restrict__ wout)
{
    extern __shared__ char dyn[];
    const uint32_t smb = smem_u32(dyn);
    const uint32_t vbuf = smb + 65536;

    const int tid = threadIdx.x;
    const int warp = tid >> 5, lane = tid & 31;
    const int g = lane >> 2, t4 = lane & 3;
    const int h = blockIdx.y;
    const int row0 = blockIdx.x * 128;
    const int qc0 = h * HD;

    const int rA = row0 + warp * 16 + g;
    const int rB = rA + 8;

    // q fragments (fp16 split, pre-scaled)
    uint32_t qh[4][4], ql[4][4];
#pragma unroll
    for (int ks = 0; ks < 4; ks++) {
        int c = qc0 + ks * 16 + 2 * t4;
        float2 x00 = *(const float2*)&g_q[(size_t)rA * E + c];
        float2 x10 = *(const float2*)&g_q[(size_t)rB * E + c];
        float2 x01 = *(const float2*)&g_q[(size_t)rA * E + c + 8];
        float2 x11 = *(const float2*)&g_q[(size_t)rB * E + c + 8];
        split2h(x00.x * SCALE, x00.y * SCALE, qh[ks][0], ql[ks][0]);
        split2h(x10.x * SCALE, x10.y * SCALE, qh[ks][1], ql[ks][1]);
        split2h(x01.x * SCALE, x01.y * SCALE, qh[ks][2], ql[ks][2]);
        split2h(x11.x * SCALE, x11.y * SCALE, qh[ks][3], ql[ks][3]);
    }

    const int bnp = (lane & 7) + ((lane >> 4) << 3);
    const int bkq = ((lane >> 3) & 1) * 8;

    const char* ksrc = g_kt + ((size_t)h * NT) * 32768;
    const char* vsrc = g_vt + ((size_t)h * NT) * 32768;

    float lA = 0.f, lB = 0.f;

    // ===================== PASS 1: row sums (double-buffered k) ==========
#pragma unroll
    for (int i = 0; i < 8; i++) {
        uint32_t off = (uint32_t)(tid + i * 256) * 16;
        CP16(smb + off, ksrc + off);
    }
    CP_COMMIT();

#pragma unroll 1
    for (int t = 0; t < NT; t++) {
        CP_WAIT(0);
        __syncthreads();
        if (t + 1 < NT) {
            const char* src = ksrc + (size_t)(t + 1) * 32768;
            uint32_t dst = smb + ((t + 1) & 1) * 32768;
#pragma unroll
            for (int i = 0; i < 8; i++) {
                uint32_t off = (uint32_t)(tid + i * 256) * 16;
                CP16(dst + off, src + off);
            }
            CP_COMMIT();
        }
        const uint32_t uSkh = smb + (t & 1) * 32768;
        const uint32_t uSkl = uSkh + 16384;

#pragma unroll 1
        for (int ch = 0; ch < 8; ch++) {
            int cg = t * 128 + ch * 16 + 2 * t4;
            float2 r00 = *(const float2*)&rel[(size_t)rA * S + cg];
            float2 r10 = *(const float2*)&rel[(size_t)rB * S + cg];
            float2 r01 = *(const float2*)&rel[(size_t)rA * S + cg + 8];
            float2 r11 = *(const float2*)&rel[(size_t)rB * S + cg + 8];

            float cs[2][4];
            uint32_t cx[2][2];
#pragma unroll
            for (int i = 0; i < 2; i++) {
#pragma unroll
                for (int t2 = 0; t2 < 4; t2++) cs[i][t2] = 0.f;
                cx[i][0] = 0u; cx[i][1] = 0u;
            }
            int brow = ch * 16 + bnp;
#pragma unroll
            for (int ks = 0; ks < 4; ks++) {
                uint32_t bh[4], bl[4];
                uint32_t cb = (uint32_t)((ks * 16 + bkq) * 2);
                ldsm4(bh, uSkh + sw128(brow * 128 + cb));
                ldsm4(bl, uSkl + sw128(brow * 128 + cb));
                mma_h32(cs[0], qh[ks], bh + 0);
                mma_h32(cs[1], qh[ks], bh + 2);
                mma_h16(cx[0], qh[ks], bl + 0);
                mma_h16(cx[1], qh[ks], bl + 2);
                mma_h16(cx[0], ql[ks], bh + 0);
                mma_h16(cx[1], ql[ks], bh + 2);
            }
            float2 x0a = __half22float2(*(__half2*)&cx[0][0]);
            float2 x0b = __half22float2(*(__half2*)&cx[0][1]);
            float2 x1a = __half22float2(*(__half2*)&cx[1][0]);
            float2 x1b = __half22float2(*(__half2*)&cx[1][1]);
            lA += __expf(cs[0][0] + x0a.x + r00.x * SCALE) +
                  __expf(cs[0][1] + x0a.y + r00.y * SCALE) +
                  __expf(cs[1][0] + x1a.x + r01.x * SCALE) +
                  __expf(cs[1][1] + x1a.y + r01.y * SCALE);
            lB += __expf(cs[0][2] + x0b.x + r10.x * SCALE) +
                  __expf(cs[0][3] + x0b.y + r10.y * SCALE) +
                  __expf(cs[1][2] + x1b.x + r11.x * SCALE) +
                  __expf(cs[1][3] + x1b.y + r11.y * SCALE);
        }
    }

    lA += __shfl_xor_sync(0xffffffffu, lA, 1);
    lA += __shfl_xor_sync(0xffffffffu, lA, 2);
    lB += __shfl_xor_sync(0xffffffffu, lB, 1);
    lB += __shfl_xor_sync(0xffffffffu, lB, 2);
    const float invA = 1.f / lA, invB = 1.f / lB;

    float o[8][4];
    uint32_t ox[8][2];
#pragma unroll
    for (int j = 0; j < 8; j++) {
#pragma unroll
        for (int t2 = 0; t2 < 4; t2++) o[j][t2] = 0.f;
        ox[j][0] = 0u; ox[j][1] = 0u;
    }

    float* wrow = wout + (size_t)h * S * S;

    // ===================== PASS 2: w + PV (pipelined) =====================
    __syncthreads();
#pragma unroll
    for (int i = 0; i < 8; i++) {
        uint32_t off = (uint32_t)(tid + i * 256) * 16;
        CP16(smb + off, ksrc + off);
    }
    CP_COMMIT();

#pragma unroll 1
    for (int t = 0; t < NT; t++) {
        // stage v_t (overlaps score MMAs)
        {
            const char* srcv = vsrc + (size_t)t * 32768;
#pragma unroll
            for (int i = 0; i < 8; i++) {
                uint32_t off = (uint32_t)(tid + i * 256) * 16;
                CP16(vbuf + off, srcv + off);
            }
            CP_COMMIT();
        }
        // stage k_{t+1} (overlaps PV)
        if (t + 1 < NT) {
            const char* src = ksrc + (size_t)(t + 1) * 32768;
            uint32_t dst = smb + ((t + 1) & 1) * 32768;
#pragma unroll
            for (int i = 0; i < 8; i++) {
                uint32_t off = (uint32_t)(tid + i * 256) * 16;
                CP16(dst + off, src + off);
            }
            CP_COMMIT();
        }
        if (t + 1 < NT) { CP_WAIT(2); } else { CP_WAIT(1); }
        __syncthreads();

        const uint32_t uSkh = smb + (t & 1) * 32768;
        const uint32_t uSkl = uSkh + 16384;

        uint32_t ahf[8][4], alf[8][4];
#pragma unroll 1
        for (int ch = 0; ch < 8; ch++) {
            int cg = t * 128 + ch * 16 + 2 * t4;
            float2 r00 = *(const float2*)&rel[(size_t)rA * S + cg];
            float2 r10 = *(const float2*)&rel[(size_t)rB * S + cg];
            float2 r01 = *(const float2*)&rel[(size_t)rA * S + cg + 8];
            float2 r11 = *(const float2*)&rel[(size_t)rB * S + cg + 8];

            float cs[2][4];
            uint32_t cx[2][2];
#pragma unroll
            for (int i = 0; i < 2; i++) {
#pragma unroll
                for (int t2 = 0; t2 < 4; t2++) cs[i][t2] = 0.f;
                cx[i][0] = 0u; cx[i][1] = 0u;
            }
            int brow = ch * 16 + bnp;
#pragma unroll
            for (int ks = 0; ks < 4; ks++) {
                uint32_t bh[4], bl[4];
                uint32_t cb = (uint32_t)((ks * 16 + bkq) * 2);
                ldsm4(bh, uSkh + sw128(brow * 128 + cb));
                ldsm4(bl, uSkl + sw128(brow * 128 + cb));
                mma_h32(cs[0], qh[ks], bh + 0);
                mma_h32(cs[1], qh[ks], bh + 2);
                mma_h16(cx[0], qh[ks], bl + 0);
                mma_h16(cx[1], qh[ks], bl + 2);
                mma_h16(cx[0], ql[ks], bh + 0);
                mma_h16(cx[1], ql[ks], bh + 2);
            }
            float2 x0a = __half22float2(*(__half2*)&cx[0][0]);
            float2 x0b = __half22float2(*(__half2*)&cx[0][1]);
            float2 x1a = __half22float2(*(__half2*)&cx[1][0]);
            float2 x1b = __half22float2(*(__half2*)&cx[1][1]);

            float wA0 = __expf(cs[0][0] + x0a.x + r00.x * SCALE) * invA;
            float wA1 = __expf(cs[0][1] + x0a.y + r00.y * SCALE) * invA;
            float wA2 = __expf(cs[1][0] + x1a.x + r01.x * SCALE) * invA;
            float wA3 = __expf(cs[1][1] + x1a.y + r01.y * SCALE) * invA;
            float wB0 = __expf(cs[0][2] + x0b.x + r10.x * SCALE) * invB;
            float wB1 = __expf(cs[0][3] + x0b.y + r10.y * SCALE) * invB;
            float wB2 = __expf(cs[1][2] + x1b.x + r11.x * SCALE) * invB;
            float wB3 = __expf(cs[1][3] + x1b.y + r11.y * SCALE) * invB;

            *(float2*)&wrow[(size_t)rA * S + cg]     = make_float2(wA0, wA1);
            *(float2*)&wrow[(size_t)rA * S + cg + 8] = make_float2(wA2, wA3);
            *(float2*)&wrow[(size_t)rB * S + cg]     = make_float2(wB0, wB1);
            *(float2*)&wrow[(size_t)rB * S + cg + 8] = make_float2(wB2, wB3);

            split2h(wA0, wA1, ahf[ch][0], alf[ch][0]);
            split2h(wB0, wB1, ahf[ch][1], alf[ch][1]);
            split2h(wA2, wA3, ahf[ch][2], alf[ch][2]);
            split2h(wB2, wB3, ahf[ch][3], alf[ch][3]);
        }

        if (t + 1 < NT) { CP_WAIT(1); } else { CP_WAIT(0); }
        __syncthreads();

        // -------- PV --------
#pragma unroll 1
        for (int ch = 0; ch < 8; ch++) {
            int sub = ch >> 2;
            uint32_t cb = (uint32_t)(((ch & 3) * 16 + bkq) * 2);
            uint32_t vbaseh = vbuf + sub * 8192;
            uint32_t vbasel = vbuf + 16384 + sub * 8192;
#pragma unroll
            for (int jd = 0; jd < 4; jd++) {
                int dn = jd * 16 + bnp;
                uint32_t vh[4], vl[4];
                ldsm4(vh, vbaseh + sw128(dn * 128 + cb));
                ldsm4(vl, vbasel + sw128(dn * 128 + cb));
                mma_h32(o[2 * jd],      ahf[ch], vh + 0);
                mma_h32(o[2 * jd + 1],  ahf[ch], vh + 2);
                mma_h16(ox[2 * jd],     ahf[ch], vl + 0);
                mma_h16(ox[2 * jd + 1], ahf[ch], vl + 2);
                mma_h16(ox[2 * jd],     alf[ch], vh + 0);
                mma_h16(ox[2 * jd + 1], alf[ch], vh + 2);
            }
        }
        __syncthreads();   // vbuf consumed before next staging
    }

    // epilogue
#pragma unroll
    for (int j = 0; j < 8; j++) {
        int gc = qc0 + j * 8 + 2 * t4;
        float2 ca = __half22float2(*(__half2*)&ox[j][0]);
        float2 cb2 = __half22float2(*(__half2*)&ox[j][1]);
        *(float2*)&g_attn[(size_t)rA * E + gc] =
            make_float2(o[j][0] + ca.x, o[j][1] + ca.y);
        *(float2*)&g_attn[(size_t)rB * E + gc] =
            make_float2(o[j][2] + cb2.x, o[j][3] + cb2.y);
    }
}

// ---------------------------------------------------------------------------
// Launch.  fused_attn must be launch index 3 (ncu capture).
// ---------------------------------------------------------------------------
extern "C" void kernel_launch(void* const* d_in, const int* in_sizes, int n_in,
                              void* d_out, int out_size)
{
    (void)in_sizes; (void)n_in; (void)out_size;
    const float* query = (const float*)d_in[0];
    const float* key   = (const float*)d_in[1];
    const float* value = (const float*)d_in[2];
    const float* sim   = (const float*)d_in[3];
    const float* Wq    = (const float*)d_in[4];
    const float* bq    = (const float*)d_in[5];
    const float* Wk    = (const float*)d_in[6];
    const float* bk    = (const float*)d_in[7];
    const float* Wv    = (const float*)d_in[8];
    const float* bv    = (const float*)d_in[9];
    const float* Wo    = (const float*)d_in[10];
    const float* bo    = (const float*)d_in[11];

    float* out = (float*)d_out;                 // [S,E]
    float* w   = out + (size_t)S * E;           // [H,S,S]

    float *grel, *gattn;
    cudaGetSymbolAddress((void**)&grel,  g_rel);
    cudaGetSymbolAddress((void**)&gattn, g_attn);

    static int attr_done = 0;
    if (!attr_done) {
        cudaFuncSetAttribute(fused_attn,
                             cudaFuncAttributeMaxDynamicSharedMemorySize, 98304);
        attr_done = 1;
    }

    dim3 blk(256);

    // 0: q/k/v projections (batched)
    proj_qkv<<<dim3(E / 128, S / 128, 3), blk>>>(query, key, value,
                                                 Wq, Wk, Wv, bq, bk, bv);

    // 1: pre-split k/v into fp16 swizzled tile images
    prep_kv<<<dim3(NT, H), dim3(128)>>>();

    // 2: rel = sim @ sim^T
    tc_gemm<<<dim3(S / 128, S / 128), blk>>>(sim, sim, grel, HD, HD, HD, S, nullptr, 0);

    // 3: fused attention  (<-- ncu capture index)
    fused_attn<<<dim3(S / 128, H), blk, 98304>>>(grel, w);

    // 4: out = attn @ Wo^T + bo
    tc_gemm<<<dim3(E / 128, S / 128), blk>>>(gattn, Wo, out, E, E, E, E, bo, 0);
}

// round 11
// speedup vs baseline: 1.3612x; 1.1207x over previous
#include <cuda_runtime.h>
#include <cuda_bf16.h>
#include <cuda_fp16.h>
#include <cstdint>
#include <cstddef>

#define S 2048
#define E 1024
#define H 16
#define HD 64
#define NT 16
#define SCALE 0.125f

// Scratch
__device__ float g_q[S * E];
__device__ float g_k[S * E];
__device__ float g_v[S * E];
__device__ float g_rel[S * S];
__device__ float g_attn[S * E];
// fp16 HI-only pre-swizzled tile images (exact smem byte layout), 16KB/tile
__device__ __align__(128) char g_kt[H * NT * 16384];
__device__ __align__(128) char g_vt[H * NT * 16384];

// ---------------------------------------------------------------------------
// Helpers
// ---------------------------------------------------------------------------
__device__ __forceinline__ uint32_t smem_u32(const void* p) {
    uint32_t a;
    asm("{ .reg .u64 t; cvta.to.shared.u64 t, %1; cvt.u32.u64 %0, t; }"
        : "=r"(a) : "l"(p));
    return a;
}

__device__ __forceinline__ uint32_t sw128(uint32_t off) {
    return off ^ ((off >> 3) & 0x70);
}

__device__ __forceinline__ void ldsm4(uint32_t* r, uint32_t addr) {
    asm volatile("ldmatrix.sync.aligned.m8n8.x4.shared.b16 {%0,%1,%2,%3}, [%4];"
                 : "=r"(r[0]), "=r"(r[1]), "=r"(r[2]), "=r"(r[3]) : "r"(addr));
}

// bf16 mma, f32 acc (GEMM path — proven)
__device__ __forceinline__ void mma16816(float* c, const uint32_t* a, const uint32_t* b) {
    asm volatile(
        "mma.sync.aligned.m16n8k16.row.col.f32.bf16.bf16.f32 "
        "{%0,%1,%2,%3}, {%4,%5,%6,%7}, {%8,%9}, {%0,%1,%2,%3};"
        : "+f"(c[0]), "+f"(c[1]), "+f"(c[2]), "+f"(c[3])
        : "r"(a[0]), "r"(a[1]), "r"(a[2]), "r"(a[3]), "r"(b[0]), "r"(b[1]));
}

// fp16 mma, f32 acc
__device__ __forceinline__ void mma_h32(float* c, const uint32_t* a, const uint32_t* b) {
    asm volatile(
        "mma.sync.aligned.m16n8k16.row.col.f32.f16.f16.f32 "
        "{%0,%1,%2,%3}, {%4,%5,%6,%7}, {%8,%9}, {%0,%1,%2,%3};"
        : "+f"(c[0]), "+f"(c[1]), "+f"(c[2]), "+f"(c[3])
        : "r"(a[0]), "r"(a[1]), "r"(a[2]), "r"(a[3]), "r"(b[0]), "r"(b[1]));
}

// fp16 mma, f16 acc (A-side lo cross term)
__device__ __forceinline__ void mma_h16(uint32_t* c, const uint32_t* a, const uint32_t* b) {
    asm volatile(
        "mma.sync.aligned.m16n8k16.row.col.f16.f16.f16.f16 "
        "{%0,%1}, {%2,%3,%4,%5}, {%6,%7}, {%0,%1};"
        : "+r"(c[0]), "+r"(c[1])
        : "r"(a[0]), "r"(a[1]), "r"(a[2]), "r"(a[3]), "r"(b[0]), "r"(b[1]));
}

// bf16 split (GEMM)
__device__ __forceinline__ void split_store_pair(char* base, int row, int col2,
                                                 float x0, float x1) {
    __nv_bfloat16 h0 = __float2bfloat16(x0);
    __nv_bfloat16 h1 = __float2bfloat16(x1);
    __nv_bfloat16 l0 = __float2bfloat16(x0 - __bfloat162float(h0));
    __nv_bfloat16 l1 = __float2bfloat16(x1 - __bfloat162float(h1));
    __nv_bfloat162 hp; hp.x = h0; hp.y = h1;
    __nv_bfloat162 lp; lp.x = l0; lp.y = l1;
    *(__nv_bfloat162*)(base + sw128(row * 128 + col2 * 2)) = hp;
    *(__nv_bfloat162*)(base + sw128(row * 128 + 64 + col2 * 2)) = lp;
}

// fp16 split of a pair
__device__ __forceinline__ void split2h(float x, float y, uint32_t& hi, uint32_t& lo) {
    __half2 hp = __floats2half2_rn(x, y);
    float rx = x - __half2float(__low2half(hp));
    float ry = y - __half2float(__high2half(hp));
    __half2 lp = __floats2half2_rn(rx, ry);
    hi = *(uint32_t*)&hp;
    lo = *(uint32_t*)&lp;
}

#define CP16(dst, src) \
    asm volatile("cp.async.cg.shared.global [%0], [%1], 16;" :: "r"(dst), "l"(src))
#define CP_COMMIT() asm volatile("cp.async.commit_group;" ::: "memory")
#define CP_WAIT(n)  asm volatile("cp.async.wait_group %0;" :: "n"(n) : "memory")

__constant__ int c_aofs[3] = {0, 0, 32};
__constant__ int c_bofs[3] = {0, 32, 0};

// ---------------------------------------------------------------------------
// GEMM body (bf16x3, proven)
// ---------------------------------------------------------------------------
__device__ __forceinline__ void gemm_body(
    const float* __restrict__ A, const float* __restrict__ B,
    float* __restrict__ C, int K, int lda, int ldb, int ldc,
    const float* __restrict__ bias, int row0, int col0)
{
    __shared__ __align__(128) char smA[128 * 128];
    __shared__ __align__(128) char smB[128 * 128];

    const int tid = threadIdx.x;
    const int warp = tid >> 5, lane = tid & 31;
    const int wm0 = (warp >> 1) * 32;
    const int wn0 = (warp & 1) * 64;

    uint32_t sA = smem_u32(smA);
    uint32_t sB = smem_u32(smB);

    float c[2][8][4];
#pragma unroll
    for (int i = 0; i < 2; i++)
#pragma unroll
        for (int j = 0; j < 8; j++)
#pragma unroll
            for (int t = 0; t < 4; t++) c[i][j][t] = 0.f;

    const int lr = tid >> 4;
    const int lp = tid & 15;

    for (int k0 = 0; k0 < K; k0 += 32) {
#pragma unroll
        for (int s = 0; s < 8; s++) {
            int r = s * 16 + lr;
            float2 va = *(const float2*)&A[(size_t)(row0 + r) * lda + k0 + 2 * lp];
            split_store_pair(smA, r, 2 * lp, va.x, va.y);
            float2 vb = *(const float2*)&B[(size_t)(col0 + r) * ldb + k0 + 2 * lp];
            split_store_pair(smB, r, 2 * lp, vb.x, vb.y);
        }
        __syncthreads();

        const int arow = wm0 + (lane & 15);
        const int acolq = (lane >> 4) * 8;
        const int bn = wn0 + (lane & 7) + ((lane >> 4) << 3);
        const int bkq = ((lane >> 3) & 1) * 8;

#pragma unroll
        for (int s3 = 0; s3 < 3; s3++) {
            const int aoff = c_aofs[s3], boff = c_bofs[s3];
#pragma unroll
            for (int ks = 0; ks < 2; ks++) {
                int acol = aoff + ks * 16 + acolq;
                uint32_t a0[4], a1[4];
                ldsm4(a0, sA + sw128((uint32_t)(arow * 128 + acol * 2)));
                ldsm4(a1, sA + sw128((uint32_t)((arow + 16) * 128 + acol * 2)));
                int bcol = boff + ks * 16 + bkq;
                uint32_t bq[4][4];
#pragma unroll
                for (int j2 = 0; j2 < 4; j2++)
                    ldsm4(bq[j2], sB + sw128((uint32_t)((bn + j2 * 16) * 128 + bcol * 2)));
#pragma unroll
                for (int i = 0; i < 2; i++) {
                    const uint32_t* ai = (i == 0) ? a0 : a1;
#pragma unroll
                    for (int j = 0; j < 8; j++)
                        mma16816(c[i][j], ai, &bq[j >> 1][(j & 1) * 2]);
                }
            }
        }
        __syncthreads();
    }

    const int g = lane >> 2, t4 = lane & 3;
#pragma unroll
    for (int i = 0; i < 2; i++) {
#pragma unroll
        for (int j = 0; j < 8; j++) {
            int gr0 = row0 + wm0 + i * 16 + g;
            int gc = col0 + wn0 + j * 8 + t4 * 2;
            float v0 = c[i][j][0], v1 = c[i][j][1];
            float v2 = c[i][j][2], v3 = c[i][j][3];
            if (bias) {
                float2 bv = *(const float2*)&bias[gc];
                v0 += bv.x; v1 += bv.y; v2 += bv.x; v3 += bv.y;
            }
            *(float2*)&C[(size_t)gr0 * ldc + gc] = make_float2(v0, v1);
            *(float2*)&C[(size_t)(gr0 + 8) * ldc + gc] = make_float2(v2, v3);
        }
    }
}

__global__ __launch_bounds__(256) void tc_gemm(
    const float* __restrict__ A, const float* __restrict__ B,
    float* __restrict__ C, int K, int lda, int ldb, int ldc,
    const float* __restrict__ bias, int row_base)
{
    gemm_body(A, B, C, K, lda, ldb, ldc, bias,
              row_base + blockIdx.y * 128, blockIdx.x * 128);
}

__global__ __launch_bounds__(256) void proj_qkv(
    const float* __restrict__ query, const float* __restrict__ key,
    const float* __restrict__ value,
    const float* __restrict__ Wq, const float* __restrict__ Wk,
    const float* __restrict__ Wv,
    const float* __restrict__ bq, const float* __restrict__ bk,
    const float* __restrict__ bv)
{
    const int z = blockIdx.z;
    const float* A = (z == 0) ? query : (z == 1) ? key : value;
    const float* B = (z == 0) ? Wq : (z == 1) ? Wk : Wv;
    const float* bias = (z == 0) ? bq : (z == 1) ? bk : bv;
    float* C = (z == 0) ? g_q : (z == 1) ? g_k : g_v;
    gemm_body(A, B, C, E, E, E, E, bias, blockIdx.y * 128, blockIdx.x * 128);
}

// ---------------------------------------------------------------------------
// prep_kv: fp16 HI-only pre-swizzled 16KB tile images. grid (NT, H), 128 thr.
// ---------------------------------------------------------------------------
__global__ __launch_bounds__(128) void prep_kv()
{
    const int tid = threadIdx.x;
    const int t0 = blockIdx.x * 128;
    const int h = blockIdx.y;
    const int qc0 = h * HD;
    char* kimg = g_kt + ((size_t)(h * NT + blockIdx.x)) * 16384;
    char* vimg = g_vt + ((size_t)(h * NT + blockIdx.x)) * 16384;

    const int lr = tid >> 4, lp = tid & 15;
#pragma unroll 4
    for (int s = 0; s < 16; s++) {
        int tr = s * 8 + lr;
        float4 kv = *(const float4*)&g_k[(size_t)(t0 + tr) * E + qc0 + 4 * lp];
        __half2 h01 = __floats2half2_rn(kv.x, kv.y);
        __half2 h23 = __floats2half2_rn(kv.z, kv.w);
        *(uint2*)(kimg + sw128(tr * 128 + 8 * lp)) =
            make_uint2(*(uint32_t*)&h01, *(uint32_t*)&h23);

        float4 vv = *(const float4*)&g_v[(size_t)(t0 + tr) * E + qc0 + 4 * lp];
        int sub = tr >> 6, tc = tr & 63;
        char* bh_ = vimg + sub * 8192;
        float vs[4] = {vv.x, vv.y, vv.z, vv.w};
#pragma unroll
        for (int j = 0; j < 4; j++) {
            int d = 4 * lp + j;
            *(__half*)(bh_ + sw128(d * 128 + tc * 2)) = __float2half_rn(vs[j]);
        }
    }
}

// ---------------------------------------------------------------------------
// fused_attn: 256 threads, 128 q-rows/CTA, grid (S/128, H), 48KB smem.
//   [0,16K)=kbuf0  [16K,32K)=kbuf1  [32K,48K)=vbuf
// MMA per group: qh*kh (f32acc) + ql*kh (f16acc).  No B-side lo.
// ---------------------------------------------------------------------------
__global__ __launch_bounds__(256) void fused_attn(
    const float* __restrict__ rel, float* __restrict__ wout)
{
    extern __shared__ char dyn[];
    const uint32_t smb = smem_u32(dyn);
    const uint32_t vbuf = smb + 32768;

    const int tid = threadIdx.x;
    const int warp = tid >> 5, lane = tid & 31;
    const int g = lane >> 2, t4 = lane & 3;
    const int h = blockIdx.y;
    const int row0 = blockIdx.x * 128;
    const int qc0 = h * HD;

    const int rA = row0 + warp * 16 + g;
    const int rB = rA + 8;

    // q fragments (fp16 split, pre-scaled)
    uint32_t qh[4][4], ql[4][4];
#pragma unroll
    for (int ks = 0; ks < 4; ks++) {
        int c = qc0 + ks * 16 + 2 * t4;
        float2 x00 = *(const float2*)&g_q[(size_t)rA * E + c];
        float2 x10 = *(const float2*)&g_q[(size_t)rB * E + c];
        float2 x01 = *(const float2*)&g_q[(size_t)rA * E + c + 8];
        float2 x11 = *(const float2*)&g_q[(size_t)rB * E + c + 8];
        split2h(x00.x * SCALE, x00.y * SCALE, qh[ks][0], ql[ks][0]);
        split2h(x10.x * SCALE, x10.y * SCALE, qh[ks][1], ql[ks][1]);
        split2h(x01.x * SCALE, x01.y * SCALE, qh[ks][2], ql[ks][2]);
        split2h(x11.x * SCALE, x11.y * SCALE, qh[ks][3], ql[ks][3]);
    }

    const int bnp = (lane & 7) + ((lane >> 4) << 3);
    const int bkq = ((lane >> 3) & 1) * 8;

    const char* ksrc = g_kt + ((size_t)h * NT) * 16384;
    const char* vsrc = g_vt + ((size_t)h * NT) * 16384;

    float lA = 0.f, lB = 0.f;

    // ===================== PASS 1: row sums (double-buffered k) ==========
#pragma unroll
    for (int i = 0; i < 4; i++) {
        uint32_t off = (uint32_t)(tid + i * 256) * 16;
        CP16(smb + off, ksrc + off);
    }
    CP_COMMIT();

#pragma unroll 1
    for (int t = 0; t < NT; t++) {
        CP_WAIT(0);
        __syncthreads();
        if (t + 1 < NT) {
            const char* src = ksrc + (size_t)(t + 1) * 16384;
            uint32_t dst = smb + ((t + 1) & 1) * 16384;
#pragma unroll
            for (int i = 0; i < 4; i++) {
                uint32_t off = (uint32_t)(tid + i * 256) * 16;
                CP16(dst + off, src + off);
            }
            CP_COMMIT();
        }
        const uint32_t uSkh = smb + (t & 1) * 16384;

#pragma unroll 1
        for (int ch = 0; ch < 8; ch++) {
            int cg = t * 128 + ch * 16 + 2 * t4;
            float2 r00 = *(const float2*)&rel[(size_t)rA * S + cg];
            float2 r10 = *(const float2*)&rel[(size_t)rB * S + cg];
            float2 r01 = *(const float2*)&rel[(size_t)rA * S + cg + 8];
            float2 r11 = *(const float2*)&rel[(size_t)rB * S + cg + 8];

            float cs[2][4];
            uint32_t cx[2][2];
#pragma unroll
            for (int i = 0; i < 2; i++) {
#pragma unroll
                for (int t2 = 0; t2 < 4; t2++) cs[i][t2] = 0.f;
                cx[i][0] = 0u; cx[i][1] = 0u;
            }
            int brow = ch * 16 + bnp;
#pragma unroll
            for (int ks = 0; ks < 4; ks++) {
                uint32_t bh[4];
                uint32_t cb = (uint32_t)((ks * 16 + bkq) * 2);
                ldsm4(bh, uSkh + sw128(brow * 128 + cb));
                mma_h32(cs[0], qh[ks], bh + 0);
                mma_h32(cs[1], qh[ks], bh + 2);
                mma_h16(cx[0], ql[ks], bh + 0);
                mma_h16(cx[1], ql[ks], bh + 2);
            }
            float2 x0a = __half22float2(*(__half2*)&cx[0][0]);
            float2 x0b = __half22float2(*(__half2*)&cx[0][1]);
            float2 x1a = __half22float2(*(__half2*)&cx[1][0]);
            float2 x1b = __half22float2(*(__half2*)&cx[1][1]);
            lA += __expf(cs[0][0] + x0a.x + r00.x * SCALE) +
                  __expf(cs[0][1] + x0a.y + r00.y * SCALE) +
                  __expf(cs[1][0] + x1a.x + r01.x * SCALE) +
                  __expf(cs[1][1] + x1a.y + r01.y * SCALE);
            lB += __expf(cs[0][2] + x0b.x + r10.x * SCALE) +
                  __expf(cs[0][3] + x0b.y + r10.y * SCALE) +
                  __expf(cs[1][2] + x1b.x + r11.x * SCALE) +
                  __expf(cs[1][3] + x1b.y + r11.y * SCALE);
        }
    }

    lA += __shfl_xor_sync(0xffffffffu, lA, 1);
    lA += __shfl_xor_sync(0xffffffffu, lA, 2);
    lB += __shfl_xor_sync(0xffffffffu, lB, 1);
    lB += __shfl_xor_sync(0xffffffffu, lB, 2);
    const float invA = 1.f / lA, invB = 1.f / lB;

    float o[8][4];
    uint32_t ox[8][2];
#pragma unroll
    for (int j = 0; j < 8; j++) {
#pragma unroll
        for (int t2 = 0; t2 < 4; t2++) o[j][t2] = 0.f;
        ox[j][0] = 0u; ox[j][1] = 0u;
    }

    float* wrow = wout + (size_t)h * S * S;

    // ===================== PASS 2: w + PV (pipelined) =====================
    __syncthreads();
#pragma unroll
    for (int i = 0; i < 4; i++) {
        uint32_t off = (uint32_t)(tid + i * 256) * 16;
        CP16(smb + off, ksrc + off);
    }
    CP_COMMIT();

#pragma unroll 1
    for (int t = 0; t < NT; t++) {
        // stage v_t (overlaps score MMAs)
        {
            const char* srcv = vsrc + (size_t)t * 16384;
#pragma unroll
            for (int i = 0; i < 4; i++) {
                uint32_t off = (uint32_t)(tid + i * 256) * 16;
                CP16(vbuf + off, srcv + off);
            }
            CP_COMMIT();
        }
        // stage k_{t+1} (overlaps PV)
        if (t + 1 < NT) {
            const char* src = ksrc + (size_t)(t + 1) * 16384;
            uint32_t dst = smb + ((t + 1) & 1) * 16384;
#pragma unroll
            for (int i = 0; i < 4; i++) {
                uint32_t off = (uint32_t)(tid + i * 256) * 16;
                CP16(dst + off, src + off);
            }
            CP_COMMIT();
        }
        if (t + 1 < NT) { CP_WAIT(2); } else { CP_WAIT(1); }
        __syncthreads();

        const uint32_t uSkh = smb + (t & 1) * 16384;

        uint32_t ahf[8][4], alf[8][4];
#pragma unroll 1
        for (int ch = 0; ch < 8; ch++) {
            int cg = t * 128 + ch * 16 + 2 * t4;
            float2 r00 = *(const float2*)&rel[(size_t)rA * S + cg];
            float2 r10 = *(const float2*)&rel[(size_t)rB * S + cg];
            float2 r01 = *(const float2*)&rel[(size_t)rA * S + cg + 8];
            float2 r11 = *(const float2*)&rel[(size_t)rB * S + cg + 8];

            float cs[2][4];
            uint32_t cx[2][2];
#pragma unroll
            for (int i = 0; i < 2; i++) {
#pragma unroll
                for (int t2 = 0; t2 < 4; t2++) cs[i][t2] = 0.f;
                cx[i][0] = 0u; cx[i][1] = 0u;
            }
            int brow = ch * 16 + bnp;
#pragma unroll
            for (int ks = 0; ks < 4; ks++) {
                uint32_t bh[4];
                uint32_t cb = (uint32_t)((ks * 16 + bkq) * 2);
                ldsm4(bh, uSkh + sw128(brow * 128 + cb));
                mma_h32(cs[0], qh[ks], bh + 0);
                mma_h32(cs[1], qh[ks], bh + 2);
                mma_h16(cx[0], ql[ks], bh + 0);
                mma_h16(cx[1], ql[ks], bh + 2);
            }
            float2 x0a = __half22float2(*(__half2*)&cx[0][0]);
            float2 x0b = __half22float2(*(__half2*)&cx[0][1]);
            float2 x1a = __half22float2(*(__half2*)&cx[1][0]);
            float2 x1b = __half22float2(*(__half2*)&cx[1][1]);

            float wA0 = __expf(cs[0][0] + x0a.x + r00.x * SCALE) * invA;
            float wA1 = __expf(cs[0][1] + x0a.y + r00.y * SCALE) * invA;
            float wA2 = __expf(cs[1][0] + x1a.x + r01.x * SCALE) * invA;
            float wA3 = __expf(cs[1][1] + x1a.y + r01.y * SCALE) * invA;
            float wB0 = __expf(cs[0][2] + x0b.x + r10.x * SCALE) * invB;
            float wB1 = __expf(cs[0][3] + x0b.y + r10.y * SCALE) * invB;
            float wB2 = __expf(cs[1][2] + x1b.x + r11.x * SCALE) * invB;
            float wB3 = __expf(cs[1][3] + x1b.y + r11.y * SCALE) * invB;

            *(float2*)&wrow[(size_t)rA * S + cg]     = make_float2(wA0, wA1);
            *(float2*)&wrow[(size_t)rA * S + cg + 8] = make_float2(wA2, wA3);
            *(float2*)&wrow[(size_t)rB * S + cg]     = make_float2(wB0, wB1);
            *(float2*)&wrow[(size_t)rB * S + cg + 8] = make_float2(wB2, wB3);

            split2h(wA0, wA1, ahf[ch][0], alf[ch][0]);
            split2h(wB0, wB1, ahf[ch][1], alf[ch][1]);
            split2h(wA2, wA3, ahf[ch][2], alf[ch][2]);
            split2h(wB2, wB3, ahf[ch][3], alf[ch][3]);
        }

        if (t + 1 < NT) { CP_WAIT(1); } else { CP_WAIT(0); }
        __syncthreads();

        // -------- PV (v hi only; w hi f32-acc, w lo f16-acc) --------
#pragma unroll 1
        for (int ch = 0; ch < 8; ch++) {
            int sub = ch >> 2;
            uint32_t cb = (uint32_t)(((ch & 3) * 16 + bkq) * 2);
            uint32_t vbaseh = vbuf + sub * 8192;
#pragma unroll
            for (int jd = 0; jd < 4; jd++) {
                int dn = jd * 16 + bnp;
                uint32_t vh[4];
                ldsm4(vh, vbaseh + sw128(dn * 128 + cb));
                mma_h32(o[2 * jd],      ahf[ch], vh + 0);
                mma_h32(o[2 * jd + 1],  ahf[ch], vh + 2);
                mma_h16(ox[2 * jd],     alf[ch], vh + 0);
                mma_h16(ox[2 * jd + 1], alf[ch], vh + 2);
            }
        }
        __syncthreads();   // vbuf consumed before next staging
    }

    // epilogue
#pragma unroll
    for (int j = 0; j < 8; j++) {
        int gc = qc0 + j * 8 + 2 * t4;
        float2 ca = __half22float2(*(__half2*)&ox[j][0]);
        float2 cb2 = __half22float2(*(__half2*)&ox[j][1]);
        *(float2*)&g_attn[(size_t)rA * E + gc] =
            make_float2(o[j][0] + ca.x, o[j][1] + ca.y);
        *(float2*)&g_attn[(size_t)rB * E + gc] =
            make_float2(o[j][2] + cb2.x, o[j][3] + cb2.y);
    }
}

// ---------------------------------------------------------------------------
// Launch.  fused_attn must be launch index 3 (ncu capture).
// ---------------------------------------------------------------------------
extern "C" void kernel_launch(void* const* d_in, const int* in_sizes, int n_in,
                              void* d_out, int out_size)
{
    (void)in_sizes; (void)n_in; (void)out_size;
    const float* query = (const float*)d_in[0];
    const float* key   = (const float*)d_in[1];
    const float* value = (const float*)d_in[2];
    const float* sim   = (const float*)d_in[3];
    const float* Wq    = (const float*)d_in[4];
    const float* bq    = (const float*)d_in[5];
    const float* Wk    = (const float*)d_in[6];
    const float* bk    = (const float*)d_in[7];
    const float* Wv    = (const float*)d_in[8];
    const float* bv    = (const float*)d_in[9];
    const float* Wo    = (const float*)d_in[10];
    const float* bo    = (const float*)d_in[11];

    float* out = (float*)d_out;                 // [S,E]
    float* w   = out + (size_t)S * E;           // [H,S,S]

    float *grel, *gattn;
    cudaGetSymbolAddress((void**)&grel,  g_rel);
    cudaGetSymbolAddress((void**)&gattn, g_attn);

    static int attr_done = 0;
    if (!attr_done) {
        cudaFuncSetAttribute(fused_attn,
                             cudaFuncAttributeMaxDynamicSharedMemorySize, 49152);
        attr_done = 1;
    }

    dim3 blk(256);

    // 0: q/k/v projections (batched)
    proj_qkv<<<dim3(E / 128, S / 128, 3), blk>>>(query, key, value,
                                                 Wq, Wk, Wv, bq, bk, bv);

    // 1: pre-split k/v into fp16 hi-only swizzled tile images
    prep_kv<<<dim3(NT, H), dim3(128)>>>();

    // 2: rel = sim @ sim^T
    tc_gemm<<<dim3(S / 128, S / 128), blk>>>(sim, sim, grel, HD, HD, HD, S, nullptr, 0);

    // 3: fused attention  (<-- ncu capture index)
    fused_attn<<<dim3(S / 128, H), blk, 49152>>>(grel, w);

    // 4: out = attn @ Wo^T + bo
    tc_gemm<<<dim3(E / 128, S / 128), blk>>>(gattn, Wo, out, E, E, E, E, bo, 0);
}

// round 12
// speedup vs baseline: 1.3857x; 1.0180x over previous
#include <cuda_runtime.h>
#include <cuda_bf16.h>
#include <cuda_fp16.h>
#include <cstdint>
#include <cstddef>

#define S 2048
#define E 1024
#define H 16
#define HD 64
#define NT 16
#define SCALE 0.125f

// Scratch
__device__ float g_q[S * E];
__device__ float g_k[S * E];
__device__ float g_v[S * E];
__device__ float g_rel[S * S];
__device__ float g_attn[S * E];
// fp16 HI-only pre-swizzled tile images (exact smem byte layout), 16KB/tile
__device__ __align__(128) char g_kt[H * NT * 16384];
__device__ __align__(128) char g_vt[H * NT * 16384];

// ---------------------------------------------------------------------------
// Helpers
// ---------------------------------------------------------------------------
__device__ __forceinline__ uint32_t smem_u32(const void* p) {
    uint32_t a;
    asm("{ .reg .u64 t; cvta.to.shared.u64 t, %1; cvt.u32.u64 %0, t; }"
        : "=r"(a) : "l"(p));
    return a;
}

__device__ __forceinline__ uint32_t sw128(uint32_t off) {
    return off ^ ((off >> 3) & 0x70);
}

__device__ __forceinline__ void ldsm4(uint32_t* r, uint32_t addr) {
    asm volatile("ldmatrix.sync.aligned.m8n8.x4.shared.b16 {%0,%1,%2,%3}, [%4];"
                 : "=r"(r[0]), "=r"(r[1]), "=r"(r[2]), "=r"(r[3]) : "r"(addr));
}

// bf16 mma, f32 acc (GEMM path — proven)
__device__ __forceinline__ void mma16816(float* c, const uint32_t* a, const uint32_t* b) {
    asm volatile(
        "mma.sync.aligned.m16n8k16.row.col.f32.bf16.bf16.f32 "
        "{%0,%1,%2,%3}, {%4,%5,%6,%7}, {%8,%9}, {%0,%1,%2,%3};"
        : "+f"(c[0]), "+f"(c[1]), "+f"(c[2]), "+f"(c[3])
        : "r"(a[0]), "r"(a[1]), "r"(a[2]), "r"(a[3]), "r"(b[0]), "r"(b[1]));
}

// fp16 mma, f32 acc
__device__ __forceinline__ void mma_h32(float* c, const uint32_t* a, const uint32_t* b) {
    asm volatile(
        "mma.sync.aligned.m16n8k16.row.col.f32.f16.f16.f32 "
        "{%0,%1,%2,%3}, {%4,%5,%6,%7}, {%8,%9}, {%0,%1,%2,%3};"
        : "+f"(c[0]), "+f"(c[1]), "+f"(c[2]), "+f"(c[3])
        : "r"(a[0]), "r"(a[1]), "r"(a[2]), "r"(a[3]), "r"(b[0]), "r"(b[1]));
}

// fp16 mma, f16 acc (A-side lo cross term)
__device__ __forceinline__ void mma_h16(uint32_t* c, const uint32_t* a, const uint32_t* b) {
    asm volatile(
        "mma.sync.aligned.m16n8k16.row.col.f16.f16.f16.f16 "
        "{%0,%1}, {%2,%3,%4,%5}, {%6,%7}, {%0,%1};"
        : "+r"(c[0]), "+r"(c[1])
        : "r"(a[0]), "r"(a[1]), "r"(a[2]), "r"(a[3]), "r"(b[0]), "r"(b[1]));
}

// packed fp16 exp2
__device__ __forceinline__ uint32_t ex2_f16x2(uint32_t y) {
    uint32_t r;
    asm("ex2.approx.f16x2 %0, %1;" : "=r"(r) : "r"(y));
    return r;
}

// bf16 split (GEMM)
__device__ __forceinline__ void split_store_pair(char* base, int row, int col2,
                                                 float x0, float x1) {
    __nv_bfloat16 h0 = __float2bfloat16(x0);
    __nv_bfloat16 h1 = __float2bfloat16(x1);
    __nv_bfloat16 l0 = __float2bfloat16(x0 - __bfloat162float(h0));
    __nv_bfloat16 l1 = __float2bfloat16(x1 - __bfloat162float(h1));
    __nv_bfloat162 hp; hp.x = h0; hp.y = h1;
    __nv_bfloat162 lp; lp.x = l0; lp.y = l1;
    *(__nv_bfloat162*)(base + sw128(row * 128 + col2 * 2)) = hp;
    *(__nv_bfloat162*)(base + sw128(row * 128 + 64 + col2 * 2)) = lp;
}

// fp16 split of a pair
__device__ __forceinline__ void split2h(float x, float y, uint32_t& hi, uint32_t& lo) {
    __half2 hp = __floats2half2_rn(x, y);
    float rx = x - __half2float(__low2half(hp));
    float ry = y - __half2float(__high2half(hp));
    __half2 lp = __floats2half2_rn(rx, ry);
    hi = *(uint32_t*)&hp;
    lo = *(uint32_t*)&lp;
}

#define CP16(dst, src) \
    asm volatile("cp.async.cg.shared.global [%0], [%1], 16;" :: "r"(dst), "l"(src))
#define CP_COMMIT() asm volatile("cp.async.commit_group;" ::: "memory")
#define CP_WAIT(n)  asm volatile("cp.async.wait_group %0;" :: "n"(n) : "memory")

__constant__ int c_aofs[3] = {0, 0, 32};
__constant__ int c_bofs[3] = {0, 32, 0};

// ---------------------------------------------------------------------------
// GEMM body (bf16x3, proven)
// ---------------------------------------------------------------------------
__device__ __forceinline__ void gemm_body(
    const float* __restrict__ A, const float* __restrict__ B,
    float* __restrict__ C, int K, int lda, int ldb, int ldc,
    const float* __restrict__ bias, int row0, int col0)
{
    __shared__ __align__(128) char smA[128 * 128];
    __shared__ __align__(128) char smB[128 * 128];

    const int tid = threadIdx.x;
    const int warp = tid >> 5, lane = tid & 31;
    const int wm0 = (warp >> 1) * 32;
    const int wn0 = (warp & 1) * 64;

    uint32_t sA = smem_u32(smA);
    uint32_t sB = smem_u32(smB);

    float c[2][8][4];
#pragma unroll
    for (int i = 0; i < 2; i++)
#pragma unroll
        for (int j = 0; j < 8; j++)
#pragma unroll
            for (int t = 0; t < 4; t++) c[i][j][t] = 0.f;

    const int lr = tid >> 4;
    const int lp = tid & 15;

    for (int k0 = 0; k0 < K; k0 += 32) {
#pragma unroll
        for (int s = 0; s < 8; s++) {
            int r = s * 16 + lr;
            float2 va = *(const float2*)&A[(size_t)(row0 + r) * lda + k0 + 2 * lp];
            split_store_pair(smA, r, 2 * lp, va.x, va.y);
            float2 vb = *(const float2*)&B[(size_t)(col0 + r) * ldb + k0 + 2 * lp];
            split_store_pair(smB, r, 2 * lp, vb.x, vb.y);
        }
        __syncthreads();

        const int arow = wm0 + (lane & 15);
        const int acolq = (lane >> 4) * 8;
        const int bn = wn0 + (lane & 7) + ((lane >> 4) << 3);
        const int bkq = ((lane >> 3) & 1) * 8;

#pragma unroll
        for (int s3 = 0; s3 < 3; s3++) {
            const int aoff = c_aofs[s3], boff = c_bofs[s3];
#pragma unroll
            for (int ks = 0; ks < 2; ks++) {
                int acol = aoff + ks * 16 + acolq;
                uint32_t a0[4], a1[4];
                ldsm4(a0, sA + sw128((uint32_t)(arow * 128 + acol * 2)));
                ldsm4(a1, sA + sw128((uint32_t)((arow + 16) * 128 + acol * 2)));
                int bcol = boff + ks * 16 + bkq;
                uint32_t bq[4][4];
#pragma unroll
                for (int j2 = 0; j2 < 4; j2++)
                    ldsm4(bq[j2], sB + sw128((uint32_t)((bn + j2 * 16) * 128 + bcol * 2)));
#pragma unroll
                for (int i = 0; i < 2; i++) {
                    const uint32_t* ai = (i == 0) ? a0 : a1;
#pragma unroll
                    for (int j = 0; j < 8; j++)
                        mma16816(c[i][j], ai, &bq[j >> 1][(j & 1) * 2]);
                }
            }
        }
        __syncthreads();
    }

    const int g = lane >> 2, t4 = lane & 3;
#pragma unroll
    for (int i = 0; i < 2; i++) {
#pragma unroll
        for (int j = 0; j < 8; j++) {
            int gr0 = row0 + wm0 + i * 16 + g;
            int gc = col0 + wn0 + j * 8 + t4 * 2;
            float v0 = c[i][j][0], v1 = c[i][j][1];
            float v2 = c[i][j][2], v3 = c[i][j][3];
            if (bias) {
                float2 bv = *(const float2*)&bias[gc];
                v0 += bv.x; v1 += bv.y; v2 += bv.x; v3 += bv.y;
            }
            *(float2*)&C[(size_t)gr0 * ldc + gc] = make_float2(v0, v1);
            *(float2*)&C[(size_t)(gr0 + 8) * ldc + gc] = make_float2(v2, v3);
        }
    }
}

__global__ __launch_bounds__(256) void tc_gemm(
    const float* __restrict__ A, const float* __restrict__ B,
    float* __restrict__ C, int K, int lda, int ldb, int ldc,
    const float* __restrict__ bias, int row_base)
{
    gemm_body(A, B, C, K, lda, ldb, ldc, bias,
              row_base + blockIdx.y * 128, blockIdx.x * 128);
}

__global__ __launch_bounds__(256) void proj_qkv(
    const float* __restrict__ query, const float* __restrict__ key,
    const float* __restrict__ value,
    const float* __restrict__ Wq, const float* __restrict__ Wk,
    const float* __restrict__ Wv,
    const float* __restrict__ bq, const float* __restrict__ bk,
    const float* __restrict__ bv)
{
    const int z = blockIdx.z;
    const float* A = (z == 0) ? query : (z == 1) ? key : value;
    const float* B = (z == 0) ? Wq : (z == 1) ? Wk : Wv;
    const float* bias = (z == 0) ? bq : (z == 1) ? bk : bv;
    float* C = (z == 0) ? g_q : (z == 1) ? g_k : g_v;
    gemm_body(A, B, C, E, E, E, E, bias, blockIdx.y * 128, blockIdx.x * 128);
}

// ---------------------------------------------------------------------------
// prep_kv: fp16 HI-only pre-swizzled 16KB tile images. grid (NT, H), 128 thr.
// ---------------------------------------------------------------------------
__global__ __launch_bounds__(128) void prep_kv()
{
    const int tid = threadIdx.x;
    const int t0 = blockIdx.x * 128;
    const int h = blockIdx.y;
    const int qc0 = h * HD;
    char* kimg = g_kt + ((size_t)(h * NT + blockIdx.x)) * 16384;
    char* vimg = g_vt + ((size_t)(h * NT + blockIdx.x)) * 16384;

    const int lr = tid >> 4, lp = tid & 15;
#pragma unroll 4
    for (int s = 0; s < 16; s++) {
        int tr = s * 8 + lr;
        float4 kv = *(const float4*)&g_k[(size_t)(t0 + tr) * E + qc0 + 4 * lp];
        __half2 h01 = __floats2half2_rn(kv.x, kv.y);
        __half2 h23 = __floats2half2_rn(kv.z, kv.w);
        *(uint2*)(kimg + sw128(tr * 128 + 8 * lp)) =
            make_uint2(*(uint32_t*)&h01, *(uint32_t*)&h23);

        float4 vv = *(const float4*)&g_v[(size_t)(t0 + tr) * E + qc0 + 4 * lp];
        int sub = tr >> 6, tc = tr & 63;
        char* bh_ = vimg + sub * 8192;
        float vs[4] = {vv.x, vv.y, vv.z, vv.w};
#pragma unroll
        for (int j = 0; j < 4; j++) {
            int d = 4 * lp + j;
            *(__half*)(bh_ + sw128(d * 128 + tc * 2)) = __float2half_rn(vs[j]);
        }
    }
}

// ---------------------------------------------------------------------------
// fused_attn: 256 threads, 128 q-rows/CTA, grid (S/128, H), 48KB smem.
//   [0,16K)=kbuf0  [16K,32K)=kbuf1  [32K,48K)=vbuf
// pass1 (cheap): l via hi-only MMA + ex2.approx.f16x2, shifted by e^-8.
// pass2 (full):  qh*kh (f32acc) + ql*kh (f16acc), fp32 exp, w + PV.
// ---------------------------------------------------------------------------
__global__ __launch_bounds__(256) void fused_attn(
    const float* __restrict__ rel, float* __restrict__ wout)
{
    extern __shared__ char dyn[];
    const uint32_t smb = smem_u32(dyn);
    const uint32_t vbuf = smb + 32768;

    const int tid = threadIdx.x;
    const int warp = tid >> 5, lane = tid & 31;
    const int g = lane >> 2, t4 = lane & 3;
    const int h = blockIdx.y;
    const int row0 = blockIdx.x * 128;
    const int qc0 = h * HD;

    const int rA = row0 + warp * 16 + g;
    const int rB = rA + 8;

    // q fragments (fp16 split, pre-scaled)
    uint32_t qh[4][4], ql[4][4];
#pragma unroll
    for (int ks = 0; ks < 4; ks++) {
        int c = qc0 + ks * 16 + 2 * t4;
        float2 x00 = *(const float2*)&g_q[(size_t)rA * E + c];
        float2 x10 = *(const float2*)&g_q[(size_t)rB * E + c];
        float2 x01 = *(const float2*)&g_q[(size_t)rA * E + c + 8];
        float2 x11 = *(const float2*)&g_q[(size_t)rB * E + c + 8];
        split2h(x00.x * SCALE, x00.y * SCALE, qh[ks][0], ql[ks][0]);
        split2h(x10.x * SCALE, x10.y * SCALE, qh[ks][1], ql[ks][1]);
        split2h(x01.x * SCALE, x01.y * SCALE, qh[ks][2], ql[ks][2]);
        split2h(x11.x * SCALE, x11.y * SCALE, qh[ks][3], ql[ks][3]);
    }

    const int bnp = (lane & 7) + ((lane >> 4) << 3);
    const int bkq = ((lane >> 3) & 1) * 8;

    const char* ksrc = g_kt + ((size_t)h * NT) * 16384;
    const char* vsrc = g_vt + ((size_t)h * NT) * 16384;

    float lA = 0.f, lB = 0.f;

    const float L2E = 1.44269504f;          // log2(e)
    const float C1  = SCALE * L2E;          // rel multiplier
    const float SH  = 8.0f * L2E;           // shift (e^-8) to keep fp16 in range

    // ===================== PASS 1: row sums (cheap) =======================
#pragma unroll
    for (int i = 0; i < 4; i++) {
        uint32_t off = (uint32_t)(tid + i * 256) * 16;
        CP16(smb + off, ksrc + off);
    }
    CP_COMMIT();

#pragma unroll 1
    for (int t = 0; t < NT; t++) {
        CP_WAIT(0);
        __syncthreads();
        if (t + 1 < NT) {
            const char* src = ksrc + (size_t)(t + 1) * 16384;
            uint32_t dst = smb + ((t + 1) & 1) * 16384;
#pragma unroll
            for (int i = 0; i < 4; i++) {
                uint32_t off = (uint32_t)(tid + i * 256) * 16;
                CP16(dst + off, src + off);
            }
            CP_COMMIT();
        }
        const uint32_t uSkh = smb + (t & 1) * 16384;

#pragma unroll 1
        for (int ch = 0; ch < 8; ch++) {
            int cg = t * 128 + ch * 16 + 2 * t4;
            float2 r00 = *(const float2*)&rel[(size_t)rA * S + cg];
            float2 r10 = *(const float2*)&rel[(size_t)rB * S + cg];
            float2 r01 = *(const float2*)&rel[(size_t)rA * S + cg + 8];
            float2 r11 = *(const float2*)&rel[(size_t)rB * S + cg + 8];

            float cs[2][4];
#pragma unroll
            for (int i = 0; i < 2; i++)
#pragma unroll
                for (int t2 = 0; t2 < 4; t2++) cs[i][t2] = 0.f;
            int brow = ch * 16 + bnp;
#pragma unroll
            for (int ks = 0; ks < 4; ks++) {
                uint32_t bh[4];
                uint32_t cb = (uint32_t)((ks * 16 + bkq) * 2);
                ldsm4(bh, uSkh + sw128(brow * 128 + cb));
                mma_h32(cs[0], qh[ks], bh + 0);
                mma_h32(cs[1], qh[ks], bh + 2);
            }
            // y = s*log2e - 8*log2e;  exp2 in fp16x2 pairs
            float yA0 = fmaf(cs[0][0], L2E, fmaf(r00.x, C1, -SH));
            float yA1 = fmaf(cs[0][1], L2E, fmaf(r00.y, C1, -SH));
            float yA2 = fmaf(cs[1][0], L2E, fmaf(r01.x, C1, -SH));
            float yA3 = fmaf(cs[1][1], L2E, fmaf(r01.y, C1, -SH));
            float yB0 = fmaf(cs[0][2], L2E, fmaf(r10.x, C1, -SH));
            float yB1 = fmaf(cs[0][3], L2E, fmaf(r10.y, C1, -SH));
            float yB2 = fmaf(cs[1][2], L2E, fmaf(r11.x, C1, -SH));
            float yB3 = fmaf(cs[1][3], L2E, fmaf(r11.y, C1, -SH));

            __half2 ya01 = __floats2half2_rn(yA0, yA1);
            __half2 ya23 = __floats2half2_rn(yA2, yA3);
            __half2 yb01 = __floats2half2_rn(yB0, yB1);
            __half2 yb23 = __floats2half2_rn(yB2, yB3);
            uint32_t ea01 = ex2_f16x2(*(uint32_t*)&ya01);
            uint32_t ea23 = ex2_f16x2(*(uint32_t*)&ya23);
            uint32_t eb01 = ex2_f16x2(*(uint32_t*)&yb01);
            uint32_t eb23 = ex2_f16x2(*(uint32_t*)&yb23);
            float2 fa01 = __half22float2(*(__half2*)&ea01);
            float2 fa23 = __half22float2(*(__half2*)&ea23);
            float2 fb01 = __half22float2(*(__half2*)&eb01);
            float2 fb23 = __half22float2(*(__half2*)&eb23);
            lA += (fa01.x + fa01.y) + (fa23.x + fa23.y);
            lB += (fb01.x + fb01.y) + (fb23.x + fb23.y);
        }
    }

    lA += __shfl_xor_sync(0xffffffffu, lA, 1);
    lA += __shfl_xor_sync(0xffffffffu, lA, 2);
    lB += __shfl_xor_sync(0xffffffffu, lB, 1);
    lB += __shfl_xor_sync(0xffffffffu, lB, 2);
    // undo the e^-8 shift: l_true = l_raw * e^8
    const float E8 = 2980.9580f;
    const float invA = 1.f / (lA * E8), invB = 1.f / (lB * E8);

    float o[8][4];
    uint32_t ox[8][2];
#pragma unroll
    for (int j = 0; j < 8; j++) {
#pragma unroll
        for (int t2 = 0; t2 < 4; t2++) o[j][t2] = 0.f;
        ox[j][0] = 0u; ox[j][1] = 0u;
    }

    float* wrow = wout + (size_t)h * S * S;

    // ===================== PASS 2: w + PV (pipelined, full precision) ====
    __syncthreads();
#pragma unroll
    for (int i = 0; i < 4; i++) {
        uint32_t off = (uint32_t)(tid + i * 256) * 16;
        CP16(smb + off, ksrc + off);
    }
    CP_COMMIT();

#pragma unroll 1
    for (int t = 0; t < NT; t++) {
        // stage v_t (overlaps score MMAs)
        {
            const char* srcv = vsrc + (size_t)t * 16384;
#pragma unroll
            for (int i = 0; i < 4; i++) {
                uint32_t off = (uint32_t)(tid + i * 256) * 16;
                CP16(vbuf + off, srcv + off);
            }
            CP_COMMIT();
        }
        // stage k_{t+1} (overlaps PV)
        if (t + 1 < NT) {
            const char* src = ksrc + (size_t)(t + 1) * 16384;
            uint32_t dst = smb + ((t + 1) & 1) * 16384;
#pragma unroll
            for (int i = 0; i < 4; i++) {
                uint32_t off = (uint32_t)(tid + i * 256) * 16;
                CP16(dst + off, src + off);
            }
            CP_COMMIT();
        }
        if (t + 1 < NT) { CP_WAIT(2); } else { CP_WAIT(1); }
        __syncthreads();

        const uint32_t uSkh = smb + (t & 1) * 16384;

        uint32_t ahf[8][4], alf[8][4];
#pragma unroll 1
        for (int ch = 0; ch < 8; ch++) {
            int cg = t * 128 + ch * 16 + 2 * t4;
            float2 r00 = *(const float2*)&rel[(size_t)rA * S + cg];
            float2 r10 = *(const float2*)&rel[(size_t)rB * S + cg];
            float2 r01 = *(const float2*)&rel[(size_t)rA * S + cg + 8];
            float2 r11 = *(const float2*)&rel[(size_t)rB * S + cg + 8];

            float cs[2][4];
            uint32_t cx[2][2];
#pragma unroll
            for (int i = 0; i < 2; i++) {
#pragma unroll
                for (int t2 = 0; t2 < 4; t2++) cs[i][t2] = 0.f;
                cx[i][0] = 0u; cx[i][1] = 0u;
            }
            int brow = ch * 16 + bnp;
#pragma unroll
            for (int ks = 0; ks < 4; ks++) {
                uint32_t bh[4];
                uint32_t cb = (uint32_t)((ks * 16 + bkq) * 2);
                ldsm4(bh, uSkh + sw128(brow * 128 + cb));
                mma_h32(cs[0], qh[ks], bh + 0);
                mma_h32(cs[1], qh[ks], bh + 2);
                mma_h16(cx[0], ql[ks], bh + 0);
                mma_h16(cx[1], ql[ks], bh + 2);
            }
            float2 x0a = __half22float2(*(__half2*)&cx[0][0]);
            float2 x0b = __half22float2(*(__half2*)&cx[0][1]);
            float2 x1a = __half22float2(*(__half2*)&cx[1][0]);
            float2 x1b = __half22float2(*(__half2*)&cx[1][1]);

            float wA0 = __expf(cs[0][0] + x0a.x + r00.x * SCALE) * invA;
            float wA1 = __expf(cs[0][1] + x0a.y + r00.y * SCALE) * invA;
            float wA2 = __expf(cs[1][0] + x1a.x + r01.x * SCALE) * invA;
            float wA3 = __expf(cs[1][1] + x1a.y + r01.y * SCALE) * invA;
            float wB0 = __expf(cs[0][2] + x0b.x + r10.x * SCALE) * invB;
            float wB1 = __expf(cs[0][3] + x0b.y + r10.y * SCALE) * invB;
            float wB2 = __expf(cs[1][2] + x1b.x + r11.x * SCALE) * invB;
            float wB3 = __expf(cs[1][3] + x1b.y + r11.y * SCALE) * invB;

            *(float2*)&wrow[(size_t)rA * S + cg]     = make_float2(wA0, wA1);
            *(float2*)&wrow[(size_t)rA * S + cg + 8] = make_float2(wA2, wA3);
            *(float2*)&wrow[(size_t)rB * S + cg]     = make_float2(wB0, wB1);
            *(float2*)&wrow[(size_t)rB * S + cg + 8] = make_float2(wB2, wB3);

            split2h(wA0, wA1, ahf[ch][0], alf[ch][0]);
            split2h(wB0, wB1, ahf[ch][1], alf[ch][1]);
            split2h(wA2, wA3, ahf[ch][2], alf[ch][2]);
            split2h(wB2, wB3, ahf[ch][3], alf[ch][3]);
        }

        if (t + 1 < NT) { CP_WAIT(1); } else { CP_WAIT(0); }
        __syncthreads();

        // -------- PV (v hi only; w hi f32-acc, w lo f16-acc) --------
#pragma unroll 1
        for (int ch = 0; ch < 8; ch++) {
            int sub = ch >> 2;
            uint32_t cb = (uint32_t)(((ch & 3) * 16 + bkq) * 2);
            uint32_t vbaseh = vbuf + sub * 8192;
#pragma unroll
            for (int jd = 0; jd < 4; jd++) {
                int dn = jd * 16 + bnp;
                uint32_t vh[4];
                ldsm4(vh, vbaseh + sw128(dn * 128 + cb));
                mma_h32(o[2 * jd],      ahf[ch], vh + 0);
                mma_h32(o[2 * jd + 1],  ahf[ch], vh + 2);
                mma_h16(ox[2 * jd],     alf[ch], vh + 0);
                mma_h16(ox[2 * jd + 1], alf[ch], vh + 2);
            }
        }
        __syncthreads();   // vbuf consumed before next staging
    }

    // epilogue
#pragma unroll
    for (int j = 0; j < 8; j++) {
        int gc = qc0 + j * 8 + 2 * t4;
        float2 ca = __half22float2(*(__half2*)&ox[j][0]);
        float2 cb2 = __half22float2(*(__half2*)&ox[j][1]);
        *(float2*)&g_attn[(size_t)rA * E + gc] =
            make_float2(o[j][0] + ca.x, o[j][1] + ca.y);
        *(float2*)&g_attn[(size_t)rB * E + gc] =
            make_float2(o[j][2] + cb2.x, o[j][3] + cb2.y);
    }
}

// ---------------------------------------------------------------------------
// Launch.  fused_attn must be launch index 3 (ncu capture).
// ---------------------------------------------------------------------------
extern "C" void kernel_launch(void* const* d_in, const int* in_sizes, int n_in,
                              void* d_out, int out_size)
{
    (void)in_sizes; (void)n_in; (void)out_size;
    const float* query = (const float*)d_in[0];
    const float* key   = (const float*)d_in[1];
    const float* value = (const float*)d_in[2];
    const float* sim   = (const float*)d_in[3];
    const float* Wq    = (const float*)d_in[4];
    const float* bq    = (const float*)d_in[5];
    const float* Wk    = (const float*)d_in[6];
    const float* bk    = (const float*)d_in[7];
    const float* Wv    = (const float*)d_in[8];
    const float* bv    = (const float*)d_in[9];
    const float* Wo    = (const float*)d_in[10];
    const float* bo    = (const float*)d_in[11];

    float* out = (float*)d_out;                 // [S,E]
    float* w   = out + (size_t)S * E;           // [H,S,S]

    float *grel, *gattn;
    cudaGetSymbolAddress((void**)&grel,  g_rel);
    cudaGetSymbolAddress((void**)&gattn, g_attn);

    static int attr_done = 0;
    if (!attr_done) {
        cudaFuncSetAttribute(fused_attn,
                             cudaFuncAttributeMaxDynamicSharedMemorySize, 49152);
        attr_done = 1;
    }

    dim3 blk(256);

    // 0: q/k/v projections (batched)
    proj_qkv<<<dim3(E / 128, S / 128, 3), blk>>>(query, key, value,
                                                 Wq, Wk, Wv, bq, bk, bv);

    // 1: pre-split k/v into fp16 hi-only swizzled tile images
    prep_kv<<<dim3(NT, H), dim3(128)>>>();

    // 2: rel = sim @ sim^T
    tc_gemm<<<dim3(S / 128, S / 128), blk>>>(sim, sim, grel, HD, HD, HD, S, nullptr, 0);

    // 3: fused attention  (<-- ncu capture index)
    fused_attn<<<dim3(S / 128, H), blk, 49152>>>(grel, w);

    // 4: out = attn @ Wo^T + bo
    tc_gemm<<<dim3(E / 128, S / 128), blk>>>(gattn, Wo, out, E, E, E, E, bo, 0);
}

// round 14
// speedup vs baseline: 1.3943x; 1.0062x over previous
#include <cuda_runtime.h>
#include <cuda_bf16.h>
#include <cuda_fp16.h>
#include <cstdint>
#include <cstddef>

#define S 2048
#define E 1024
#define H 16
#define HD 64
#define NT 16
#define SCALE 0.125f

// Scratch
__device__ float g_q[S * E];
__device__ float g_k[S * E];
__device__ float g_v[S * E];
__device__ float g_rel[S * S];
__device__ float g_attn[S * E];
// fp16 HI-only pre-swizzled tile images (exact smem byte layout), 16KB/tile
__device__ __align__(128) char g_kt[H * NT * 16384];
__device__ __align__(128) char g_vt[H * NT * 16384];

// ---------------------------------------------------------------------------
// Helpers
// ---------------------------------------------------------------------------
__device__ __forceinline__ uint32_t smem_u32(const void* p) {
    uint32_t a;
    asm("{ .reg .u64 t; cvta.to.shared.u64 t, %1; cvt.u32.u64 %0, t; }"
        : "=r"(a) : "l"(p));
    return a;
}

__device__ __forceinline__ uint32_t sw128(uint32_t off) {
    return off ^ ((off >> 3) & 0x70);
}

__device__ __forceinline__ void ldsm4(uint32_t* r, uint32_t addr) {
    asm volatile("ldmatrix.sync.aligned.m8n8.x4.shared.b16 {%0,%1,%2,%3}, [%4];"
                 : "=r"(r[0]), "=r"(r[1]), "=r"(r[2]), "=r"(r[3]) : "r"(addr));
}

// bf16 mma, f32 acc (GEMM path — proven)
__device__ __forceinline__ void mma16816(float* c, const uint32_t* a, const uint32_t* b) {
    asm volatile(
        "mma.sync.aligned.m16n8k16.row.col.f32.bf16.bf16.f32 "
        "{%0,%1,%2,%3}, {%4,%5,%6,%7}, {%8,%9}, {%0,%1,%2,%3};"
        : "+f"(c[0]), "+f"(c[1]), "+f"(c[2]), "+f"(c[3])
        : "r"(a[0]), "r"(a[1]), "r"(a[2]), "r"(a[3]), "r"(b[0]), "r"(b[1]));
}

// fp16 mma, f32 acc
__device__ __forceinline__ void mma_h32(float* c, const uint32_t* a, const uint32_t* b) {
    asm volatile(
        "mma.sync.aligned.m16n8k16.row.col.f32.f16.f16.f32 "
        "{%0,%1,%2,%3}, {%4,%5,%6,%7}, {%8,%9}, {%0,%1,%2,%3};"
        : "+f"(c[0]), "+f"(c[1]), "+f"(c[2]), "+f"(c[3])
        : "r"(a[0]), "r"(a[1]), "r"(a[2]), "r"(a[3]), "r"(b[0]), "r"(b[1]));
}

// fp16 mma, f16 acc (A-side lo cross term)
__device__ __forceinline__ void mma_h16(uint32_t* c, const uint32_t* a, const uint32_t* b) {
    asm volatile(
        "mma.sync.aligned.m16n8k16.row.col.f16.f16.f16.f16 "
        "{%0,%1}, {%2,%3,%4,%5}, {%6,%7}, {%0,%1};"
        : "+r"(c[0]), "+r"(c[1])
        : "r"(a[0]), "r"(a[1]), "r"(a[2]), "r"(a[3]), "r"(b[0]), "r"(b[1]));
}

// bf16 split (GEMM)
__device__ __forceinline__ void split_store_pair(char* base, int row, int col2,
                                                 float x0, float x1) {
    __nv_bfloat16 h0 = __float2bfloat16(x0);
    __nv_bfloat16 h1 = __float2bfloat16(x1);
    __nv_bfloat16 l0 = __float2bfloat16(x0 - __bfloat162float(h0));
    __nv_bfloat16 l1 = __float2bfloat16(x1 - __bfloat162float(h1));
    __nv_bfloat162 hp; hp.x = h0; hp.y = h1;
    __nv_bfloat162 lp; lp.x = l0; lp.y = l1;
    *(__nv_bfloat162*)(base + sw128(row * 128 + col2 * 2)) = hp;
    *(__nv_bfloat162*)(base + sw128(row * 128 + 64 + col2 * 2)) = lp;
}

// fp16 split of a pair
__device__ __forceinline__ void split2h(float x, float y, uint32_t& hi, uint32_t& lo) {
    __half2 hp = __floats2half2_rn(x, y);
    float rx = x - __half2float(__low2half(hp));
    float ry = y - __half2float(__high2half(hp));
    __half2 lp = __floats2half2_rn(rx, ry);
    hi = *(uint32_t*)&hp;
    lo = *(uint32_t*)&lp;
}

#define CP16(dst, src) \
    asm volatile("cp.async.cg.shared.global [%0], [%1], 16;" :: "r"(dst), "l"(src))
#define CP_COMMIT() asm volatile("cp.async.commit_group;" ::: "memory")
#define CP_WAIT(n)  asm volatile("cp.async.wait_group %0;" :: "n"(n) : "memory")

__constant__ int c_aofs[3] = {0, 0, 32};
__constant__ int c_bofs[3] = {0, 32, 0};

// ---------------------------------------------------------------------------
// GEMM body (bf16x3, proven)
// ---------------------------------------------------------------------------
__device__ __forceinline__ void gemm_body(
    const float* __restrict__ A, const float* __restrict__ B,
    float* __restrict__ C, int K, int lda, int ldb, int ldc,
    const float* __restrict__ bias, int row0, int col0)
{
    __shared__ __align__(128) char smA[128 * 128];
    __shared__ __align__(128) char smB[128 * 128];

    const int tid = threadIdx.x;
    const int warp = tid >> 5, lane = tid & 31;
    const int wm0 = (warp >> 1) * 32;
    const int wn0 = (warp & 1) * 64;

    uint32_t sA = smem_u32(smA);
    uint32_t sB = smem_u32(smB);

    float c[2][8][4];
#pragma unroll
    for (int i = 0; i < 2; i++)
#pragma unroll
        for (int j = 0; j < 8; j++)
#pragma unroll
            for (int t = 0; t < 4; t++) c[i][j][t] = 0.f;

    const int lr = tid >> 4;
    const int lp = tid & 15;

    for (int k0 = 0; k0 < K; k0 += 32) {
#pragma unroll
        for (int s = 0; s < 8; s++) {
            int r = s * 16 + lr;
            float2 va = *(const float2*)&A[(size_t)(row0 + r) * lda + k0 + 2 * lp];
            split_store_pair(smA, r, 2 * lp, va.x, va.y);
            float2 vb = *(const float2*)&B[(size_t)(col0 + r) * ldb + k0 + 2 * lp];
            split_store_pair(smB, r, 2 * lp, vb.x, vb.y);
        }
        __syncthreads();

        const int arow = wm0 + (lane & 15);
        const int acolq = (lane >> 4) * 8;
        const int bn = wn0 + (lane & 7) + ((lane >> 4) << 3);
        const int bkq = ((lane >> 3) & 1) * 8;

#pragma unroll
        for (int s3 = 0; s3 < 3; s3++) {
            const int aoff = c_aofs[s3], boff = c_bofs[s3];
#pragma unroll
            for (int ks = 0; ks < 2; ks++) {
                int acol = aoff + ks * 16 + acolq;
                uint32_t a0[4], a1[4];
                ldsm4(a0, sA + sw128((uint32_t)(arow * 128 + acol * 2)));
                ldsm4(a1, sA + sw128((uint32_t)((arow + 16) * 128 + acol * 2)));
                int bcol = boff + ks * 16 + bkq;
                uint32_t bq[4][4];
#pragma unroll
                for (int j2 = 0; j2 < 4; j2++)
                    ldsm4(bq[j2], sB + sw128((uint32_t)((bn + j2 * 16) * 128 + bcol * 2)));
#pragma unroll
                for (int i = 0; i < 2; i++) {
                    const uint32_t* ai = (i == 0) ? a0 : a1;
#pragma unroll
                    for (int j = 0; j < 8; j++)
                        mma16816(c[i][j], ai, &bq[j >> 1][(j & 1) * 2]);
                }
            }
        }
        __syncthreads();
    }

    const int g = lane >> 2, t4 = lane & 3;
#pragma unroll
    for (int i = 0; i < 2; i++) {
#pragma unroll
        for (int j = 0; j < 8; j++) {
            int gr0 = row0 + wm0 + i * 16 + g;
            int gc = col0 + wn0 + j * 8 + t4 * 2;
            float v0 = c[i][j][0], v1 = c[i][j][1];
            float v2 = c[i][j][2], v3 = c[i][j][3];
            if (bias) {
                float2 bv = *(const float2*)&bias[gc];
                v0 += bv.x; v1 += bv.y; v2 += bv.x; v3 += bv.y;
            }
            *(float2*)&C[(size_t)gr0 * ldc + gc] = make_float2(v0, v1);
            *(float2*)&C[(size_t)(gr0 + 8) * ldc + gc] = make_float2(v2, v3);
        }
    }
}

__global__ __launch_bounds__(256) void tc_gemm(
    const float* __restrict__ A, const float* __restrict__ B,
    float* __restrict__ C, int K, int lda, int ldb, int ldc,
    const float* __restrict__ bias, int row_base)
{
    gemm_body(A, B, C, K, lda, ldb, ldc, bias,
              row_base + blockIdx.y * 128, blockIdx.x * 128);
}

__global__ __launch_bounds__(256) void proj_qkv(
    const float* __restrict__ query, const float* __restrict__ key,
    const float* __restrict__ value,
    const float* __restrict__ Wq, const float* __restrict__ Wk,
    const float* __restrict__ Wv,
    const float* __restrict__ bq, const float* __restrict__ bk,
    const float* __restrict__ bv)
{
    const int z = blockIdx.z;
    const float* A = (z == 0) ? query : (z == 1) ? key : value;
    const float* B = (z == 0) ? Wq : (z == 1) ? Wk : Wv;
    const float* bias = (z == 0) ? bq : (z == 1) ? bk : bv;
    float* C = (z == 0) ? g_q : (z == 1) ? g_k : g_v;
    gemm_body(A, B, C, E, E, E, E, bias, blockIdx.y * 128, blockIdx.x * 128);
}

// ---------------------------------------------------------------------------
// prep_kv: fp16 HI-only pre-swizzled 16KB tile images. grid (NT, H), 128 thr.
// ---------------------------------------------------------------------------
__global__ __launch_bounds__(128) void prep_kv()
{
    const int tid = threadIdx.x;
    const int t0 = blockIdx.x * 128;
    const int h = blockIdx.y;
    const int qc0 = h * HD;
    char* kimg = g_kt + ((size_t)(h * NT + blockIdx.x)) * 16384;
    char* vimg = g_vt + ((size_t)(h * NT + blockIdx.x)) * 16384;

    const int lr = tid >> 4, lp = tid & 15;
#pragma unroll 4
    for (int s = 0; s < 16; s++) {
        int tr = s * 8 + lr;
        float4 kv = *(const float4*)&g_k[(size_t)(t0 + tr) * E + qc0 + 4 * lp];
        __half2 h01 = __floats2half2_rn(kv.x, kv.y);
        __half2 h23 = __floats2half2_rn(kv.z, kv.w);
        *(uint2*)(kimg + sw128(tr * 128 + 8 * lp)) =
            make_uint2(*(uint32_t*)&h01, *(uint32_t*)&h23);

        float4 vv = *(const float4*)&g_v[(size_t)(t0 + tr) * E + qc0 + 4 * lp];
        int sub = tr >> 6, tc = tr & 63;
        char* bh_ = vimg + sub * 8192;
        float vs[4] = {vv.x, vv.y, vv.z, vv.w};
#pragma unroll
        for (int j = 0; j < 4; j++) {
            int d = 4 * lp + j;
            *(__half*)(bh_ + sw128(d * 128 + tc * 2)) = __float2half_rn(vs[j]);
        }
    }
}

// ---------------------------------------------------------------------------
// fused_attn: 128 threads (4 warps, 2M x 2N), 64 q-rows/CTA, grid (S/64, H).
// Warp: scores m32 x n64(t-slice).  PV: full d=64 over own t-slice, then
// cross-warp (wn) partial-sum combine through smem.  48KB smem:
//   [0,16K)=kbuf0  [16K,32K)=kbuf1  [32K,48K)=vbuf / l-combine / o-combine
// ---------------------------------------------------------------------------
__global__ __launch_bounds__(128) void fused_attn(
    const float* __restrict__ rel, float* __restrict__ wout)
{
    extern __shared__ char dyn[];
    const uint32_t smb = smem_u32(dyn);
    const uint32_t vbuf = smb + 32768;

    const int tid = threadIdx.x;
    const int warp = tid >> 5, lane = tid & 31;
    const int wm = warp >> 1, wn = warp & 1;
    const int g = lane >> 2, t4 = lane & 3;
    const int h = blockIdx.y;
    const int row0 = blockIdx.x * 64;
    const int qc0 = h * HD;

    const int rA = row0 + wm * 32 + g;      // rows: rA, rA+8, rA+16, rA+24
    const int rB = rA + 8, rC = rA + 16, rD = rA + 24;

    // q fragments m32: blk0 = rows rA/rB, blk1 = rows rC/rD
    uint32_t qh[4][2][4], ql[4][2][4];
#pragma unroll
    for (int ks = 0; ks < 4; ks++) {
        int c = qc0 + ks * 16 + 2 * t4;
#pragma unroll
        for (int blk = 0; blk < 2; blk++) {
            int ra = rA + blk * 16, rb = rB + blk * 16;
            float2 x00 = *(const float2*)&g_q[(size_t)ra * E + c];
            float2 x10 = *(const float2*)&g_q[(size_t)rb * E + c];
            float2 x01 = *(const float2*)&g_q[(size_t)ra * E + c + 8];
            float2 x11 = *(const float2*)&g_q[(size_t)rb * E + c + 8];
            split2h(x00.x * SCALE, x00.y * SCALE, qh[ks][blk][0], ql[ks][blk][0]);
            split2h(x10.x * SCALE, x10.y * SCALE, qh[ks][blk][1], ql[ks][blk][1]);
            split2h(x01.x * SCALE, x01.y * SCALE, qh[ks][blk][2], ql[ks][blk][2]);
            split2h(x11.x * SCALE, x11.y * SCALE, qh[ks][blk][3], ql[ks][blk][3]);
        }
    }

    const int bnp = (lane & 7) + ((lane >> 4) << 3);
    const int bkq = ((lane >> 3) & 1) * 8;
    const int tco = wn * 64;                 // warp's t-col base within tile

    const char* ksrc = g_kt + ((size_t)h * NT) * 16384;
    const char* vsrc = g_vt + ((size_t)h * NT) * 16384;

    float lA = 0.f, lB = 0.f, lC = 0.f, lD = 0.f;

    // ===================== PASS 1: row sums =====================
#pragma unroll
    for (int i = 0; i < 8; i++) {
        uint32_t off = (uint32_t)(tid + i * 128) * 16;
        CP16(smb + off, ksrc + off);
    }
    CP_COMMIT();

#pragma unroll 1
    for (int t = 0; t < NT; t++) {
        CP_WAIT(0);
        __syncthreads();
        if (t + 1 < NT) {
            const char* src = ksrc + (size_t)(t + 1) * 16384;
            uint32_t dst = smb + ((t + 1) & 1) * 16384;
#pragma unroll
            for (int i = 0; i < 8; i++) {
                uint32_t off = (uint32_t)(tid + i * 128) * 16;
                CP16(dst + off, src + off);
            }
            CP_COMMIT();
        }
        const uint32_t uSkh = smb + (t & 1) * 16384;

#pragma unroll 1
        for (int ch = 0; ch < 4; ch++) {
            int tc = tco + ch * 16;
            int cg = t * 128 + tc + 2 * t4;
            float2 r00 = *(const float2*)&rel[(size_t)rA * S + cg];
            float2 r01 = *(const float2*)&rel[(size_t)rA * S + cg + 8];
            float2 r10 = *(const float2*)&rel[(size_t)rB * S + cg];
            float2 r11 = *(const float2*)&rel[(size_t)rB * S + cg + 8];
            float2 r20 = *(const float2*)&rel[(size_t)rC * S + cg];
            float2 r21 = *(const float2*)&rel[(size_t)rC * S + cg + 8];
            float2 r30 = *(const float2*)&rel[(size_t)rD * S + cg];
            float2 r31 = *(const float2*)&rel[(size_t)rD * S + cg + 8];

            float cs[2][2][4];
#pragma unroll
            for (int i = 0; i < 2; i++)
#pragma unroll
                for (int j = 0; j < 2; j++)
#pragma unroll
                    for (int q2 = 0; q2 < 4; q2++) cs[i][j][q2] = 0.f;

            int brow = tc + bnp;
#pragma unroll
            for (int ks = 0; ks < 4; ks++) {
                uint32_t bh[4];
                ldsm4(bh, uSkh + sw128((uint32_t)(brow * 128 + (ks * 16 + bkq) * 2)));
                mma_h32(cs[0][0], qh[ks][0], bh + 0);
                mma_h32(cs[0][1], qh[ks][0], bh + 2);
                mma_h32(cs[1][0], qh[ks][1], bh + 0);
                mma_h32(cs[1][1], qh[ks][1], bh + 2);
            }
            lA += __expf(cs[0][0][0] + r00.x * SCALE) + __expf(cs[0][0][1] + r00.y * SCALE) +
                  __expf(cs[0][1][0] + r01.x * SCALE) + __expf(cs[0][1][1] + r01.y * SCALE);
            lB += __expf(cs[0][0][2] + r10.x * SCALE) + __expf(cs[0][0][3] + r10.y * SCALE) +
                  __expf(cs[0][1][2] + r11.x * SCALE) + __expf(cs[0][1][3] + r11.y * SCALE);
            lC += __expf(cs[1][0][0] + r20.x * SCALE) + __expf(cs[1][0][1] + r20.y * SCALE) +
                  __expf(cs[1][1][0] + r21.x * SCALE) + __expf(cs[1][1][1] + r21.y * SCALE);
            lD += __expf(cs[1][0][2] + r30.x * SCALE) + __expf(cs[1][0][3] + r30.y * SCALE) +
                  __expf(cs[1][1][2] + r31.x * SCALE) + __expf(cs[1][1][3] + r31.y * SCALE);
        }
    }

    lA += __shfl_xor_sync(0xffffffffu, lA, 1);
    lA += __shfl_xor_sync(0xffffffffu, lA, 2);
    lB += __shfl_xor_sync(0xffffffffu, lB, 1);
    lB += __shfl_xor_sync(0xffffffffu, lB, 2);
    lC += __shfl_xor_sync(0xffffffffu, lC, 1);
    lC += __shfl_xor_sync(0xffffffffu, lC, 2);
    lD += __shfl_xor_sync(0xffffffffu, lD, 1);
    lD += __shfl_xor_sync(0xffffffffu, lD, 2);

    // combine l across the two N-warps via smem (vbuf free in pass 1)
    float* sml = (float*)(dyn + 32768);
    __syncthreads();
    if (t4 == 0) {
        sml[wn * 64 + wm * 32 + g]      = lA;
        sml[wn * 64 + wm * 32 + g + 8]  = lB;
        sml[wn * 64 + wm * 32 + g + 16] = lC;
        sml[wn * 64 + wm * 32 + g + 24] = lD;
    }
    __syncthreads();
    const float invA = 1.f / (sml[wm * 32 + g]      + sml[64 + wm * 32 + g]);
    const float invB = 1.f / (sml[wm * 32 + g + 8]  + sml[64 + wm * 32 + g + 8]);
    const float invC = 1.f / (sml[wm * 32 + g + 16] + sml[64 + wm * 32 + g + 16]);
    const float invD = 1.f / (sml[wm * 32 + g + 24] + sml[64 + wm * 32 + g + 24]);
    __syncthreads();   // done reading smem-l before vbuf reuse

    // PV partials: full d=64 (8 n8-tiles), own t-half.  o[blk][n8][4]
    float o[2][8][4];
    uint32_t ox[2][8][2];
#pragma unroll
    for (int i = 0; i < 2; i++)
#pragma unroll
        for (int j = 0; j < 8; j++) {
#pragma unroll
            for (int q2 = 0; q2 < 4; q2++) o[i][j][q2] = 0.f;
            ox[i][j][0] = 0u; ox[i][j][1] = 0u;
        }

    float* wrow = wout + (size_t)h * S * S;

    // ===================== PASS 2: w + PV (per-chunk interleaved) =========
#pragma unroll
    for (int i = 0; i < 8; i++) {
        uint32_t off = (uint32_t)(tid + i * 128) * 16;
        CP16(smb + off, ksrc + off);
    }
    CP_COMMIT();

#pragma unroll 1
    for (int t = 0; t < NT; t++) {
        // stage v_t
        {
            const char* srcv = vsrc + (size_t)t * 16384;
#pragma unroll
            for (int i = 0; i < 8; i++) {
                uint32_t off = (uint32_t)(tid + i * 128) * 16;
                CP16(vbuf + off, srcv + off);
            }
            CP_COMMIT();
        }
        // stage k_{t+1}
        if (t + 1 < NT) {
            const char* src = ksrc + (size_t)(t + 1) * 16384;
            uint32_t dst = smb + ((t + 1) & 1) * 16384;
#pragma unroll
            for (int i = 0; i < 8; i++) {
                uint32_t off = (uint32_t)(tid + i * 128) * 16;
                CP16(dst + off, src + off);
            }
            CP_COMMIT();
        }
        if (t + 1 < NT) { CP_WAIT(1); } else { CP_WAIT(0); }   // k_t & v_t ready
        __syncthreads();

        const uint32_t uSkh = smb + (t & 1) * 16384;

#pragma unroll 1
        for (int ch = 0; ch < 4; ch++) {
            int tc = tco + ch * 16;
            int cg = t * 128 + tc + 2 * t4;
            float2 r00 = *(const float2*)&rel[(size_t)rA * S + cg];
            float2 r01 = *(const float2*)&rel[(size_t)rA * S + cg + 8];
            float2 r10 = *(const float2*)&rel[(size_t)rB * S + cg];
            float2 r11 = *(const float2*)&rel[(size_t)rB * S + cg + 8];
            float2 r20 = *(const float2*)&rel[(size_t)rC * S + cg];
            float2 r21 = *(const float2*)&rel[(size_t)rC * S + cg + 8];
            float2 r30 = *(const float2*)&rel[(size_t)rD * S + cg];
            float2 r31 = *(const float2*)&rel[(size_t)rD * S + cg + 8];

            float cs[2][2][4];
            uint32_t cx[2][2][2];
#pragma unroll
            for (int i = 0; i < 2; i++)
#pragma unroll
                for (int j = 0; j < 2; j++) {
#pragma unroll
                    for (int q2 = 0; q2 < 4; q2++) cs[i][j][q2] = 0.f;
                    cx[i][j][0] = 0u; cx[i][j][1] = 0u;
                }

            int brow = tc + bnp;
#pragma unroll
            for (int ks = 0; ks < 4; ks++) {
                uint32_t bh[4];
                ldsm4(bh, uSkh + sw128((uint32_t)(brow * 128 + (ks * 16 + bkq) * 2)));
                mma_h32(cs[0][0], qh[ks][0], bh + 0);
                mma_h32(cs[0][1], qh[ks][0], bh + 2);
                mma_h32(cs[1][0], qh[ks][1], bh + 0);
                mma_h32(cs[1][1], qh[ks][1], bh + 2);
                mma_h16(cx[0][0], ql[ks][0], bh + 0);
                mma_h16(cx[0][1], ql[ks][0], bh + 2);
                mma_h16(cx[1][0], ql[ks][1], bh + 0);
                mma_h16(cx[1][1], ql[ks][1], bh + 2);
            }

            float2 xa0 = __half22float2(*(__half2*)&cx[0][0][0]);
            float2 xa1 = __half22float2(*(__half2*)&cx[0][1][0]);
            float2 xb0 = __half22float2(*(__half2*)&cx[0][0][1]);
            float2 xb1 = __half22float2(*(__half2*)&cx[0][1][1]);
            float2 xc0 = __half22float2(*(__half2*)&cx[1][0][0]);
            float2 xc1 = __half22float2(*(__half2*)&cx[1][1][0]);
            float2 xd0 = __half22float2(*(__half2*)&cx[1][0][1]);
            float2 xd1 = __half22float2(*(__half2*)&cx[1][1][1]);

            float wA0 = __expf(cs[0][0][0] + xa0.x + r00.x * SCALE) * invA;
            float wA1 = __expf(cs[0][0][1] + xa0.y + r00.y * SCALE) * invA;
            float wA2 = __expf(cs[0][1][0] + xa1.x + r01.x * SCALE) * invA;
            float wA3 = __expf(cs[0][1][1] + xa1.y + r01.y * SCALE) * invA;
            float wB0 = __expf(cs[0][0][2] + xb0.x + r10.x * SCALE) * invB;
            float wB1 = __expf(cs[0][0][3] + xb0.y + r10.y * SCALE) * invB;
            float wB2 = __expf(cs[0][1][2] + xb1.x + r11.x * SCALE) * invB;
            float wB3 = __expf(cs[0][1][3] + xb1.y + r11.y * SCALE) * invB;
            float wC0 = __expf(cs[1][0][0] + xc0.x + r20.x * SCALE) * invC;
            float wC1 = __expf(cs[1][0][1] + xc0.y + r20.y * SCALE) * invC;
            float wC2 = __expf(cs[1][1][0] + xc1.x + r21.x * SCALE) * invC;
            float wC3 = __expf(cs[1][1][1] + xc1.y + r21.y * SCALE) * invC;
            float wD0 = __expf(cs[1][0][2] + xd0.x + r30.x * SCALE) * invD;
            float wD1 = __expf(cs[1][0][3] + xd0.y + r30.y * SCALE) * invD;
            float wD2 = __expf(cs[1][1][2] + xd1.x + r31.x * SCALE) * invD;
            float wD3 = __expf(cs[1][1][3] + xd1.y + r31.y * SCALE) * invD;

            *(float2*)&wrow[(size_t)rA * S + cg]     = make_float2(wA0, wA1);
            *(float2*)&wrow[(size_t)rA * S + cg + 8] = make_float2(wA2, wA3);
            *(float2*)&wrow[(size_t)rB * S + cg]     = make_float2(wB0, wB1);
            *(float2*)&wrow[(size_t)rB * S + cg + 8] = make_float2(wB2, wB3);
            *(float2*)&wrow[(size_t)rC * S + cg]     = make_float2(wC0, wC1);
            *(float2*)&wrow[(size_t)rC * S + cg + 8] = make_float2(wC2, wC3);
            *(float2*)&wrow[(size_t)rD * S + cg]     = make_float2(wD0, wD1);
            *(float2*)&wrow[(size_t)rD * S + cg + 8] = make_float2(wD2, wD3);

            // pack A-frags for PV
            uint32_t ah0[4], al0[4], ah1[4], al1[4];
            split2h(wA0, wA1, ah0[0], al0[0]);
            split2h(wB0, wB1, ah0[1], al0[1]);
            split2h(wA2, wA3, ah0[2], al0[2]);
            split2h(wB2, wB3, ah0[3], al0[3]);
            split2h(wC0, wC1, ah1[0], al1[0]);
            split2h(wD0, wD1, ah1[1], al1[1]);
            split2h(wC2, wC3, ah1[2], al1[2]);
            split2h(wD2, wD3, ah1[3], al1[3]);

            // PV for this chunk: FULL d=64 (jd 0..3) over own t-slice
            int sub = tc >> 6;                               // = wn
            uint32_t cb = (uint32_t)(((tc & 63) + bkq) * 2);
#pragma unroll
            for (int jd = 0; jd < 4; jd++) {
                int dn = jd * 16 + bnp;
                uint32_t vh[4];
                ldsm4(vh, vbuf + sub * 8192 + sw128((uint32_t)(dn * 128 + cb)));
                mma_h32(o[0][jd * 2 + 0], ah0, vh + 0);
                mma_h32(o[0][jd * 2 + 1], ah0, vh + 2);
                mma_h32(o[1][jd * 2 + 0], ah1, vh + 0);
                mma_h32(o[1][jd * 2 + 1], ah1, vh + 2);
                mma_h16(ox[0][jd * 2 + 0], al0, vh + 0);
                mma_h16(ox[0][jd * 2 + 1], al0, vh + 2);
                mma_h16(ox[1][jd * 2 + 0], al1, vh + 0);
                mma_h16(ox[1][jd * 2 + 1], al1, vh + 2);
            }
        }
        __syncthreads();   // buffers consumed before next staging
    }

    // ---- epilogue: combine PV partials across the two N-warps ----
    // of = o + ox  (fp16 cross term folded in)
    float of[2][8][4];
#pragma unroll
    for (int i = 0; i < 2; i++)
#pragma unroll
        for (int j = 0; j < 8; j++) {
            float2 cl = __half22float2(*(__half2*)&ox[i][j][0]);
            float2 ch2 = __half22float2(*(__half2*)&ox[i][j][1]);
            of[i][j][0] = o[i][j][0] + cl.x;
            of[i][j][1] = o[i][j][1] + cl.y;
            of[i][j][2] = o[i][j][2] + ch2.x;
            of[i][j][3] = o[i][j][3] + ch2.y;
        }

    float* red = (float*)dyn;   // 64 rows x 64 cols = 16KB (kbuf region, free now)
    __syncthreads();
    if (wn == 0) {
#pragma unroll
        for (int i = 0; i < 2; i++)
#pragma unroll
            for (int j = 0; j < 8; j++) {
                int r = wm * 32 + i * 16 + g;
                int c = j * 8 + 2 * t4;
                *(float2*)&red[r * 64 + c] = make_float2(of[i][j][0], of[i][j][1]);
                *(float2*)&red[(r + 8) * 64 + c] = make_float2(of[i][j][2], of[i][j][3]);
            }
    }
    __syncthreads();
    if (wn == 1) {
#pragma unroll
        for (int i = 0; i < 2; i++)
#pragma unroll
            for (int j = 0; j < 8; j++) {
                int r = wm * 32 + i * 16 + g;
                int c = j * 8 + 2 * t4;
                float2 p0 = *(const float2*)&red[r * 64 + c];
                float2 p1 = *(const float2*)&red[(r + 8) * 64 + c];
                *(float2*)&g_attn[(size_t)(row0 + r) * E + qc0 + c] =
                    make_float2(of[i][j][0] + p0.x, of[i][j][1] + p0.y);
                *(float2*)&g_attn[(size_t)(row0 + r + 8) * E + qc0 + c] =
                    make_float2(of[i][j][2] + p1.x, of[i][j][3] + p1.y);
            }
    }
}

// ---------------------------------------------------------------------------
// Launch.  fused_attn must be launch index 3 (ncu capture).
// ---------------------------------------------------------------------------
extern "C" void kernel_launch(void* const* d_in, const int* in_sizes, int n_in,
                              void* d_out, int out_size)
{
    (void)in_sizes; (void)n_in; (void)out_size;
    const float* query = (const float*)d_in[0];
    const float* key   = (const float*)d_in[1];
    const float* value = (const float*)d_in[2];
    const float* sim   = (const float*)d_in[3];
    const float* Wq    = (const float*)d_in[4];
    const float* bq    = (const float*)d_in[5];
    const float* Wk    = (const float*)d_in[6];
    const float* bk    = (const float*)d_in[7];
    const float* Wv    = (const float*)d_in[8];
    const float* bv    = (const float*)d_in[9];
    const float* Wo    = (const float*)d_in[10];
    const float* bo    = (const float*)d_in[11];

    float* out = (float*)d_out;                 // [S,E]
    float* w   = out + (size_t)S * E;           // [H,S,S]

    float *grel, *gattn;
    cudaGetSymbolAddress((void**)&grel,  g_rel);
    cudaGetSymbolAddress((void**)&gattn, g_attn);

    static int attr_done = 0;
    if (!attr_done) {
        cudaFuncSetAttribute(fused_attn,
                             cudaFuncAttributeMaxDynamicSharedMemorySize, 49152);
        attr_done = 1;
    }

    dim3 blk(256);

    // 0: q/k/v projections (batched)
    proj_qkv<<<dim3(E / 128, S / 128, 3), blk>>>(query, key, value,
                                                 Wq, Wk, Wv, bq, bk, bv);

    // 1: pre-split k/v into fp16 hi-only swizzled tile images
    prep_kv<<<dim3(NT, H), dim3(128)>>>();

    // 2: rel = sim @ sim^T
    tc_gemm<<<dim3(S / 128, S / 128), blk>>>(sim, sim, grel, HD, HD, HD, S, nullptr, 0);

    // 3: fused attention  (<-- ncu capture index)
    fused_attn<<<dim3(S / 64, H), dim3(128), 49152>>>(grel, w);

    // 4: out = attn @ Wo^T + bo
    tc_gemm<<<dim3(E / 128, S / 128), blk>>>(gattn, Wo, out, E, E, E, E, bo, 0);
}

// round 15
// speedup vs baseline: 1.6222x; 1.1634x over previous
#include <cuda_runtime.h>
#include <cuda_bf16.h>
#include <cuda_fp16.h>
#include <cstdint>
#include <cstddef>

#define S 2048
#define E 1024
#define H 16
#define HD 64
#define NT 16
#define SCALE 0.125f

// Scratch
__device__ float g_q[S * E];
__device__ float g_k[S * E];
__device__ float g_v[S * E];
__device__ float g_rel[S * S];
__device__ float g_attn[S * E];
// fp16 HI-only pre-swizzled tile images (exact smem byte layout), 16KB/tile
__device__ __align__(128) char g_kt[H * NT * 16384];
__device__ __align__(128) char g_vt[H * NT * 16384];

// ---------------------------------------------------------------------------
// Helpers
// ---------------------------------------------------------------------------
__device__ __forceinline__ uint32_t smem_u32(const void* p) {
    uint32_t a;
    asm("{ .reg .u64 t; cvta.to.shared.u64 t, %1; cvt.u32.u64 %0, t; }"
        : "=r"(a) : "l"(p));
    return a;
}

__device__ __forceinline__ uint32_t sw128(uint32_t off) {
    return off ^ ((off >> 3) & 0x70);
}

__device__ __forceinline__ void ldsm4(uint32_t* r, uint32_t addr) {
    asm volatile("ldmatrix.sync.aligned.m8n8.x4.shared.b16 {%0,%1,%2,%3}, [%4];"
                 : "=r"(r[0]), "=r"(r[1]), "=r"(r[2]), "=r"(r[3]) : "r"(addr));
}

// fp16 mma, f32 acc
__device__ __forceinline__ void mma_h32(float* c, const uint32_t* a, const uint32_t* b) {
    asm volatile(
        "mma.sync.aligned.m16n8k16.row.col.f32.f16.f16.f32 "
        "{%0,%1,%2,%3}, {%4,%5,%6,%7}, {%8,%9}, {%0,%1,%2,%3};"
        : "+f"(c[0]), "+f"(c[1]), "+f"(c[2]), "+f"(c[3])
        : "r"(a[0]), "r"(a[1]), "r"(a[2]), "r"(a[3]), "r"(b[0]), "r"(b[1]));
}

// fp16 mma, f16 acc (cross terms; double-rate)
__device__ __forceinline__ void mma_h16(uint32_t* c, const uint32_t* a, const uint32_t* b) {
    asm volatile(
        "mma.sync.aligned.m16n8k16.row.col.f16.f16.f16.f16 "
        "{%0,%1}, {%2,%3,%4,%5}, {%6,%7}, {%0,%1};"
        : "+r"(c[0]), "+r"(c[1])
        : "r"(a[0]), "r"(a[1]), "r"(a[2]), "r"(a[3]), "r"(b[0]), "r"(b[1]));
}

// fp16 split of a pair
__device__ __forceinline__ void split2h(float x, float y, uint32_t& hi, uint32_t& lo) {
    __half2 hp = __floats2half2_rn(x, y);
    float rx = x - __half2float(__low2half(hp));
    float ry = y - __half2float(__high2half(hp));
    __half2 lp = __floats2half2_rn(rx, ry);
    hi = *(uint32_t*)&hp;
    lo = *(uint32_t*)&lp;
}

// fp16 split-store into SW128 row: [hi 32 fp16 | lo 32 fp16] (128B rows)
__device__ __forceinline__ void split_store_h(char* base, int row, int col2,
                                              float x0, float x1) {
    uint32_t hi, lo;
    split2h(x0, x1, hi, lo);
    *(uint32_t*)(base + sw128(row * 128 + col2 * 2)) = hi;
    *(uint32_t*)(base + sw128(row * 128 + 64 + col2 * 2)) = lo;
}

#define CP16(dst, src) \
    asm volatile("cp.async.cg.shared.global [%0], [%1], 16;" :: "r"(dst), "l"(src))
#define CP_COMMIT() asm volatile("cp.async.commit_group;" ::: "memory")
#define CP_WAIT(n)  asm volatile("cp.async.wait_group %0;" :: "n"(n) : "memory")

// ---------------------------------------------------------------------------
// GEMM body: fp16 split, hh f32-acc + cross f16-acc.
// BM=128, BN=64, BK=32, 256 threads (8 warps = 4M x 2N, m32 x n32 each).
// ---------------------------------------------------------------------------
__device__ __forceinline__ void gemm_body(
    const float* __restrict__ A, const float* __restrict__ B,
    float* __restrict__ C, int K, int lda, int ldb, int ldc,
    const float* __restrict__ bias, int row0, int col0)
{
    __shared__ __align__(128) char smA[128 * 128];   // 16KB
    __shared__ __align__(128) char smB[64 * 128];    //  8KB

    const int tid = threadIdx.x;
    const int warp = tid >> 5, lane = tid & 31;
    const int wm0 = (warp >> 1) * 32;
    const int wn0 = (warp & 1) * 32;

    uint32_t sA = smem_u32(smA);
    uint32_t sB = smem_u32(smB);

    float c[2][4][4];
    uint32_t cx[2][4][2];
#pragma unroll
    for (int i = 0; i < 2; i++)
#pragma unroll
        for (int j = 0; j < 4; j++) {
#pragma unroll
            for (int t = 0; t < 4; t++) c[i][j][t] = 0.f;
            cx[i][j][0] = 0u; cx[i][j][1] = 0u;
        }

    const int lr = tid >> 4;   // 0..15
    const int lp = tid & 15;   // 0..15

    const int arow = wm0 + (lane & 15);
    const int acolq = (lane >> 4) * 8;
    const int bn = wn0 + (lane & 7) + ((lane >> 4) << 3);
    const int bkq = ((lane >> 3) & 1) * 8;

    for (int k0 = 0; k0 < K; k0 += 32) {
#pragma unroll
        for (int s = 0; s < 8; s++) {
            int r = s * 16 + lr;
            float2 va = *(const float2*)&A[(size_t)(row0 + r) * lda + k0 + 2 * lp];
            split_store_h(smA, r, 2 * lp, va.x, va.y);
        }
#pragma unroll
        for (int s = 0; s < 4; s++) {
            int r = s * 16 + lr;
            float2 vb = *(const float2*)&B[(size_t)(col0 + r) * ldb + k0 + 2 * lp];
            split_store_h(smB, r, 2 * lp, vb.x, vb.y);
        }
        __syncthreads();

#pragma unroll
        for (int ks = 0; ks < 2; ks++) {
            uint32_t ca = (uint32_t)((ks * 16 + acolq) * 2);
            uint32_t ah0[4], ah1[4], al0[4], al1[4];
            ldsm4(ah0, sA + sw128((uint32_t)(arow * 128) + ca));
            ldsm4(ah1, sA + sw128((uint32_t)((arow + 16) * 128) + ca));
            ldsm4(al0, sA + sw128((uint32_t)(arow * 128 + 64) + ca));
            ldsm4(al1, sA + sw128((uint32_t)((arow + 16) * 128 + 64) + ca));

            uint32_t cb = (uint32_t)((ks * 16 + bkq) * 2);
            uint32_t bh[2][4], bl[2][4];
#pragma unroll
            for (int j2 = 0; j2 < 2; j2++) {
                ldsm4(bh[j2], sB + sw128((uint32_t)((bn + j2 * 16) * 128) + cb));
                ldsm4(bl[j2], sB + sw128((uint32_t)((bn + j2 * 16) * 128 + 64) + cb));
            }
#pragma unroll
            for (int i = 0; i < 2; i++) {
                const uint32_t* aih = (i == 0) ? ah0 : ah1;
                const uint32_t* ail = (i == 0) ? al0 : al1;
#pragma unroll
                for (int j = 0; j < 4; j++) {
                    const uint32_t* bhf = &bh[j >> 1][(j & 1) * 2];
                    const uint32_t* blf = &bl[j >> 1][(j & 1) * 2];
                    mma_h32(c[i][j], aih, bhf);
                    mma_h16(cx[i][j], aih, blf);
                    mma_h16(cx[i][j], ail, bhf);
                }
            }
        }
        __syncthreads();
    }

    const int g = lane >> 2, t4 = lane & 3;
#pragma unroll
    for (int i = 0; i < 2; i++) {
#pragma unroll
        for (int j = 0; j < 4; j++) {
            int gr0 = row0 + wm0 + i * 16 + g;
            int gc = col0 + wn0 + j * 8 + t4 * 2;
            float2 x0 = __half22float2(*(__half2*)&cx[i][j][0]);
            float2 x1 = __half22float2(*(__half2*)&cx[i][j][1]);
            float v0 = c[i][j][0] + x0.x, v1 = c[i][j][1] + x0.y;
            float v2 = c[i][j][2] + x1.x, v3 = c[i][j][3] + x1.y;
            if (bias) {
                float2 bv = *(const float2*)&bias[gc];
                v0 += bv.x; v1 += bv.y; v2 += bv.x; v3 += bv.y;
            }
            *(float2*)&C[(size_t)gr0 * ldc + gc] = make_float2(v0, v1);
            *(float2*)&C[(size_t)(gr0 + 8) * ldc + gc] = make_float2(v2, v3);
        }
    }
}

__global__ __launch_bounds__(256) void tc_gemm(
    const float* __restrict__ A, const float* __restrict__ B,
    float* __restrict__ C, int K, int lda, int ldb, int ldc,
    const float* __restrict__ bias, int row_base)
{
    gemm_body(A, B, C, K, lda, ldb, ldc, bias,
              row_base + blockIdx.y * 128, blockIdx.x * 64);
}

__global__ __launch_bounds__(256) void proj_qkv(
    const float* __restrict__ query, const float* __restrict__ key,
    const float* __restrict__ value,
    const float* __restrict__ Wq, const float* __restrict__ Wk,
    const float* __restrict__ Wv,
    const float* __restrict__ bq, const float* __restrict__ bk,
    const float* __restrict__ bv)
{
    const int z = blockIdx.z;
    const float* A = (z == 0) ? query : (z == 1) ? key : value;
    const float* B = (z == 0) ? Wq : (z == 1) ? Wk : Wv;
    const float* bias = (z == 0) ? bq : (z == 1) ? bk : bv;
    float* C = (z == 0) ? g_q : (z == 1) ? g_k : g_v;
    gemm_body(A, B, C, E, E, E, E, bias, blockIdx.y * 128, blockIdx.x * 64);
}

// ---------------------------------------------------------------------------
// prep_kv: fp16 HI-only pre-swizzled 16KB tile images. grid (NT, H), 128 thr.
// ---------------------------------------------------------------------------
__global__ __launch_bounds__(128) void prep_kv()
{
    const int tid = threadIdx.x;
    const int t0 = blockIdx.x * 128;
    const int h = blockIdx.y;
    const int qc0 = h * HD;
    char* kimg = g_kt + ((size_t)(h * NT + blockIdx.x)) * 16384;
    char* vimg = g_vt + ((size_t)(h * NT + blockIdx.x)) * 16384;

    const int lr = tid >> 4, lp = tid & 15;
#pragma unroll 4
    for (int s = 0; s < 16; s++) {
        int tr = s * 8 + lr;
        float4 kv = *(const float4*)&g_k[(size_t)(t0 + tr) * E + qc0 + 4 * lp];
        __half2 h01 = __floats2half2_rn(kv.x, kv.y);
        __half2 h23 = __floats2half2_rn(kv.z, kv.w);
        *(uint2*)(kimg + sw128(tr * 128 + 8 * lp)) =
            make_uint2(*(uint32_t*)&h01, *(uint32_t*)&h23);

        float4 vv = *(const float4*)&g_v[(size_t)(t0 + tr) * E + qc0 + 4 * lp];
        int sub = tr >> 6, tc = tr & 63;
        char* bh_ = vimg + sub * 8192;
        float vs[4] = {vv.x, vv.y, vv.z, vv.w};
#pragma unroll
        for (int j = 0; j < 4; j++) {
            int d = 4 * lp + j;
            *(__half*)(bh_ + sw128(d * 128 + tc * 2)) = __float2half_rn(vs[j]);
        }
    }
}

// ---------------------------------------------------------------------------
// fused_attn (unchanged from R14, passing @ 225us):
// 128 threads (4 warps, 2M x 2N), 64 q-rows/CTA, grid (S/64, H). 48KB smem.
// ---------------------------------------------------------------------------
__global__ __launch_bounds__(128) void fused_attn(
    const float* __restrict__ rel, float* __restrict__ wout)
{
    extern __shared__ char dyn[];
    const uint32_t smb = smem_u32(dyn);
    const uint32_t vbuf = smb + 32768;

    const int tid = threadIdx.x;
    const int warp = tid >> 5, lane = tid & 31;
    const int wm = warp >> 1, wn = warp & 1;
    const int g = lane >> 2, t4 = lane & 3;
    const int h = blockIdx.y;
    const int row0 = blockIdx.x * 64;
    const int qc0 = h * HD;

    const int rA = row0 + wm * 32 + g;
    const int rB = rA + 8, rC = rA + 16, rD = rA + 24;

    uint32_t qh[4][2][4], ql[4][2][4];
#pragma unroll
    for (int ks = 0; ks < 4; ks++) {
        int c = qc0 + ks * 16 + 2 * t4;
#pragma unroll
        for (int blk = 0; blk < 2; blk++) {
            int ra = rA + blk * 16, rb = rB + blk * 16;
            float2 x00 = *(const float2*)&g_q[(size_t)ra * E + c];
            float2 x10 = *(const float2*)&g_q[(size_t)rb * E + c];
            float2 x01 = *(const float2*)&g_q[(size_t)ra * E + c + 8];
            float2 x11 = *(const float2*)&g_q[(size_t)rb * E + c + 8];
            split2h(x00.x * SCALE, x00.y * SCALE, qh[ks][blk][0], ql[ks][blk][0]);
            split2h(x10.x * SCALE, x10.y * SCALE, qh[ks][blk][1], ql[ks][blk][1]);
            split2h(x01.x * SCALE, x01.y * SCALE, qh[ks][blk][2], ql[ks][blk][2]);
            split2h(x11.x * SCALE, x11.y * SCALE, qh[ks][blk][3], ql[ks][blk][3]);
        }
    }

    const int bnp = (lane & 7) + ((lane >> 4) << 3);
    const int bkq = ((lane >> 3) & 1) * 8;
    const int tco = wn * 64;

    const char* ksrc = g_kt + ((size_t)h * NT) * 16384;
    const char* vsrc = g_vt + ((size_t)h * NT) * 16384;

    float lA = 0.f, lB = 0.f, lC = 0.f, lD = 0.f;

    // ===================== PASS 1: row sums =====================
#pragma unroll
    for (int i = 0; i < 8; i++) {
        uint32_t off = (uint32_t)(tid + i * 128) * 16;
        CP16(smb + off, ksrc + off);
    }
    CP_COMMIT();

#pragma unroll 1
    for (int t = 0; t < NT; t++) {
        CP_WAIT(0);
        __syncthreads();
        if (t + 1 < NT) {
            const char* src = ksrc + (size_t)(t + 1) * 16384;
            uint32_t dst = smb + ((t + 1) & 1) * 16384;
#pragma unroll
            for (int i = 0; i < 8; i++) {
                uint32_t off = (uint32_t)(tid + i * 128) * 16;
                CP16(dst + off, src + off);
            }
            CP_COMMIT();
        }
        const uint32_t uSkh = smb + (t & 1) * 16384;

#pragma unroll 1
        for (int ch = 0; ch < 4; ch++) {
            int tc = tco + ch * 16;
            int cg = t * 128 + tc + 2 * t4;
            float2 r00 = *(const float2*)&rel[(size_t)rA * S + cg];
            float2 r01 = *(const float2*)&rel[(size_t)rA * S + cg + 8];
            float2 r10 = *(const float2*)&rel[(size_t)rB * S + cg];
            float2 r11 = *(const float2*)&rel[(size_t)rB * S + cg + 8];
            float2 r20 = *(const float2*)&rel[(size_t)rC * S + cg];
            float2 r21 = *(const float2*)&rel[(size_t)rC * S + cg + 8];
            float2 r30 = *(const float2*)&rel[(size_t)rD * S + cg];
            float2 r31 = *(const float2*)&rel[(size_t)rD * S + cg + 8];

            float cs[2][2][4];
#pragma unroll
            for (int i = 0; i < 2; i++)
#pragma unroll
                for (int j = 0; j < 2; j++)
#pragma unroll
                    for (int q2 = 0; q2 < 4; q2++) cs[i][j][q2] = 0.f;

            int brow = tc + bnp;
#pragma unroll
            for (int ks = 0; ks < 4; ks++) {
                uint32_t bh[4];
                ldsm4(bh, uSkh + sw128((uint32_t)(brow * 128 + (ks * 16 + bkq) * 2)));
                mma_h32(cs[0][0], qh[ks][0], bh + 0);
                mma_h32(cs[0][1], qh[ks][0], bh + 2);
                mma_h32(cs[1][0], qh[ks][1], bh + 0);
                mma_h32(cs[1][1], qh[ks][1], bh + 2);
            }
            lA += __expf(cs[0][0][0] + r00.x * SCALE) + __expf(cs[0][0][1] + r00.y * SCALE) +
                  __expf(cs[0][1][0] + r01.x * SCALE) + __expf(cs[0][1][1] + r01.y * SCALE);
            lB += __expf(cs[0][0][2] + r10.x * SCALE) + __expf(cs[0][0][3] + r10.y * SCALE) +
                  __expf(cs[0][1][2] + r11.x * SCALE) + __expf(cs[0][1][3] + r11.y * SCALE);
            lC += __expf(cs[1][0][0] + r20.x * SCALE) + __expf(cs[1][0][1] + r20.y * SCALE) +
                  __expf(cs[1][1][0] + r21.x * SCALE) + __expf(cs[1][1][1] + r21.y * SCALE);
            lD += __expf(cs[1][0][2] + r30.x * SCALE) + __expf(cs[1][0][3] + r30.y * SCALE) +
                  __expf(cs[1][1][2] + r31.x * SCALE) + __expf(cs[1][1][3] + r31.y * SCALE);
        }
    }

    lA += __shfl_xor_sync(0xffffffffu, lA, 1);
    lA += __shfl_xor_sync(0xffffffffu, lA, 2);
    lB += __shfl_xor_sync(0xffffffffu, lB, 1);
    lB += __shfl_xor_sync(0xffffffffu, lB, 2);
    lC += __shfl_xor_sync(0xffffffffu, lC, 1);
    lC += __shfl_xor_sync(0xffffffffu, lC, 2);
    lD += __shfl_xor_sync(0xffffffffu, lD, 1);
    lD += __shfl_xor_sync(0xffffffffu, lD, 2);

    float* sml = (float*)(dyn + 32768);
    __syncthreads();
    if (t4 == 0) {
        sml[wn * 64 + wm * 32 + g]      = lA;
        sml[wn * 64 + wm * 32 + g + 8]  = lB;
        sml[wn * 64 + wm * 32 + g + 16] = lC;
        sml[wn * 64 + wm * 32 + g + 24] = lD;
    }
    __syncthreads();
    const float invA = 1.f / (sml[wm * 32 + g]      + sml[64 + wm * 32 + g]);
    const float invB = 1.f / (sml[wm * 32 + g + 8]  + sml[64 + wm * 32 + g + 8]);
    const float invC = 1.f / (sml[wm * 32 + g + 16] + sml[64 + wm * 32 + g + 16]);
    const float invD = 1.f / (sml[wm * 32 + g + 24] + sml[64 + wm * 32 + g + 24]);
    __syncthreads();

    float o[2][8][4];
    uint32_t ox[2][8][2];
#pragma unroll
    for (int i = 0; i < 2; i++)
#pragma unroll
        for (int j = 0; j < 8; j++) {
#pragma unroll
            for (int q2 = 0; q2 < 4; q2++) o[i][j][q2] = 0.f;
            ox[i][j][0] = 0u; ox[i][j][1] = 0u;
        }

    float* wrow = wout + (size_t)h * S * S;

    // ===================== PASS 2: w + PV =====================
#pragma unroll
    for (int i = 0; i < 8; i++) {
        uint32_t off = (uint32_t)(tid + i * 128) * 16;
        CP16(smb + off, ksrc + off);
    }
    CP_COMMIT();

#pragma unroll 1
    for (int t = 0; t < NT; t++) {
        {
            const char* srcv = vsrc + (size_t)t * 16384;
#pragma unroll
            for (int i = 0; i < 8; i++) {
                uint32_t off = (uint32_t)(tid + i * 128) * 16;
                CP16(vbuf + off, srcv + off);
            }
            CP_COMMIT();
        }
        if (t + 1 < NT) {
            const char* src = ksrc + (size_t)(t + 1) * 16384;
            uint32_t dst = smb + ((t + 1) & 1) * 16384;
#pragma unroll
            for (int i = 0; i < 8; i++) {
                uint32_t off = (uint32_t)(tid + i * 128) * 16;
                CP16(dst + off, src + off);
            }
            CP_COMMIT();
        }
        if (t + 1 < NT) { CP_WAIT(1); } else { CP_WAIT(0); }
        __syncthreads();

        const uint32_t uSkh = smb + (t & 1) * 16384;

#pragma unroll 1
        for (int ch = 0; ch < 4; ch++) {
            int tc = tco + ch * 16;
            int cg = t * 128 + tc + 2 * t4;
            float2 r00 = *(const float2*)&rel[(size_t)rA * S + cg];
            float2 r01 = *(const float2*)&rel[(size_t)rA * S + cg + 8];
            float2 r10 = *(const float2*)&rel[(size_t)rB * S + cg];
            float2 r11 = *(const float2*)&rel[(size_t)rB * S + cg + 8];
            float2 r20 = *(const float2*)&rel[(size_t)rC * S + cg];
            float2 r21 = *(const float2*)&rel[(size_t)rC * S + cg + 8];
            float2 r30 = *(const float2*)&rel[(size_t)rD * S + cg];
            float2 r31 = *(const float2*)&rel[(size_t)rD * S + cg + 8];

            float cs[2][2][4];
            uint32_t cx[2][2][2];
#pragma unroll
            for (int i = 0; i < 2; i++)
#pragma unroll
                for (int j = 0; j < 2; j++) {
#pragma unroll
                    for (int q2 = 0; q2 < 4; q2++) cs[i][j][q2] = 0.f;
                    cx[i][j][0] = 0u; cx[i][j][1] = 0u;
                }

            int brow = tc + bnp;
#pragma unroll
            for (int ks = 0; ks < 4; ks++) {
                uint32_t bh[4];
                ldsm4(bh, uSkh + sw128((uint32_t)(brow * 128 + (ks * 16 + bkq) * 2)));
                mma_h32(cs[0][0], qh[ks][0], bh + 0);
                mma_h32(cs[0][1], qh[ks][0], bh + 2);
                mma_h32(cs[1][0], qh[ks][1], bh + 0);
                mma_h32(cs[1][1], qh[ks][1], bh + 2);
                mma_h16(cx[0][0], ql[ks][0], bh + 0);
                mma_h16(cx[0][1], ql[ks][0], bh + 2);
                mma_h16(cx[1][0], ql[ks][1], bh + 0);
                mma_h16(cx[1][1], ql[ks][1], bh + 2);
            }

            float2 xa0 = __half22float2(*(__half2*)&cx[0][0][0]);
            float2 xa1 = __half22float2(*(__half2*)&cx[0][1][0]);
            float2 xb0 = __half22float2(*(__half2*)&cx[0][0][1]);
            float2 xb1 = __half22float2(*(__half2*)&cx[0][1][1]);
            float2 xc0 = __half22float2(*(__half2*)&cx[1][0][0]);
            float2 xc1 = __half22float2(*(__half2*)&cx[1][1][0]);
            float2 xd0 = __half22float2(*(__half2*)&cx[1][0][1]);
            float2 xd1 = __half22float2(*(__half2*)&cx[1][1][1]);

            float wA0 = __expf(cs[0][0][0] + xa0.x + r00.x * SCALE) * invA;
            float wA1 = __expf(cs[0][0][1] + xa0.y + r00.y * SCALE) * invA;
            float wA2 = __expf(cs[0][1][0] + xa1.x + r01.x * SCALE) * invA;
            float wA3 = __expf(cs[0][1][1] + xa1.y + r01.y * SCALE) * invA;
            float wB0 = __expf(cs[0][0][2] + xb0.x + r10.x * SCALE) * invB;
            float wB1 = __expf(cs[0][0][3] + xb0.y + r10.y * SCALE) * invB;
            float wB2 = __expf(cs[0][1][2] + xb1.x + r11.x * SCALE) * invB;
            float wB3 = __expf(cs[0][1][3] + xb1.y + r11.y * SCALE) * invB;
            float wC0 = __expf(cs[1][0][0] + xc0.x + r20.x * SCALE) * invC;
            float wC1 = __expf(cs[1][0][1] + xc0.y + r20.y * SCALE) * invC;
            float wC2 = __expf(cs[1][1][0] + xc1.x + r21.x * SCALE) * invC;
            float wC3 = __expf(cs[1][1][1] + xc1.y + r21.y * SCALE) * invC;
            float wD0 = __expf(cs[1][0][2] + xd0.x + r30.x * SCALE) * invD;
            float wD1 = __expf(cs[1][0][3] + xd0.y + r30.y * SCALE) * invD;
            float wD2 = __expf(cs[1][1][2] + xd1.x + r31.x * SCALE) * invD;
            float wD3 = __expf(cs[1][1][3] + xd1.y + r31.y * SCALE) * invD;

            *(float2*)&wrow[(size_t)rA * S + cg]     = make_float2(wA0, wA1);
            *(float2*)&wrow[(size_t)rA * S + cg + 8] = make_float2(wA2, wA3);
            *(float2*)&wrow[(size_t)rB * S + cg]     = make_float2(wB0, wB1);
            *(float2*)&wrow[(size_t)rB * S + cg + 8] = make_float2(wB2, wB3);
            *(float2*)&wrow[(size_t)rC * S + cg]     = make_float2(wC0, wC1);
            *(float2*)&wrow[(size_t)rC * S + cg + 8] = make_float2(wC2, wC3);
            *(float2*)&wrow[(size_t)rD * S + cg]     = make_float2(wD0, wD1);
            *(float2*)&wrow[(size_t)rD * S + cg + 8] = make_float2(wD2, wD3);

            uint32_t ah0[4], al0[4], ah1[4], al1[4];
            split2h(wA0, wA1, ah0[0], al0[0]);
            split2h(wB0, wB1, ah0[1], al0[1]);
            split2h(wA2, wA3, ah0[2], al0[2]);
            split2h(wB2, wB3, ah0[3], al0[3]);
            split2h(wC0, wC1, ah1[0], al1[0]);
            split2h(wD0, wD1, ah1[1], al1[1]);
            split2h(wC2, wC3, ah1[2], al1[2]);
            split2h(wD2, wD3, ah1[3], al1[3]);

            int sub = tc >> 6;
            uint32_t cb = (uint32_t)(((tc & 63) + bkq) * 2);
#pragma unroll
            for (int jd = 0; jd < 4; jd++) {
                int dn = jd * 16 + bnp;
                uint32_t vh[4];
                ldsm4(vh, vbuf + sub * 8192 + sw128((uint32_t)(dn * 128 + cb)));
                mma_h32(o[0][jd * 2 + 0], ah0, vh + 0);
                mma_h32(o[0][jd * 2 + 1], ah0, vh + 2);
                mma_h32(o[1][jd * 2 + 0], ah1, vh + 0);
                mma_h32(o[1][jd * 2 + 1], ah1, vh + 2);
                mma_h16(ox[0][jd * 2 + 0], al0, vh + 0);
                mma_h16(ox[0][jd * 2 + 1], al0, vh + 2);
                mma_h16(ox[1][jd * 2 + 0], al1, vh + 0);
                mma_h16(ox[1][jd * 2 + 1], al1, vh + 2);
            }
        }
        __syncthreads();
    }

    // epilogue: combine PV partials across N-warps
    float of[2][8][4];
#pragma unroll
    for (int i = 0; i < 2; i++)
#pragma unroll
        for (int j = 0; j < 8; j++) {
            float2 cl = __half22float2(*(__half2*)&ox[i][j][0]);
            float2 ch2 = __half22float2(*(__half2*)&ox[i][j][1]);
            of[i][j][0] = o[i][j][0] + cl.x;
            of[i][j][1] = o[i][j][1] + cl.y;
            of[i][j][2] = o[i][j][2] + ch2.x;
            of[i][j][3] = o[i][j][3] + ch2.y;
        }

    float* red = (float*)dyn;
    __syncthreads();
    if (wn == 0) {
#pragma unroll
        for (int i = 0; i < 2; i++)
#pragma unroll
            for (int j = 0; j < 8; j++) {
                int r = wm * 32 + i * 16 + g;
                int c = j * 8 + 2 * t4;
                *(float2*)&red[r * 64 + c] = make_float2(of[i][j][0], of[i][j][1]);
                *(float2*)&red[(r + 8) * 64 + c] = make_float2(of[i][j][2], of[i][j][3]);
            }
    }
    __syncthreads();
    if (wn == 1) {
#pragma unroll
        for (int i = 0; i < 2; i++)
#pragma unroll
            for (int j = 0; j < 8; j++) {
                int r = wm * 32 + i * 16 + g;
                int c = j * 8 + 2 * t4;
                float2 p0 = *(const float2*)&red[r * 64 + c];
                float2 p1 = *(const float2*)&red[(r + 8) * 64 + c];
                *(float2*)&g_attn[(size_t)(row0 + r) * E + qc0 + c] =
                    make_float2(of[i][j][0] + p0.x, of[i][j][1] + p0.y);
                *(float2*)&g_attn[(size_t)(row0 + r + 8) * E + qc0 + c] =
                    make_float2(of[i][j][2] + p1.x, of[i][j][3] + p1.y);
            }
    }
}

// ---------------------------------------------------------------------------
// Launch.  fused_attn must be launch index 3 (ncu capture).
// ---------------------------------------------------------------------------
extern "C" void kernel_launch(void* const* d_in, const int* in_sizes, int n_in,
                              void* d_out, int out_size)
{
    (void)in_sizes; (void)n_in; (void)out_size;
    const float* query = (const float*)d_in[0];
    const float* key   = (const float*)d_in[1];
    const float* value = (const float*)d_in[2];
    const float* sim   = (const float*)d_in[3];
    const float* Wq    = (const float*)d_in[4];
    const float* bq    = (const float*)d_in[5];
    const float* Wk    = (const float*)d_in[6];
    const float* bk    = (const float*)d_in[7];
    const float* Wv    = (const float*)d_in[8];
    const float* bv    = (const float*)d_in[9];
    const float* Wo    = (const float*)d_in[10];
    const float* bo    = (const float*)d_in[11];

    float* out = (float*)d_out;                 // [S,E]
    float* w   = out + (size_t)S * E;           // [H,S,S]

    float *grel, *gattn;
    cudaGetSymbolAddress((void**)&grel,  g_rel);
    cudaGetSymbolAddress((void**)&gattn, g_attn);

    static int attr_done = 0;
    if (!attr_done) {
        cudaFuncSetAttribute(fused_attn,
                             cudaFuncAttributeMaxDynamicSharedMemorySize, 49152);
        attr_done = 1;
    }

    dim3 blk(256);

    // 0: q/k/v projections (batched)
    proj_qkv<<<dim3(E / 64, S / 128, 3), blk>>>(query, key, value,
                                                Wq, Wk, Wv, bq, bk, bv);

    // 1: pre-split k/v into fp16 hi-only swizzled tile images
    prep_kv<<<dim3(NT, H), dim3(128)>>>();

    // 2: rel = sim @ sim^T
    tc_gemm<<<dim3(S / 64, S / 128), blk>>>(sim, sim, grel, HD, HD, HD, S, nullptr, 0);

    // 3: fused attention  (<-- ncu capture index)
    fused_attn<<<dim3(S / 64, H), dim3(128), 49152>>>(grel, w);

    // 4: out = attn @ Wo^T + bo
    tc_gemm<<<dim3(E / 64, S / 128), blk>>>(gattn, Wo, out, E, E, E, E, bo, 0);
}

// round 16
// speedup vs baseline: 1.8747x; 1.1557x over previous
#include <cuda_runtime.h>
#include <cuda_bf16.h>
#include <cuda_fp16.h>
#include <cstdint>
#include <cstddef>

#define S 2048
#define E 1024
#define H 16
#define HD 64
#define NT 16
#define SCALE 0.125f

// fp32 scratch
__device__ float g_q[S * E];
__device__ float g_k[S * E];
__device__ float g_v[S * E];
__device__ float g_rel[S * S];
__device__ float g_attn[S * E];
// fp16 hi-only pre-swizzled k/v tile images (fused), 16KB/tile
__device__ __align__(128) char g_kt[H * NT * 16384];
__device__ __align__(128) char g_vt[H * NT * 16384];
// fp16 hi/lo pre-swizzled GEMM operand images
__device__ __align__(128) char g_xi[3u * 8388608u];     // query/key/value A-images
__device__ __align__(128) char g_wi[4u * 4194304u];     // Wq/Wk/Wv/Wo B-images
__device__ __align__(128) char g_simAi[524288];          // sim as A (16rb x 2kc x 16K)
__device__ __align__(128) char g_simBi[524288];          // sim as B (32cb x 2kc x 8K)
__device__ __align__(128) char g_atti[8388608];          // attn A-image

// ---------------------------------------------------------------------------
// Helpers
// ---------------------------------------------------------------------------
__device__ __forceinline__ uint32_t smem_u32(const void* p) {
    uint32_t a;
    asm("{ .reg .u64 t; cvta.to.shared.u64 t, %1; cvt.u32.u64 %0, t; }"
        : "=r"(a) : "l"(p));
    return a;
}

__device__ __forceinline__ uint32_t sw128(uint32_t off) {
    return off ^ ((off >> 3) & 0x70);
}

__device__ __forceinline__ void ldsm4(uint32_t* r, uint32_t addr) {
    asm volatile("ldmatrix.sync.aligned.m8n8.x4.shared.b16 {%0,%1,%2,%3}, [%4];"
                 : "=r"(r[0]), "=r"(r[1]), "=r"(r[2]), "=r"(r[3]) : "r"(addr));
}

__device__ __forceinline__ void mma_h32(float* c, const uint32_t* a, const uint32_t* b) {
    asm volatile(
        "mma.sync.aligned.m16n8k16.row.col.f32.f16.f16.f32 "
        "{%0,%1,%2,%3}, {%4,%5,%6,%7}, {%8,%9}, {%0,%1,%2,%3};"
        : "+f"(c[0]), "+f"(c[1]), "+f"(c[2]), "+f"(c[3])
        : "r"(a[0]), "r"(a[1]), "r"(a[2]), "r"(a[3]), "r"(b[0]), "r"(b[1]));
}

__device__ __forceinline__ void mma_h16(uint32_t* c, const uint32_t* a, const uint32_t* b) {
    asm volatile(
        "mma.sync.aligned.m16n8k16.row.col.f16.f16.f16.f16 "
        "{%0,%1}, {%2,%3,%4,%5}, {%6,%7}, {%0,%1};"
        : "+r"(c[0]), "+r"(c[1])
        : "r"(a[0]), "r"(a[1]), "r"(a[2]), "r"(a[3]), "r"(b[0]), "r"(b[1]));
}

__device__ __forceinline__ void split2h(float x, float y, uint32_t& hi, uint32_t& lo) {
    __half2 hp = __floats2half2_rn(x, y);
    float rx = x - __half2float(__low2half(hp));
    float ry = y - __half2float(__high2half(hp));
    __half2 lp = __floats2half2_rn(rx, ry);
    hi = *(uint32_t*)&hp;
    lo = *(uint32_t*)&lp;
}

// fp16 split-store into SW128 row image: [hi 32 fp16 | lo 32 fp16] (128B rows)
__device__ __forceinline__ void split_store_h(char* base, int row, int col2,
                                              float x0, float x1) {
    uint32_t hi, lo;
    split2h(x0, x1, hi, lo);
    *(uint32_t*)(base + sw128(row * 128 + col2 * 2)) = hi;
    *(uint32_t*)(base + sw128(row * 128 + 64 + col2 * 2)) = lo;
}

#define CP16(dst, src) \
    asm volatile("cp.async.cg.shared.global [%0], [%1], 16;" :: "r"(dst), "l"(src))
#define CP_COMMIT() asm volatile("cp.async.commit_group;" ::: "memory")
#define CP_WAIT(n)  asm volatile("cp.async.wait_group %0;" :: "n"(n) : "memory")

// ---------------------------------------------------------------------------
// prep_all: convert operands to fp16 hi/lo swizzled tile images.
// grid (32, 32, 9), 256 threads.  z: 0-2 q/k/v A-img, 3-6 W B-img,
// 7 sim A-img, 8 sim B-img.
// ---------------------------------------------------------------------------
__global__ __launch_bounds__(256) void prep_all(
    const float* __restrict__ q, const float* __restrict__ k,
    const float* __restrict__ v,
    const float* __restrict__ Wq, const float* __restrict__ Wk,
    const float* __restrict__ Wv, const float* __restrict__ Wo,
    const float* __restrict__ sim)
{
    const int kc = blockIdx.x, rb = blockIdx.y, z = blockIdx.z;
    const float* src;
    char* dst;
    int ld, numKC, numRB, rows;
    if (z < 3) {
        src = (z == 0) ? q : (z == 1) ? k : v;
        ld = E; numKC = 32; numRB = 16; rows = 128;
        dst = g_xi + (size_t)z * 8388608u + ((size_t)rb * 32 + kc) * 16384;
    } else if (z < 7) {
        src = (z == 3) ? Wq : (z == 4) ? Wk : (z == 5) ? Wv : Wo;
        ld = E; numKC = 32; numRB = 16; rows = 64;
        dst = g_wi + (size_t)(z - 3) * 4194304u + ((size_t)rb * 32 + kc) * 8192;
    } else if (z == 7) {
        src = sim; ld = 64; numKC = 2; numRB = 16; rows = 128;
        dst = g_simAi + ((size_t)rb * 2 + kc) * 16384;
    } else {
        src = sim; ld = 64; numKC = 2; numRB = 32; rows = 64;
        dst = g_simBi + ((size_t)rb * 2 + kc) * 8192;
    }
    if (kc >= numKC || rb >= numRB) return;

    const int iters = rows * 16 / 256;
    const int tid = threadIdx.x;
    for (int s = 0; s < iters; s++) {
        int idx = s * 256 + tid;
        int r = idx >> 4, p = idx & 15;
        float2 val = *(const float2*)&src[(size_t)(rb * rows + r) * ld + kc * 32 + 2 * p];
        split_store_h(dst, r, 2 * p, val.x, val.y);
    }
}

// ---------------------------------------------------------------------------
// prep_attn: g_attn fp32 -> A-image. grid (32, 16), 256 threads.
// ---------------------------------------------------------------------------
__global__ __launch_bounds__(256) void prep_attn()
{
    const int kc = blockIdx.x, rb = blockIdx.y;
    char* dst = g_atti + ((size_t)rb * 32 + kc) * 16384;
    const int tid = threadIdx.x;
#pragma unroll
    for (int s = 0; s < 8; s++) {
        int idx = s * 256 + tid;
        int r = idx >> 4, p = idx & 15;
        float2 val = *(const float2*)&g_attn[(size_t)(rb * 128 + r) * E + kc * 32 + 2 * p];
        split_store_h(dst, r, 2 * p, val.x, val.y);
    }
}

// ---------------------------------------------------------------------------
// Image GEMM body: cp.async double-buffered, fp16 split (hh f32acc + cross f16acc)
// BM=128, BN=64, BK=32, 256 threads (8 warps = 4M x 2N, m32 x n32 each).
// ---------------------------------------------------------------------------
__device__ __forceinline__ void gemm_img_body(
    const char* __restrict__ Ai, const char* __restrict__ Bi,
    float* __restrict__ C, int numKC, int ldc, const float* __restrict__ bias,
    int row0, int col0)
{
    __shared__ __align__(128) char smA[2][16384];
    __shared__ __align__(128) char smB[2][8192];

    const int tid = threadIdx.x;
    const int warp = tid >> 5, lane = tid & 31;
    const int wm0 = (warp >> 1) * 32;
    const int wn0 = (warp & 1) * 32;

    const uint32_t sAb[2] = {smem_u32(smA[0]), smem_u32(smA[1])};
    const uint32_t sBb[2] = {smem_u32(smB[0]), smem_u32(smB[1])};

    float c[2][4][4];
    uint32_t cx[2][4][2];
#pragma unroll
    for (int i = 0; i < 2; i++)
#pragma unroll
        for (int j = 0; j < 4; j++) {
#pragma unroll
            for (int t = 0; t < 4; t++) c[i][j][t] = 0.f;
            cx[i][j][0] = 0u; cx[i][j][1] = 0u;
        }

    const int arow = wm0 + (lane & 15);
    const int acolq = (lane >> 4) * 8;
    const int bn = wn0 + (lane & 7) + ((lane >> 4) << 3);
    const int bkq = ((lane >> 3) & 1) * 8;

    // prologue: stage chunk 0
#pragma unroll
    for (int i = 0; i < 4; i++) {
        uint32_t off = (uint32_t)(tid + i * 256) * 16;
        CP16(sAb[0] + off, Ai + off);
    }
#pragma unroll
    for (int i = 0; i < 2; i++) {
        uint32_t off = (uint32_t)(tid + i * 256) * 16;
        CP16(sBb[0] + off, Bi + off);
    }
    CP_COMMIT();

    for (int kc = 0; kc < numKC; kc++) {
        if (kc + 1 < numKC) {
            const char* an = Ai + (size_t)(kc + 1) * 16384;
            const char* bns = Bi + (size_t)(kc + 1) * 8192;
            uint32_t dA = sAb[(kc + 1) & 1];
            uint32_t dB = sBb[(kc + 1) & 1];
#pragma unroll
            for (int i = 0; i < 4; i++) {
                uint32_t off = (uint32_t)(tid + i * 256) * 16;
                CP16(dA + off, an + off);
            }
#pragma unroll
            for (int i = 0; i < 2; i++) {
                uint32_t off = (uint32_t)(tid + i * 256) * 16;
                CP16(dB + off, bns + off);
            }
            CP_COMMIT();
            CP_WAIT(1);
        } else {
            CP_WAIT(0);
        }
        __syncthreads();

        const uint32_t sA = sAb[kc & 1];
        const uint32_t sB = sBb[kc & 1];

#pragma unroll
        for (int ks = 0; ks < 2; ks++) {
            uint32_t ca = (uint32_t)((ks * 16 + acolq) * 2);
            uint32_t ah0[4], ah1[4], al0[4], al1[4];
            ldsm4(ah0, sA + sw128((uint32_t)(arow * 128) + ca));
            ldsm4(ah1, sA + sw128((uint32_t)((arow + 16) * 128) + ca));
            ldsm4(al0, sA + sw128((uint32_t)(arow * 128 + 64) + ca));
            ldsm4(al1, sA + sw128((uint32_t)((arow + 16) * 128 + 64) + ca));

            uint32_t cb = (uint32_t)((ks * 16 + bkq) * 2);
            uint32_t bh[2][4], bl[2][4];
#pragma unroll
            for (int j2 = 0; j2 < 2; j2++) {
                ldsm4(bh[j2], sB + sw128((uint32_t)((bn + j2 * 16) * 128) + cb));
                ldsm4(bl[j2], sB + sw128((uint32_t)((bn + j2 * 16) * 128 + 64) + cb));
            }
#pragma unroll
            for (int i = 0; i < 2; i++) {
                const uint32_t* aih = (i == 0) ? ah0 : ah1;
                const uint32_t* ail = (i == 0) ? al0 : al1;
#pragma unroll
                for (int j = 0; j < 4; j++) {
                    const uint32_t* bhf = &bh[j >> 1][(j & 1) * 2];
                    const uint32_t* blf = &bl[j >> 1][(j & 1) * 2];
                    mma_h32(c[i][j], aih, bhf);
                    mma_h16(cx[i][j], aih, blf);
                    mma_h16(cx[i][j], ail, bhf);
                }
            }
        }
        __syncthreads();
    }

    const int g = lane >> 2, t4 = lane & 3;
#pragma unroll
    for (int i = 0; i < 2; i++) {
#pragma unroll
        for (int j = 0; j < 4; j++) {
            int gr0 = row0 + wm0 + i * 16 + g;
            int gc = col0 + wn0 + j * 8 + t4 * 2;
            float2 x0 = __half22float2(*(__half2*)&cx[i][j][0]);
            float2 x1 = __half22float2(*(__half2*)&cx[i][j][1]);
            float v0 = c[i][j][0] + x0.x, v1 = c[i][j][1] + x0.y;
            float v2 = c[i][j][2] + x1.x, v3 = c[i][j][3] + x1.y;
            if (bias) {
                float2 bv = *(const float2*)&bias[gc];
                v0 += bv.x; v1 += bv.y; v2 += bv.x; v3 += bv.y;
            }
            *(float2*)&C[(size_t)gr0 * ldc + gc] = make_float2(v0, v1);
            *(float2*)&C[(size_t)(gr0 + 8) * ldc + gc] = make_float2(v2, v3);
        }
    }
}

__global__ __launch_bounds__(256) void tc_gemm_img(
    const char* __restrict__ Ai, const char* __restrict__ Bi,
    float* __restrict__ C, int numKC, int ldc, const float* __restrict__ bias)
{
    gemm_img_body(Ai + ((size_t)blockIdx.y * numKC) * 16384,
                  Bi + ((size_t)blockIdx.x * numKC) * 8192,
                  C, numKC, ldc, bias, blockIdx.y * 128, blockIdx.x * 64);
}

__global__ __launch_bounds__(256) void proj_img(
    const float* __restrict__ bq, const float* __restrict__ bk,
    const float* __restrict__ bv)
{
    const int z = blockIdx.z;
    const float* bias = (z == 0) ? bq : (z == 1) ? bk : bv;
    float* C = (z == 0) ? g_q : (z == 1) ? g_k : g_v;
    gemm_img_body(g_xi + (size_t)z * 8388608u + ((size_t)blockIdx.y * 32) * 16384,
                  g_wi + (size_t)z * 4194304u + ((size_t)blockIdx.x * 32) * 8192,
                  C, 32, E, bias, blockIdx.y * 128, blockIdx.x * 64);
}

// ---------------------------------------------------------------------------
// prep_kv (unchanged): fp16 HI-only pre-swizzled 16KB tile images.
// ---------------------------------------------------------------------------
__global__ __launch_bounds__(128) void prep_kv()
{
    const int tid = threadIdx.x;
    const int t0 = blockIdx.x * 128;
    const int h = blockIdx.y;
    const int qc0 = h * HD;
    char* kimg = g_kt + ((size_t)(h * NT + blockIdx.x)) * 16384;
    char* vimg = g_vt + ((size_t)(h * NT + blockIdx.x)) * 16384;

    const int lr = tid >> 4, lp = tid & 15;
#pragma unroll 4
    for (int s = 0; s < 16; s++) {
        int tr = s * 8 + lr;
        float4 kv = *(const float4*)&g_k[(size_t)(t0 + tr) * E + qc0 + 4 * lp];
        __half2 h01 = __floats2half2_rn(kv.x, kv.y);
        __half2 h23 = __floats2half2_rn(kv.z, kv.w);
        *(uint2*)(kimg + sw128(tr * 128 + 8 * lp)) =
            make_uint2(*(uint32_t*)&h01, *(uint32_t*)&h23);

        float4 vv = *(const float4*)&g_v[(size_t)(t0 + tr) * E + qc0 + 4 * lp];
        int sub = tr >> 6, tc = tr & 63;
        char* bh_ = vimg + sub * 8192;
        float vs[4] = {vv.x, vv.y, vv.z, vv.w};
#pragma unroll
        for (int j = 0; j < 4; j++) {
            int d = 4 * lp + j;
            *(__half*)(bh_ + sw128(d * 128 + tc * 2)) = __float2half_rn(vs[j]);
        }
    }
}

// ---------------------------------------------------------------------------
// fused_attn (unchanged from R15, passing):
// 128 threads (4 warps, 2M x 2N), 64 q-rows/CTA, grid (S/64, H). 48KB smem.
// ---------------------------------------------------------------------------
__global__ __launch_bounds__(128) void fused_attn(
    const float* __restrict__ rel, float* __restrict__ wout)
{
    extern __shared__ char dyn[];
    const uint32_t smb = smem_u32(dyn);
    const uint32_t vbuf = smb + 32768;

    const int tid = threadIdx.x;
    const int warp = tid >> 5, lane = tid & 31;
    const int wm = warp >> 1, wn = warp & 1;
    const int g = lane >> 2, t4 = lane & 3;
    const int h = blockIdx.y;
    const int row0 = blockIdx.x * 64;
    const int qc0 = h * HD;

    const int rA = row0 + wm * 32 + g;
    const int rB = rA + 8, rC = rA + 16, rD = rA + 24;

    uint32_t qh[4][2][4], ql[4][2][4];
#pragma unroll
    for (int ks = 0; ks < 4; ks++) {
        int c = qc0 + ks * 16 + 2 * t4;
#pragma unroll
        for (int blk = 0; blk < 2; blk++) {
            int ra = rA + blk * 16, rb = rB + blk * 16;
            float2 x00 = *(const float2*)&g_q[(size_t)ra * E + c];
            float2 x10 = *(const float2*)&g_q[(size_t)rb * E + c];
            float2 x01 = *(const float2*)&g_q[(size_t)ra * E + c + 8];
            float2 x11 = *(const float2*)&g_q[(size_t)rb * E + c + 8];
            split2h(x00.x * SCALE, x00.y * SCALE, qh[ks][blk][0], ql[ks][blk][0]);
            split2h(x10.x * SCALE, x10.y * SCALE, qh[ks][blk][1], ql[ks][blk][1]);
            split2h(x01.x * SCALE, x01.y * SCALE, qh[ks][blk][2], ql[ks][blk][2]);
            split2h(x11.x * SCALE, x11.y * SCALE, qh[ks][blk][3], ql[ks][blk][3]);
        }
    }

    const int bnp = (lane & 7) + ((lane >> 4) << 3);
    const int bkq = ((lane >> 3) & 1) * 8;
    const int tco = wn * 64;

    const char* ksrc = g_kt + ((size_t)h * NT) * 16384;
    const char* vsrc = g_vt + ((size_t)h * NT) * 16384;

    float lA = 0.f, lB = 0.f, lC = 0.f, lD = 0.f;

    // PASS 1
#pragma unroll
    for (int i = 0; i < 8; i++) {
        uint32_t off = (uint32_t)(tid + i * 128) * 16;
        CP16(smb + off, ksrc + off);
    }
    CP_COMMIT();

#pragma unroll 1
    for (int t = 0; t < NT; t++) {
        CP_WAIT(0);
        __syncthreads();
        if (t + 1 < NT) {
            const char* src = ksrc + (size_t)(t + 1) * 16384;
            uint32_t dst = smb + ((t + 1) & 1) * 16384;
#pragma unroll
            for (int i = 0; i < 8; i++) {
                uint32_t off = (uint32_t)(tid + i * 128) * 16;
                CP16(dst + off, src + off);
            }
            CP_COMMIT();
        }
        const uint32_t uSkh = smb + (t & 1) * 16384;

#pragma unroll 1
        for (int ch = 0; ch < 4; ch++) {
            int tc = tco + ch * 16;
            int cg = t * 128 + tc + 2 * t4;
            float2 r00 = *(const float2*)&rel[(size_t)rA * S + cg];
            float2 r01 = *(const float2*)&rel[(size_t)rA * S + cg + 8];
            float2 r10 = *(const float2*)&rel[(size_t)rB * S + cg];
            float2 r11 = *(const float2*)&rel[(size_t)rB * S + cg + 8];
            float2 r20 = *(const float2*)&rel[(size_t)rC * S + cg];
            float2 r21 = *(const float2*)&rel[(size_t)rC * S + cg + 8];
            float2 r30 = *(const float2*)&rel[(size_t)rD * S + cg];
            float2 r31 = *(const float2*)&rel[(size_t)rD * S + cg + 8];

            float cs[2][2][4];
#pragma unroll
            for (int i = 0; i < 2; i++)
#pragma unroll
                for (int j = 0; j < 2; j++)
#pragma unroll
                    for (int q2 = 0; q2 < 4; q2++) cs[i][j][q2] = 0.f;

            int brow = tc + bnp;
#pragma unroll
            for (int ks = 0; ks < 4; ks++) {
                uint32_t bh[4];
                ldsm4(bh, uSkh + sw128((uint32_t)(brow * 128 + (ks * 16 + bkq) * 2)));
                mma_h32(cs[0][0], qh[ks][0], bh + 0);
                mma_h32(cs[0][1], qh[ks][0], bh + 2);
                mma_h32(cs[1][0], qh[ks][1], bh + 0);
                mma_h32(cs[1][1], qh[ks][1], bh + 2);
            }
            lA += __expf(cs[0][0][0] + r00.x * SCALE) + __expf(cs[0][0][1] + r00.y * SCALE) +
                  __expf(cs[0][1][0] + r01.x * SCALE) + __expf(cs[0][1][1] + r01.y * SCALE);
            lB += __expf(cs[0][0][2] + r10.x * SCALE) + __expf(cs[0][0][3] + r10.y * SCALE) +
                  __expf(cs[0][1][2] + r11.x * SCALE) + __expf(cs[0][1][3] + r11.y * SCALE);
            lC += __expf(cs[1][0][0] + r20.x * SCALE) + __expf(cs[1][0][1] + r20.y * SCALE) +
                  __expf(cs[1][1][0] + r21.x * SCALE) + __expf(cs[1][1][1] + r21.y * SCALE);
            lD += __expf(cs[1][0][2] + r30.x * SCALE) + __expf(cs[1][0][3] + r30.y * SCALE) +
                  __expf(cs[1][1][2] + r31.x * SCALE) + __expf(cs[1][1][3] + r31.y * SCALE);
        }
    }

    lA += __shfl_xor_sync(0xffffffffu, lA, 1);
    lA += __shfl_xor_sync(0xffffffffu, lA, 2);
    lB += __shfl_xor_sync(0xffffffffu, lB, 1);
    lB += __shfl_xor_sync(0xffffffffu, lB, 2);
    lC += __shfl_xor_sync(0xffffffffu, lC, 1);
    lC += __shfl_xor_sync(0xffffffffu, lC, 2);
    lD += __shfl_xor_sync(0xffffffffu, lD, 1);
    lD += __shfl_xor_sync(0xffffffffu, lD, 2);

    float* sml = (float*)(dyn + 32768);
    __syncthreads();
    if (t4 == 0) {
        sml[wn * 64 + wm * 32 + g]      = lA;
        sml[wn * 64 + wm * 32 + g + 8]  = lB;
        sml[wn * 64 + wm * 32 + g + 16] = lC;
        sml[wn * 64 + wm * 32 + g + 24] = lD;
    }
    __syncthreads();
    const float invA = 1.f / (sml[wm * 32 + g]      + sml[64 + wm * 32 + g]);
    const float invB = 1.f / (sml[wm * 32 + g + 8]  + sml[64 + wm * 32 + g + 8]);
    const float invC = 1.f / (sml[wm * 32 + g + 16] + sml[64 + wm * 32 + g + 16]);
    const float invD = 1.f / (sml[wm * 32 + g + 24] + sml[64 + wm * 32 + g + 24]);
    __syncthreads();

    float o[2][8][4];
    uint32_t ox[2][8][2];
#pragma unroll
    for (int i = 0; i < 2; i++)
#pragma unroll
        for (int j = 0; j < 8; j++) {
#pragma unroll
            for (int q2 = 0; q2 < 4; q2++) o[i][j][q2] = 0.f;
            ox[i][j][0] = 0u; ox[i][j][1] = 0u;
        }

    float* wrow = wout + (size_t)h * S * S;

    // PASS 2
#pragma unroll
    for (int i = 0; i < 8; i++) {
        uint32_t off = (uint32_t)(tid + i * 128) * 16;
        CP16(smb + off, ksrc + off);
    }
    CP_COMMIT();

#pragma unroll 1
    for (int t = 0; t < NT; t++) {
        {
            const char* srcv = vsrc + (size_t)t * 16384;
#pragma unroll
            for (int i = 0; i < 8; i++) {
                uint32_t off = (uint32_t)(tid + i * 128) * 16;
                CP16(vbuf + off, srcv + off);
            }
            CP_COMMIT();
        }
        if (t + 1 < NT) {
            const char* src = ksrc + (size_t)(t + 1) * 16384;
            uint32_t dst = smb + ((t + 1) & 1) * 16384;
#pragma unroll
            for (int i = 0; i < 8; i++) {
                uint32_t off = (uint32_t)(tid + i * 128) * 16;
                CP16(dst + off, src + off);
            }
            CP_COMMIT();
        }
        if (t + 1 < NT) { CP_WAIT(1); } else { CP_WAIT(0); }
        __syncthreads();

        const uint32_t uSkh = smb + (t & 1) * 16384;

#pragma unroll 1
        for (int ch = 0; ch < 4; ch++) {
            int tc = tco + ch * 16;
            int cg = t * 128 + tc + 2 * t4;
            float2 r00 = *(const float2*)&rel[(size_t)rA * S + cg];
            float2 r01 = *(const float2*)&rel[(size_t)rA * S + cg + 8];
            float2 r10 = *(const float2*)&rel[(size_t)rB * S + cg];
            float2 r11 = *(const float2*)&rel[(size_t)rB * S + cg + 8];
            float2 r20 = *(const float2*)&rel[(size_t)rC * S + cg];
            float2 r21 = *(const float2*)&rel[(size_t)rC * S + cg + 8];
            float2 r30 = *(const float2*)&rel[(size_t)rD * S + cg];
            float2 r31 = *(const float2*)&rel[(size_t)rD * S + cg + 8];

            float cs[2][2][4];
            uint32_t cx[2][2][2];
#pragma unroll
            for (int i = 0; i < 2; i++)
#pragma unroll
                for (int j = 0; j < 2; j++) {
#pragma unroll
                    for (int q2 = 0; q2 < 4; q2++) cs[i][j][q2] = 0.f;
                    cx[i][j][0] = 0u; cx[i][j][1] = 0u;
                }

            int brow = tc + bnp;
#pragma unroll
            for (int ks = 0; ks < 4; ks++) {
                uint32_t bh[4];
                ldsm4(bh, uSkh + sw128((uint32_t)(brow * 128 + (ks * 16 + bkq) * 2)));
                mma_h32(cs[0][0], qh[ks][0], bh + 0);
                mma_h32(cs[0][1], qh[ks][0], bh + 2);
                mma_h32(cs[1][0], qh[ks][1], bh + 0);
                mma_h32(cs[1][1], qh[ks][1], bh + 2);
                mma_h16(cx[0][0], ql[ks][0], bh + 0);
                mma_h16(cx[0][1], ql[ks][0], bh + 2);
                mma_h16(cx[1][0], ql[ks][1], bh + 0);
                mma_h16(cx[1][1], ql[ks][1], bh + 2);
            }

            float2 xa0 = __half22float2(*(__half2*)&cx[0][0][0]);
            float2 xa1 = __half22float2(*(__half2*)&cx[0][1][0]);
            float2 xb0 = __half22float2(*(__half2*)&cx[0][0][1]);
            float2 xb1 = __half22float2(*(__half2*)&cx[0][1][1]);
            float2 xc0 = __half22float2(*(__half2*)&cx[1][0][0]);
            float2 xc1 = __half22float2(*(__half2*)&cx[1][1][0]);
            float2 xd0 = __half22float2(*(__half2*)&cx[1][0][1]);
            float2 xd1 = __half22float2(*(__half2*)&cx[1][1][1]);

            float wA0 = __expf(cs[0][0][0] + xa0.x + r00.x * SCALE) * invA;
            float wA1 = __expf(cs[0][0][1] + xa0.y + r00.y * SCALE) * invA;
            float wA2 = __expf(cs[0][1][0] + xa1.x + r01.x * SCALE) * invA;
            float wA3 = __expf(cs[0][1][1] + xa1.y + r01.y * SCALE) * invA;
            float wB0 = __expf(cs[0][0][2] + xb0.x + r10.x * SCALE) * invB;
            float wB1 = __expf(cs[0][0][3] + xb0.y + r10.y * SCALE) * invB;
            float wB2 = __expf(cs[0][1][2] + xb1.x + r11.x * SCALE) * invB;
            float wB3 = __expf(cs[0][1][3] + xb1.y + r11.y * SCALE) * invB;
            float wC0 = __expf(cs[1][0][0] + xc0.x + r20.x * SCALE) * invC;
            float wC1 = __expf(cs[1][0][1] + xc0.y + r20.y * SCALE) * invC;
            float wC2 = __expf(cs[1][1][0] + xc1.x + r21.x * SCALE) * invC;
            float wC3 = __expf(cs[1][1][1] + xc1.y + r21.y * SCALE) * invC;
            float wD0 = __expf(cs[1][0][2] + xd0.x + r30.x * SCALE) * invD;
            float wD1 = __expf(cs[1][0][3] + xd0.y + r30.y * SCALE) * invD;
            float wD2 = __expf(cs[1][1][2] + xd1.x + r31.x * SCALE) * invD;
            float wD3 = __expf(cs[1][1][3] + xd1.y + r31.y * SCALE) * invD;

            *(float2*)&wrow[(size_t)rA * S + cg]     = make_float2(wA0, wA1);
            *(float2*)&wrow[(size_t)rA * S + cg + 8] = make_float2(wA2, wA3);
            *(float2*)&wrow[(size_t)rB * S + cg]     = make_float2(wB0, wB1);
            *(float2*)&wrow[(size_t)rB * S + cg + 8] = make_float2(wB2, wB3);
            *(float2*)&wrow[(size_t)rC * S + cg]     = make_float2(wC0, wC1);
            *(float2*)&wrow[(size_t)rC * S + cg + 8] = make_float2(wC2, wC3);
            *(float2*)&wrow[(size_t)rD * S + cg]     = make_float2(wD0, wD1);
            *(float2*)&wrow[(size_t)rD * S + cg + 8] = make_float2(wD2, wD3);

            uint32_t ah0[4], al0[4], ah1[4], al1[4];
            split2h(wA0, wA1, ah0[0], al0[0]);
            split2h(wB0, wB1, ah0[1], al0[1]);
            split2h(wA2, wA3, ah0[2], al0[2]);
            split2h(wB2, wB3, ah0[3], al0[3]);
            split2h(wC0, wC1, ah1[0], al1[0]);
            split2h(wD0, wD1, ah1[1], al1[1]);
            split2h(wC2, wC3, ah1[2], al1[2]);
            split2h(wD2, wD3, ah1[3], al1[3]);

            int sub = tc >> 6;
            uint32_t cb = (uint32_t)(((tc & 63) + bkq) * 2);
#pragma unroll
            for (int jd = 0; jd < 4; jd++) {
                int dn = jd * 16 + bnp;
                uint32_t vh[4];
                ldsm4(vh, vbuf + sub * 8192 + sw128((uint32_t)(dn * 128 + cb)));
                mma_h32(o[0][jd * 2 + 0], ah0, vh + 0);
                mma_h32(o[0][jd * 2 + 1], ah0, vh + 2);
                mma_h32(o[1][jd * 2 + 0], ah1, vh + 0);
                mma_h32(o[1][jd * 2 + 1], ah1, vh + 2);
                mma_h16(ox[0][jd * 2 + 0], al0, vh + 0);
                mma_h16(ox[0][jd * 2 + 1], al0, vh + 2);
                mma_h16(ox[1][jd * 2 + 0], al1, vh + 0);
                mma_h16(ox[1][jd * 2 + 1], al1, vh + 2);
            }
        }
        __syncthreads();
    }

    // epilogue: combine PV partials across N-warps
    float of[2][8][4];
#pragma unroll
    for (int i = 0; i < 2; i++)
#pragma unroll
        for (int j = 0; j < 8; j++) {
            float2 cl = __half22float2(*(__half2*)&ox[i][j][0]);
            float2 ch2 = __half22float2(*(__half2*)&ox[i][j][1]);
            of[i][j][0] = o[i][j][0] + cl.x;
            of[i][j][1] = o[i][j][1] + cl.y;
            of[i][j][2] = o[i][j][2] + ch2.x;
            of[i][j][3] = o[i][j][3] + ch2.y;
        }

    float* red = (float*)dyn;
    __syncthreads();
    if (wn == 0) {
#pragma unroll
        for (int i = 0; i < 2; i++)
#pragma unroll
            for (int j = 0; j < 8; j++) {
                int r = wm * 32 + i * 16 + g;
                int c = j * 8 + 2 * t4;
                *(float2*)&red[r * 64 + c] = make_float2(of[i][j][0], of[i][j][1]);
                *(float2*)&red[(r + 8) * 64 + c] = make_float2(of[i][j][2], of[i][j][3]);
            }
    }
    __syncthreads();
    if (wn == 1) {
#pragma unroll
        for (int i = 0; i < 2; i++)
#pragma unroll
            for (int j = 0; j < 8; j++) {
                int r = wm * 32 + i * 16 + g;
                int c = j * 8 + 2 * t4;
                float2 p0 = *(const float2*)&red[r * 64 + c];
                float2 p1 = *(const float2*)&red[(r + 8) * 64 + c];
                *(float2*)&g_attn[(size_t)(row0 + r) * E + qc0 + c] =
                    make_float2(of[i][j][0] + p0.x, of[i][j][1] + p0.y);
                *(float2*)&g_attn[(size_t)(row0 + r + 8) * E + qc0 + c] =
                    make_float2(of[i][j][2] + p1.x, of[i][j][3] + p1.y);
            }
    }
}

// ---------------------------------------------------------------------------
// Launch
// ---------------------------------------------------------------------------
extern "C" void kernel_launch(void* const* d_in, const int* in_sizes, int n_in,
                              void* d_out, int out_size)
{
    (void)in_sizes; (void)n_in; (void)out_size;
    const float* query = (const float*)d_in[0];
    const float* key   = (const float*)d_in[1];
    const float* value = (const float*)d_in[2];
    const float* sim   = (const float*)d_in[3];
    const float* bq    = (const float*)d_in[5];
    const float* bk    = (const float*)d_in[7];
    const float* bv    = (const float*)d_in[9];
    const float* Wq    = (const float*)d_in[4];
    const float* Wk    = (const float*)d_in[6];
    const float* Wv    = (const float*)d_in[8];
    const float* Wo    = (const float*)d_in[10];
    const float* bo    = (const float*)d_in[11];

    float* out = (float*)d_out;                 // [S,E]
    float* w   = out + (size_t)S * E;           // [H,S,S]

    float *grel;
    char *simAi, *simBi, *atti, *wi;
    cudaGetSymbolAddress((void**)&grel,  g_rel);
    cudaGetSymbolAddress((void**)&simAi, g_simAi);
    cudaGetSymbolAddress((void**)&simBi, g_simBi);
    cudaGetSymbolAddress((void**)&atti,  g_atti);
    cudaGetSymbolAddress((void**)&wi,    g_wi);

    static int attr_done = 0;
    if (!attr_done) {
        cudaFuncSetAttribute(fused_attn,
                             cudaFuncAttributeMaxDynamicSharedMemorySize, 49152);
        attr_done = 1;
    }

    // 0: convert all GEMM operands to fp16 hi/lo swizzled images
    prep_all<<<dim3(32, 32, 9), dim3(256)>>>(query, key, value, Wq, Wk, Wv, Wo, sim);

    // 1: q/k/v projections (image-based, double-buffered)
    proj_img<<<dim3(E / 64, S / 128, 3), dim3(256)>>>(bq, bk, bv);

    // 2: pre-split k/v for fused attention
    prep_kv<<<dim3(NT, H), dim3(128)>>>();

    // 3: rel = sim @ sim^T (image-based)
    tc_gemm_img<<<dim3(S / 64, S / 128), dim3(256)>>>(simAi, simBi, grel, 2, S, nullptr);

    // 4: fused attention
    fused_attn<<<dim3(S / 64, H), dim3(128), 49152>>>(grel, w);

    // 5: convert attn to image
    prep_attn<<<dim3(32, 16), dim3(256)>>>();

    // 6: out = attn @ Wo^T + bo (image-based)
    tc_gemm_img<<<dim3(E / 64, S / 128), dim3(256)>>>(atti, wi + (size_t)3 * 4194304u,
                                                      out, 32, E, bo);
}